// round 2
// baseline (speedup 1.0000x reference)
#include <cuda_runtime.h>
#include <math.h>
#include <stdint.h>

#define BB  32
#define NSQ 1024
#define NCQ 1024
#define DD  256
#define DP1 257
#define KKW 128
#define KP1 129

// ----------------------------- scratch (static device globals; no runtime alloc) ---
static __device__ float2 g_c1 [(size_t)BB*NSQ*DD];
static __device__ float2 g_c1T[(size_t)BB*DD*NSQ];
static __device__ float  g_sT [(size_t)BB*DD*NSQ];
static __device__ float  g_real[(size_t)BB*NSQ*DD];
static __device__ float  g_Ls [(size_t)BB*NSQ*DP1];
static __device__ float  g_Lc [(size_t)BB*NCQ*DP1];
static __device__ float  g_Llin[(size_t)BB*NCQ*DP1];
static __device__ float  g_Yt [(size_t)BB*NSQ*KP1];
static __device__ float  g_Lb [(size_t)BB*NSQ*NCQ];
static __device__ float  g_xnr[BB*NSQ];
static __device__ float  g_xnc[BB*NCQ];
static __device__ float  g_Hsa[(size_t)BB*NSQ*KKW];
static __device__ float  g_Hca[(size_t)BB*NCQ*KKW];
static __device__ float  g_Mxs[(size_t)BB*NSQ*KKW];
static __device__ float  g_Mxc[(size_t)BB*NCQ*KKW];
static __device__ float  g_Hcm[(size_t)BB*KKW*NCQ];
static __device__ float  g_lgs[BB*NSQ];
static __device__ float  g_lgc[BB*NCQ];
static __device__ float  g_cs [BB*DP1];
static __device__ float  g_cc [BB*DP1];
static __device__ float2 g_tw1024a[512];
static __device__ float2 g_tw256a[128];

// ----------------------------- helpers ---------------------------------------------
__device__ __forceinline__ float atanhc(float x){
    x = fminf(fmaxf(x, -1.f + 1e-5f), 1.f - 1e-5f);
    return 0.5f * (log1pf(x) - log1pf(-x));
}
__device__ __forceinline__ float gelu_exact(float v){
    return 0.5f * v * (1.f + erff(v * 0.70710678118654752f));
}
__device__ __forceinline__ float blockReduceSum(float v){
    __shared__ float sh[32];
    #pragma unroll
    for (int o = 16; o; o >>= 1) v += __shfl_down_sync(0xffffffffu, v, o);
    int lane = threadIdx.x & 31, w = threadIdx.x >> 5;
    if (lane == 0) sh[w] = v;
    __syncthreads();
    int nw = (blockDim.x + 31) >> 5;
    v = (threadIdx.x < (unsigned)nw) ? sh[threadIdx.x] : 0.f;
    if (w == 0){
        #pragma unroll
        for (int o = 16; o; o >>= 1) v += __shfl_down_sync(0xffffffffu, v, o);
        if (lane == 0) sh[0] = v;
    }
    __syncthreads();
    float r = sh[0];
    __syncthreads();
    return r;
}
__device__ __forceinline__ void blockReduceSum3(float& a, float& b, float& c){
    __shared__ float sh3[32][3];
    #pragma unroll
    for (int o = 16; o; o >>= 1){
        a += __shfl_down_sync(0xffffffffu, a, o);
        b += __shfl_down_sync(0xffffffffu, b, o);
        c += __shfl_down_sync(0xffffffffu, c, o);
    }
    int lane = threadIdx.x & 31, w = threadIdx.x >> 5;
    if (lane == 0){ sh3[w][0] = a; sh3[w][1] = b; sh3[w][2] = c; }
    __syncthreads();
    int nw = (blockDim.x + 31) >> 5;
    a = (threadIdx.x < (unsigned)nw) ? sh3[threadIdx.x][0] : 0.f;
    b = (threadIdx.x < (unsigned)nw) ? sh3[threadIdx.x][1] : 0.f;
    c = (threadIdx.x < (unsigned)nw) ? sh3[threadIdx.x][2] : 0.f;
    if (w == 0){
        #pragma unroll
        for (int o = 16; o; o >>= 1){
            a += __shfl_down_sync(0xffffffffu, a, o);
            b += __shfl_down_sync(0xffffffffu, b, o);
            c += __shfl_down_sync(0xffffffffu, c, o);
        }
        if (lane == 0){ sh3[0][0] = a; sh3[0][1] = b; sh3[0][2] = c; }
    }
    __syncthreads();
    a = sh3[0][0]; b = sh3[0][1]; c = sh3[0][2];
    __syncthreads();
}
__device__ __forceinline__ float blockReduceMax(float v){
    __shared__ float sh[32];
    #pragma unroll
    for (int o = 16; o; o >>= 1) v = fmaxf(v, __shfl_down_sync(0xffffffffu, v, o));
    int lane = threadIdx.x & 31, w = threadIdx.x >> 5;
    if (lane == 0) sh[w] = v;
    __syncthreads();
    int nw = (blockDim.x + 31) >> 5;
    v = (threadIdx.x < (unsigned)nw) ? sh[threadIdx.x] : -3.4e38f;
    if (w == 0){
        #pragma unroll
        for (int o = 16; o; o >>= 1) v = fmaxf(v, __shfl_down_sync(0xffffffffu, v, o));
        if (lane == 0) sh[0] = v;
    }
    __syncthreads();
    float r = sh[0];
    __syncthreads();
    return r;
}
__device__ __forceinline__ uint32_t f2tf32(float v){
    uint32_t r;
    asm("cvt.rna.tf32.f32 %0, %1;" : "=r"(r) : "f"(v));
    return r;
}
__device__ __forceinline__ void mma_tf32(float* c, const uint32_t* a, const uint32_t* b){
    asm volatile("mma.sync.aligned.m16n8k8.row.col.f32.tf32.tf32.f32 "
        "{%0,%1,%2,%3}, {%4,%5,%6,%7}, {%8,%9}, {%0,%1,%2,%3};"
        : "+f"(c[0]), "+f"(c[1]), "+f"(c[2]), "+f"(c[3])
        : "r"(a[0]), "r"(a[1]), "r"(a[2]), "r"(a[3]), "r"(b[0]), "r"(b[1]));
}

// ----------------------------- twiddle fill ----------------------------------------
__global__ void k_twfill(){
    int i = threadIdx.x;
    if (i < 512){
        double a = -6.283185307179586476925287 * (double)i / 1024.0;
        g_tw1024a[i] = make_float2((float)cos(a), (float)sin(a));
    }
    if (i < 128){
        double a = -6.283185307179586476925287 * (double)i / 256.0;
        g_tw256a[i] = make_float2((float)cos(a), (float)sin(a));
    }
}

// ----------------------------- FFT kernels -----------------------------------------
__global__ void k_fft256(const float* __restrict__ in, float2* __restrict__ out, int do_log){
    __shared__ float2 sa[256];
    __shared__ float2 tws[128];
    size_t row = blockIdx.x;
    const float* x = in + row * 256;
    int t = threadIdx.x;                       // 128 threads
    tws[t] = g_tw256a[t];
    float v0 = x[t], v1 = x[t + 128];
    if (do_log){
        float ss = blockReduceSum(v0*v0 + v1*v1);
        float yn = sqrtf(fmaxf(ss, 1e-15f));
        float f  = atanhc(yn) / yn;
        v0 *= f; v1 *= f;
    }
    sa[__brev((unsigned)t) >> 24]        = make_float2(v0, 0.f);
    sa[__brev((unsigned)(t+128)) >> 24]  = make_float2(v1, 0.f);
    __syncthreads();
    int shift = 7;
    for (int len = 2; len <= 256; len <<= 1, shift--){
        int half = len >> 1;
        int g = t / half, j = t & (half-1);
        int pos = g*len + j;
        float2 w = tws[j << shift];
        float2 u = sa[pos], q = sa[pos + half];
        float2 wv = make_float2(q.x*w.x - q.y*w.y, q.x*w.y + q.y*w.x);
        sa[pos]        = make_float2(u.x + wv.x, u.y + wv.y);
        sa[pos + half] = make_float2(u.x - wv.x, u.y - wv.y);
        __syncthreads();
    }
    out[row*256 + t]       = sa[t];
    out[row*256 + t + 128] = sa[t + 128];
}

__global__ void k_fft1024(const float2* __restrict__ in, float* __restrict__ outr){
    __shared__ float2 sa[1024];
    __shared__ float2 tws[512];
    size_t row = blockIdx.x;
    int t = threadIdx.x;                       // 512 threads
    tws[t] = g_tw1024a[t];
    float2 a0 = in[row*1024 + t];
    float2 a1 = in[row*1024 + t + 512];
    sa[__brev((unsigned)t) >> 22]        = a0;
    sa[__brev((unsigned)(t+512)) >> 22]  = a1;
    __syncthreads();
    int shift = 9;
    for (int len = 2; len <= 1024; len <<= 1, shift--){
        int half = len >> 1;
        int g = t / half, j = t & (half-1);
        int pos = g*len + j;
        float2 w = tws[j << shift];
        float2 u = sa[pos], q = sa[pos + half];
        float2 wv = make_float2(q.x*w.x - q.y*w.y, q.x*w.y + q.y*w.x);
        sa[pos]        = make_float2(u.x + wv.x, u.y + wv.y);
        sa[pos + half] = make_float2(u.x - wv.x, u.y - wv.y);
        __syncthreads();
    }
    outr[row*1024 + t]       = sa[t].x;
    outr[row*1024 + t + 512] = sa[t + 512].x;
}

// tiled transposes: per batch (R,C) -> (C,R)
__global__ void k_transpose_c(const float2* __restrict__ in, float2* __restrict__ out, int R, int C){
    __shared__ float2 tile[32][33];
    int b = blockIdx.z;
    size_t base = (size_t)b * R * C;
    int c0 = blockIdx.x * 32, r0 = blockIdx.y * 32;
    for (int i = threadIdx.y; i < 32; i += 8)
        tile[i][threadIdx.x] = in[base + (size_t)(r0+i)*C + (c0+threadIdx.x)];
    __syncthreads();
    for (int i = threadIdx.y; i < 32; i += 8)
        out[base + (size_t)(c0+i)*R + (r0+threadIdx.x)] = tile[threadIdx.x][i];
}
__global__ void k_transpose_f(const float* __restrict__ in, float* __restrict__ out, int R, int C){
    __shared__ float tile[32][33];
    int b = blockIdx.z;
    size_t base = (size_t)b * R * C;
    int c0 = blockIdx.x * 32, r0 = blockIdx.y * 32;
    for (int i = threadIdx.y; i < 32; i += 8)
        tile[i][threadIdx.x] = in[base + (size_t)(r0+i)*C + (c0+threadIdx.x)];
    __syncthreads();
    for (int i = threadIdx.y; i < 32; i += 8)
        out[base + (size_t)(c0+i)*R + (r0+threadIdx.x)] = tile[threadIdx.x][i];
}

// euclid_to_lorentz: 256-wide row -> 257-wide Lorentz row
__global__ void k_e2l(const float* __restrict__ in, float* __restrict__ out){
    size_t row = blockIdx.x;
    int t = threadIdx.x;                       // 256
    float v = in[row*256 + t];
    float ss = blockReduceSum(v*v);
    float xn = sqrtf(fmaxf(ss, 1e-15f)) + 1e-5f;
    float scl = fminf(1.f, 2.0f / xn);
    v *= scl;
    float vn = sqrtf(fmaxf(ss*scl*scl, 1e-15f));
    float f = sinhf(vn) / vn;
    if (t == 0) out[row*DP1] = coshf(vn);
    out[row*DP1 + 1 + t] = f * v;
}

// ----------------------------- tensor-core GEMM (3xTF32) ---------------------------
// C[M,N] = op(A)*op(B), fp32-grade accuracy via hi/lo tf32 split.
//  ATRANS=0: A is M x K (lda)    ATRANS=1: A is K x M (lda)
//  BTRANS=1: B is N x K (ldb)    BTRANS=0: B is K x N (ldb)
//  MODE: 0 plain, 1 +bias[n], 2 gelu except global col 0 (col0 -> 0)
template<int ATRANS, int BTRANS, int MODE>
__global__ void k_tgemm(const float* __restrict__ A, const float* __restrict__ Bm,
                        const float* __restrict__ bias, float* __restrict__ C,
                        int M, int N, int Klen, int lda, int ldb, int ldc,
                        long sA, long sB, long sC)
{
    __shared__ uint32_t AshH[128][20];
    __shared__ uint32_t AshL[128][20];
    __shared__ uint32_t BshH[128][20];
    __shared__ uint32_t BshL[128][20];

    int bz = blockIdx.z;
    A  += (size_t)bz * sA;
    Bm += (size_t)bz * sB;
    C  += (size_t)bz * sC;
    int bm = blockIdx.y * 128, bn = blockIdx.x * 128;
    int tid = threadIdx.x;
    int wid = tid >> 5, lane = tid & 31;
    int wm = (wid >> 2) * 64;      // 0 / 64
    int wn = (wid & 3) * 32;       // 0 / 32 / 64 / 96
    int g = lane >> 2, tg = lane & 3;

    float acc[4][4][4];
    #pragma unroll
    for (int mi = 0; mi < 4; mi++)
        #pragma unroll
        for (int ni = 0; ni < 4; ni++)
            #pragma unroll
            for (int r = 0; r < 4; r++) acc[mi][ni][r] = 0.f;

    for (int k0 = 0; k0 < Klen; k0 += 16){
        #pragma unroll
        for (int i = 0; i < 8; i++){
            int e = tid + i*256;
            int mm, kk;
            if (ATRANS == 0){ kk = e & 15; mm = e >> 4; }
            else            { mm = e & 127; kk = e >> 7; }
            int gm = bm + mm, gk = k0 + kk;
            float av = 0.f;
            if (gm < M && gk < Klen)
                av = (ATRANS == 0) ? A[(size_t)gm*lda + gk] : A[(size_t)gk*lda + gm];
            uint32_t ah = f2tf32(av);
            uint32_t al = f2tf32(av - __uint_as_float(ah));
            AshH[mm][kk] = ah; AshL[mm][kk] = al;

            int nn, kb;
            if (BTRANS == 1){ kb = e & 15; nn = e >> 4; }
            else            { nn = e & 127; kb = e >> 7; }
            int gn = bn + nn, gk2 = k0 + kb;
            float bv = 0.f;
            if (gn < N && gk2 < Klen)
                bv = (BTRANS == 1) ? Bm[(size_t)gn*ldb + gk2] : Bm[(size_t)gk2*ldb + gn];
            uint32_t bh = f2tf32(bv);
            uint32_t bl = f2tf32(bv - __uint_as_float(bh));
            BshH[nn][kb] = bh; BshL[nn][kb] = bl;
        }
        __syncthreads();

        #pragma unroll
        for (int ks = 0; ks < 2; ks++){
            int kk = ks*8;
            uint32_t bhf[4][2], blf[4][2];
            #pragma unroll
            for (int ni = 0; ni < 4; ni++){
                int n = wn + ni*8 + g;
                bhf[ni][0] = BshH[n][kk+tg];   bhf[ni][1] = BshH[n][kk+tg+4];
                blf[ni][0] = BshL[n][kk+tg];   blf[ni][1] = BshL[n][kk+tg+4];
            }
            #pragma unroll
            for (int mi = 0; mi < 4; mi++){
                int m = wm + mi*16;
                uint32_t ahf[4], alf[4];
                ahf[0] = AshH[m+g  ][kk+tg];   ahf[1] = AshH[m+g+8][kk+tg];
                ahf[2] = AshH[m+g  ][kk+tg+4]; ahf[3] = AshH[m+g+8][kk+tg+4];
                alf[0] = AshL[m+g  ][kk+tg];   alf[1] = AshL[m+g+8][kk+tg];
                alf[2] = AshL[m+g  ][kk+tg+4]; alf[3] = AshL[m+g+8][kk+tg+4];
                #pragma unroll
                for (int ni = 0; ni < 4; ni++){
                    mma_tf32(acc[mi][ni], alf, bhf[ni]);
                    mma_tf32(acc[mi][ni], ahf, blf[ni]);
                    mma_tf32(acc[mi][ni], ahf, bhf[ni]);
                }
            }
        }
        __syncthreads();
    }

    #pragma unroll
    for (int mi = 0; mi < 4; mi++){
        #pragma unroll
        for (int ni = 0; ni < 4; ni++){
            int col = bn + wn + ni*8 + 2*tg;
            #pragma unroll
            for (int r = 0; r < 4; r++){
                int gm = bm + wm + mi*16 + g + (r >= 2 ? 8 : 0);
                int gn = col + (r & 1);
                if (gm >= M || gn >= N) continue;
                float v = acc[mi][ni][r];
                if (MODE == 1) v += bias[gn];
                if (MODE == 2) v = (gn == 0) ? 0.f : gelu_exact(v);
                C[(size_t)gm*ldc + gn] = v;
            }
        }
    }
}

// ----------------------------- row-wise kernels ------------------------------------
__global__ void k_fix_time(float* __restrict__ Y){        // width 257, recompute time
    size_t row = blockIdx.x;
    int t = threadIdx.x;                                  // 256
    float sp = Y[row*DP1 + 1 + t];
    float S = blockReduceSum(sp*sp);
    if (t == 0) Y[row*DP1] = sqrtf(S + 1.f);
}
__global__ void k_poincare(const float* __restrict__ Y, float* __restrict__ out){ // 129 -> 128
    size_t row = blockIdx.x;
    int t = threadIdx.x;                                  // 128
    float sp = Y[row*KP1 + 1 + t];
    float S = blockReduceSum(sp*sp);
    float time = sqrtf(S + 1.f);
    out[row*KKW + t] = sp / (time + 1.f);
}
__global__ void k_rowfix(float* __restrict__ L, float* __restrict__ xnr){
    size_t row = blockIdx.x;
    int t = threadIdx.x;                                  // 256
    float* p = L + row*1024;
    float s = 0.f;
    #pragma unroll
    for (int i = 0; i < 4; i++){ float v = p[t + i*256]; s += v*v; }  // col0 currently 0
    float S = blockReduceSum(s);
    if (t == 0){
        p[0] = sqrtf(S + 1.f);
        xnr[row] = sqrtf(fmaxf(2.f*S + 1.f, 1e-15f));
    }
}
__global__ void k_colnorm(const float* __restrict__ L, float* __restrict__ xnc){
    int b = blockIdx.y;
    int m = blockIdx.x*256 + threadIdx.x;
    const float* base = L + (size_t)b*NSQ*NCQ + m;
    float cs = 0.f;
    for (int n = 0; n < NSQ; n++){ float v = base[(size_t)n*NCQ]; cs += v*v; }
    xnc[b*NCQ + m] = sqrtf(fmaxf(cs, 1e-15f));
}
// mobius_matvec finalize (in-place): row width 128 (Mxc only)
__global__ void k_mfin(float* __restrict__ Mx, const float* __restrict__ xna){
    size_t row = blockIdx.x;
    int t = threadIdx.x;                                  // 128
    float v = Mx[row*KKW + t];
    float mm = blockReduceSum(v*v);
    float mxn = sqrtf(fmaxf(mm, 1e-15f));
    float xn = xna[row];
    float s = tanhf(mxn / xn * atanhc(xn)) / mxn;
    Mx[row*KKW + t] = v * s;
}
// fused: mobius_matvec finalize + mobius_add + logmap + gelu + expmap + As logit
__global__ void k_hs(const float* __restrict__ Hsa, const float* __restrict__ MxRaw,
                     const float* __restrict__ xnr,
                     const float* __restrict__ whs, float* __restrict__ lg){
    size_t row = blockIdx.x;
    int t = threadIdx.x;                                  // 128
    float yr = MxRaw[row*KKW + t];
    float mm = blockReduceSum(yr*yr);
    float mxn = sqrtf(fmaxf(mm, 1e-15f));
    float xnb = xnr[row];
    float y = yr * (tanhf(mxn / xnb * atanhc(xnb)) / mxn);

    float x = Hsa[row*KKW + t];
    float xy = x*y, x2 = x*x, y2 = y*y;
    blockReduceSum3(xy, x2, y2);
    float den = fmaxf(1.f + 2.f*xy + x2*y2, 1e-15f);
    float h = ((1.f + 2.f*xy + y2)*x + (1.f - x2)*y) / den;
    float hn = sqrtf(fmaxf(blockReduceSum(h*h), 1e-15f));
    float u = atanhc(hn) / hn * h;
    float gv = gelu_exact(u);
    float gn = sqrtf(fmaxf(blockReduceSum(gv*gv), 1e-15f));
    float hs = tanhf(gn) / gn * gv;
    float mx = hs * whs[t], xn2 = hs*hs, dmy = 0.f;
    blockReduceSum3(mx, xn2, dmy);
    if (t == 0){
        float xn = sqrtf(fmaxf(xn2, 1e-15f));
        float mxn2 = sqrtf(fmaxf(mx*mx, 1e-15f));
        lg[row] = tanhf(mxn2 / xn * atanhc(xn)) * mx / mxn2;
    }
}
// Hc path: rows over NC=1024 in transposed space; write Hc (B,K,NC)
__global__ void k_hc(const float* __restrict__ Hca, const float* __restrict__ Yb,
                     float* __restrict__ Hc){
    int bj = blockIdx.x;
    int b = bj >> 7, j = bj & 127;
    int t = threadIdx.x;                                  // 256
    float x[4], y[4];
    #pragma unroll
    for (int i = 0; i < 4; i++){
        int m = t + i*256;
        size_t idx = ((size_t)(b*NCQ + m))*KKW + j;
        x[i] = Hca[idx]; y[i] = Yb[idx];
    }
    float sxy = 0.f, sx2 = 0.f, sy2 = 0.f;
    #pragma unroll
    for (int i = 0; i < 4; i++){ sxy += x[i]*y[i]; sx2 += x[i]*x[i]; sy2 += y[i]*y[i]; }
    blockReduceSum3(sxy, sx2, sy2);
    float xy = sxy, x2 = sx2, y2 = sy2;
    float den = fmaxf(1.f + 2.f*xy + x2*y2, 1e-15f);
    float c1 = 1.f + 2.f*xy + y2, c2 = 1.f - x2;
    float h[4], hh = 0.f;
    #pragma unroll
    for (int i = 0; i < 4; i++){ h[i] = (c1*x[i] + c2*y[i]) / den; hh += h[i]*h[i]; }
    float hn = sqrtf(fmaxf(blockReduceSum(hh), 1e-15f));
    float fa = atanhc(hn) / hn;
    float g[4], gg = 0.f;
    #pragma unroll
    for (int i = 0; i < 4; i++){ g[i] = gelu_exact(fa*h[i]); gg += g[i]*g[i]; }
    float gn = sqrtf(fmaxf(blockReduceSum(gg), 1e-15f));
    float fb = tanhf(gn) / gn;
    #pragma unroll
    for (int i = 0; i < 4; i++)
        Hc[((size_t)(b*KKW + j))*NCQ + (t + i*256)] = fb * g[i];
}
// Ac logits: per (b,m) reduce over j of Hc[b,j,m]
__global__ void k_ac(const float* __restrict__ Hc, const float* __restrict__ whc,
                     float* __restrict__ lg){
    __shared__ float wsh[KKW];
    int b = blockIdx.y;
    int m = blockIdx.x*256 + threadIdx.x;
    if (threadIdx.x < KKW) wsh[threadIdx.x] = whc[threadIdx.x];
    __syncthreads();
    const float* base = Hc + (size_t)b*KKW*NCQ + m;
    float mx = 0.f, ss = 0.f;
    #pragma unroll 4
    for (int j = 0; j < KKW; j++){
        float v = base[(size_t)j*NCQ];
        mx += v * wsh[j]; ss += v*v;
    }
    float xn = sqrtf(fmaxf(ss, 1e-15f));
    float mxn = sqrtf(fmaxf(mx*mx, 1e-15f));
    lg[b*NCQ + m] = tanhf(mxn / xn * atanhc(xn)) * mx / mxn;
}
__global__ void k_softmax(const float* __restrict__ lg, float* __restrict__ out){
    int b = blockIdx.x, t = threadIdx.x;                  // 256
    float l[4];
    float lm = -3.4e38f;
    #pragma unroll
    for (int i = 0; i < 4; i++){ l[i] = lg[b*1024 + t + i*256]; lm = fmaxf(lm, l[i]); }
    float M = blockReduceMax(lm);
    float es = 0.f, e[4];
    #pragma unroll
    for (int i = 0; i < 4; i++){ e[i] = expf(l[i] - M); es += e[i]; }
    float S = blockReduceSum(es);
    #pragma unroll
    for (int i = 0; i < 4; i++) out[b*1024 + t + i*256] = e[i] / S;
}
__global__ void k_centroid(const float* __restrict__ Lx, const float* __restrict__ w,
                           float* __restrict__ co){
    __shared__ float wsh[NSQ];
    __shared__ float t0sh;
    int b = blockIdx.x, t = threadIdx.x;                  // 288 threads, t<257 active
    for (int i = t; i < NSQ; i += blockDim.x) wsh[i] = w[(size_t)b*NSQ + i];
    __syncthreads();
    float acc = 0.f;
    if (t < DP1){
        const float* base = Lx + (size_t)b*NSQ*DP1 + t;
        for (int n = 0; n < NSQ; n++) acc += wsh[n] * base[(size_t)n*DP1];
    }
    float sp = (t >= 1 && t < DP1) ? acc*acc : 0.f;
    float ssp = blockReduceSum(sp);
    if (t == 0) t0sh = acc;
    __syncthreads();
    float inner = -t0sh*t0sh + ssp;
    float den = sqrtf(fmaxf(fabsf(inner), 1e-8f));
    if (t < DP1) co[(size_t)b*DP1 + t] = acc / den;
}
__global__ void k_concat(const float* __restrict__ cs, const float* __restrict__ cc,
                         float* __restrict__ out){
    int b = blockIdx.x, t = threadIdx.x;                  // 256
    float t0s = cs[(size_t)b*DP1];
    float t0c = cc[(size_t)b*DP1];
    float sps = cs[(size_t)b*DP1 + 1 + t];
    float spc = cc[(size_t)b*DP1 + 1 + t];
    float ns  = sqrtf(fmaxf(blockReduceSum(sps*sps), 1e-15f));
    float ncv = sqrtf(fmaxf(blockReduceSum(spc*spc), 1e-15f));
    float zs = acoshf(fmaxf(t0s, 1.f + 1e-7f)) * sps / ns;
    float zc = acoshf(fmaxf(t0c, 1.f + 1e-7f)) * spc / ncv;
    float vn = sqrtf(fmaxf(blockReduceSum(zs*zs + zc*zc), 1e-15f));
    float f = sinhf(vn) / vn;
    float* o = out + (size_t)b*513;
    if (t == 0) o[0] = coshf(vn);
    o[1 + t]       = f * zs;
    o[1 + DD + t]  = f * zc;
}

// ----------------------------- launch ----------------------------------------------
extern "C" void kernel_launch(void* const* d_in, const int* in_sizes, int n_in,
                              void* d_out, int out_size)
{
    const float* sent = (const float*)d_in[0];
    const float* comm = (const float*)d_in[1];
    const float* WlW  = (const float*)d_in[2];
    const float* Wlb  = (const float*)d_in[3];
    const float* WcW  = (const float*)d_in[4];
    const float* Wcb  = (const float*)d_in[5];
    const float* WsW  = (const float*)d_in[6];
    const float* Wsb  = (const float*)d_in[7];
    const float* whs  = (const float*)d_in[8];
    const float* whc  = (const float*)d_in[9];
    float* out = (float*)d_out;
    (void)in_sizes; (void)n_in; (void)out_size;

    float2 *c1, *c1T;
    float *sT, *rl, *Ls, *Lc, *Llin, *Yt, *Lb, *xnr, *xnc, *Hsa, *Hca, *Mxs, *Mxc, *Hcm,
          *lgs, *lgc, *cs, *cc;
    cudaGetSymbolAddress((void**)&c1,  g_c1);
    cudaGetSymbolAddress((void**)&c1T, g_c1T);
    cudaGetSymbolAddress((void**)&sT,  g_sT);
    cudaGetSymbolAddress((void**)&rl,  g_real);
    cudaGetSymbolAddress((void**)&Ls,  g_Ls);
    cudaGetSymbolAddress((void**)&Lc,  g_Lc);
    cudaGetSymbolAddress((void**)&Llin,g_Llin);
    cudaGetSymbolAddress((void**)&Yt,  g_Yt);
    cudaGetSymbolAddress((void**)&Lb,  g_Lb);
    cudaGetSymbolAddress((void**)&xnr, g_xnr);
    cudaGetSymbolAddress((void**)&xnc, g_xnc);
    cudaGetSymbolAddress((void**)&Hsa, g_Hsa);
    cudaGetSymbolAddress((void**)&Hca, g_Hca);
    cudaGetSymbolAddress((void**)&Mxs, g_Mxs);
    cudaGetSymbolAddress((void**)&Mxc, g_Mxc);
    cudaGetSymbolAddress((void**)&Hcm, g_Hcm);
    cudaGetSymbolAddress((void**)&lgs, g_lgs);
    cudaGetSymbolAddress((void**)&lgc, g_lgc);
    cudaGetSymbolAddress((void**)&cs,  g_cs);
    cudaGetSymbolAddress((void**)&cc,  g_cc);

    const int AS_OFF = BB*513;             // 16416
    const int AC_OFF = AS_OFF + BB*NSQ;    // 49184

    k_twfill<<<1, 512>>>();

    // ---- FFT2 + euclid_to_lorentz, both branches ----
    for (int branch = 0; branch < 2; branch++){
        const float* inp = branch ? comm : sent;
        float* Lout = branch ? Lc : Ls;
        int dolog = branch ? 1 : 0;
        k_fft256<<<BB*NSQ, 128>>>(inp, c1, dolog);
        k_transpose_c<<<dim3(DD/32, NSQ/32, BB), dim3(32,8)>>>(c1, c1T, NSQ, DD);
        k_fft1024<<<BB*DD, 512>>>(c1T, sT);
        k_transpose_f<<<dim3(NSQ/32, DD/32, BB), dim3(32,8)>>>(sT, rl, DD, NSQ);
        k_e2l<<<BB*NSQ, 256>>>(rl, Lout);
    }

    // ---- linear layers (tensor cores) ----
    k_tgemm<0,1,1><<<dim3(3,256,1),256>>>(Lc, WlW, Wlb, Llin,
        BB*NCQ, DP1, DP1, DP1, DP1, DP1, 0, 0, 0);
    k_fix_time<<<BB*NCQ, 256>>>(Llin);

    k_tgemm<0,1,1><<<dim3(2,256,1),256>>>(Ls, WsW, Wsb, Yt,
        BB*NSQ, KP1, DP1, DP1, DP1, KP1, 0, 0, 0);
    k_poincare<<<BB*NSQ, 128>>>(Yt, Hsa);

    k_tgemm<0,1,1><<<dim3(2,256,1),256>>>(Lc, WcW, Wcb, Yt,
        BB*NCQ, KP1, DP1, DP1, DP1, KP1, 0, 0, 0);
    k_poincare<<<BB*NCQ, 128>>>(Yt, Hca);

    // ---- big einsum + lorentz_act (fused gelu epilogue) ----
    k_tgemm<0,1,2><<<dim3(8,8,BB),256>>>(Ls, Llin, nullptr, Lb,
        NSQ, NCQ, DP1, DP1, DP1, NCQ,
        (long)NSQ*DP1, (long)NCQ*DP1, (long)NSQ*NCQ);
    k_rowfix<<<BB*NSQ, 256>>>(Lb, xnr);
    k_colnorm<<<dim3(NCQ/256, BB), 256>>>(Lb, xnc);

    // ---- mobius_matvec GEMMs ----
    k_tgemm<0,0,0><<<dim3(1,8,BB),256>>>(Lb, Hca, nullptr, Mxs,
        NSQ, KKW, NCQ, NCQ, KKW, KKW,
        (long)NSQ*NCQ, (long)NCQ*KKW, (long)NSQ*KKW);
    k_tgemm<1,0,0><<<dim3(1,8,BB),256>>>(Lb, Hsa, nullptr, Mxc,
        NCQ, KKW, NSQ, NCQ, KKW, KKW,
        (long)NSQ*NCQ, (long)NSQ*KKW, (long)NCQ*KKW);
    k_mfin<<<BB*NCQ, 128>>>(Mxc, xnc);

    // ---- mobius_add + gelu pipeline + attention logits ----
    k_hs<<<BB*NSQ, 128>>>(Hsa, Mxs, xnr, whs, lgs);
    k_hc<<<BB*KKW, 256>>>(Hca, Mxc, Hcm);
    k_ac<<<dim3(NCQ/256, BB), 256>>>(Hcm, whc, lgc);

    // ---- softmaxes straight into output ----
    k_softmax<<<BB, 256>>>(lgs, out + AS_OFF);
    k_softmax<<<BB, 256>>>(lgc, out + AC_OFF);

    // ---- centroids + concat ----
    k_centroid<<<BB, 288>>>(Ls, out + AS_OFF, cs);
    k_centroid<<<BB, 288>>>(Lc, out + AC_OFF, cc);
    k_concat<<<BB, 256>>>(cs, cc, out);
}

// round 3
// speedup vs baseline: 1.1237x; 1.1237x over previous
#include <cuda_runtime.h>
#include <math.h>
#include <stdint.h>

#define BB  32
#define NSQ 1024
#define NCQ 1024
#define DD  256
#define DP1 257
#define KKW 128
#define KP1 129

// ----------------------------- scratch (static device globals; no runtime alloc) ---
static __device__ float2 g_c1 [(size_t)BB*NSQ*DD];
static __device__ float2 g_c1T[(size_t)BB*DD*NSQ];
static __device__ float  g_sT [(size_t)BB*DD*NSQ];
static __device__ float  g_real[(size_t)BB*NSQ*DD];
static __device__ float  g_Ls [(size_t)BB*NSQ*DP1];
static __device__ float  g_Lc [(size_t)BB*NCQ*DP1];
static __device__ float  g_Llin[(size_t)BB*NCQ*DP1];
static __device__ float  g_Yt [(size_t)BB*NSQ*KP1];
static __device__ float  g_Lb [(size_t)BB*NSQ*NCQ];
static __device__ float  g_xnr[BB*NSQ];
static __device__ float  g_xnc[BB*NCQ];
static __device__ float  g_Hsa[(size_t)BB*NSQ*KKW];
static __device__ float  g_Hca[(size_t)BB*NCQ*KKW];
static __device__ float  g_Mxs[(size_t)BB*NSQ*KKW];
static __device__ float  g_Mxc[(size_t)BB*NCQ*KKW];
static __device__ float  g_Hcm[(size_t)BB*KKW*NCQ];
static __device__ float  g_lgs[BB*NSQ];
static __device__ float  g_lgc[BB*NCQ];
static __device__ float  g_cs [BB*DP1];
static __device__ float  g_cc [BB*DP1];
static __device__ float2 g_tw1024[1024];
static __device__ float2 g_tw256[256];

// ----------------------------- helpers ---------------------------------------------
__device__ __forceinline__ float atanhc(float x){
    x = fminf(fmaxf(x, -1.f + 1e-5f), 1.f - 1e-5f);
    return 0.5f * (log1pf(x) - log1pf(-x));
}
__device__ __forceinline__ float gelu_exact(float v){
    return 0.5f * v * (1.f + erff(v * 0.70710678118654752f));
}
__device__ __forceinline__ float2 cmul(float2 a, float2 b){
    return make_float2(a.x*b.x - a.y*b.y, a.x*b.y + a.y*b.x);
}
__device__ __forceinline__ float2 cadd(float2 a, float2 b){ return make_float2(a.x+b.x, a.y+b.y); }
__device__ __forceinline__ float2 csub(float2 a, float2 b){ return make_float2(a.x-b.x, a.y-b.y); }

__device__ __forceinline__ float blockReduceSum(float v){
    __shared__ float sh[32];
    #pragma unroll
    for (int o = 16; o; o >>= 1) v += __shfl_down_sync(0xffffffffu, v, o);
    int lane = threadIdx.x & 31, w = threadIdx.x >> 5;
    if (lane == 0) sh[w] = v;
    __syncthreads();
    int nw = (blockDim.x + 31) >> 5;
    v = (threadIdx.x < (unsigned)nw) ? sh[threadIdx.x] : 0.f;
    if (w == 0){
        #pragma unroll
        for (int o = 16; o; o >>= 1) v += __shfl_down_sync(0xffffffffu, v, o);
        if (lane == 0) sh[0] = v;
    }
    __syncthreads();
    float r = sh[0];
    __syncthreads();
    return r;
}
__device__ __forceinline__ void blockReduceSum3(float& a, float& b, float& c){
    __shared__ float sh3[32][3];
    #pragma unroll
    for (int o = 16; o; o >>= 1){
        a += __shfl_down_sync(0xffffffffu, a, o);
        b += __shfl_down_sync(0xffffffffu, b, o);
        c += __shfl_down_sync(0xffffffffu, c, o);
    }
    int lane = threadIdx.x & 31, w = threadIdx.x >> 5;
    if (lane == 0){ sh3[w][0] = a; sh3[w][1] = b; sh3[w][2] = c; }
    __syncthreads();
    int nw = (blockDim.x + 31) >> 5;
    a = (threadIdx.x < (unsigned)nw) ? sh3[threadIdx.x][0] : 0.f;
    b = (threadIdx.x < (unsigned)nw) ? sh3[threadIdx.x][1] : 0.f;
    c = (threadIdx.x < (unsigned)nw) ? sh3[threadIdx.x][2] : 0.f;
    if (w == 0){
        #pragma unroll
        for (int o = 16; o; o >>= 1){
            a += __shfl_down_sync(0xffffffffu, a, o);
            b += __shfl_down_sync(0xffffffffu, b, o);
            c += __shfl_down_sync(0xffffffffu, c, o);
        }
        if (lane == 0){ sh3[0][0] = a; sh3[0][1] = b; sh3[0][2] = c; }
    }
    __syncthreads();
    a = sh3[0][0]; b = sh3[0][1]; c = sh3[0][2];
    __syncthreads();
}
__device__ __forceinline__ float blockReduceMax(float v){
    __shared__ float sh[32];
    #pragma unroll
    for (int o = 16; o; o >>= 1) v = fmaxf(v, __shfl_down_sync(0xffffffffu, v, o));
    int lane = threadIdx.x & 31, w = threadIdx.x >> 5;
    if (lane == 0) sh[w] = v;
    __syncthreads();
    int nw = (blockDim.x + 31) >> 5;
    v = (threadIdx.x < (unsigned)nw) ? sh[threadIdx.x] : -3.4e38f;
    if (w == 0){
        #pragma unroll
        for (int o = 16; o; o >>= 1) v = fmaxf(v, __shfl_down_sync(0xffffffffu, v, o));
        if (lane == 0) sh[0] = v;
    }
    __syncthreads();
    float r = sh[0];
    __syncthreads();
    return r;
}
__device__ __forceinline__ uint32_t f2tf32(float v){
    uint32_t r;
    asm("cvt.rna.tf32.f32 %0, %1;" : "=r"(r) : "f"(v));
    return r;
}
__device__ __forceinline__ void mma_tf32(float* c, const uint32_t* a, const uint32_t* b){
    asm volatile("mma.sync.aligned.m16n8k8.row.col.f32.tf32.tf32.f32 "
        "{%0,%1,%2,%3}, {%4,%5,%6,%7}, {%8,%9}, {%0,%1,%2,%3};"
        : "+f"(c[0]), "+f"(c[1]), "+f"(c[2]), "+f"(c[3])
        : "r"(a[0]), "r"(a[1]), "r"(a[2]), "r"(a[3]), "r"(b[0]), "r"(b[1]));
}

// ----------------------------- twiddle fill ----------------------------------------
__global__ void k_twfill(){
    int i = threadIdx.x + blockIdx.x*1024;
    if (i < 1024){
        double a = -6.283185307179586476925287 * (double)i / 1024.0;
        g_tw1024[i] = make_float2((float)cos(a), (float)sin(a));
    }
    if (i < 256){
        double a = -6.283185307179586476925287 * (double)i / 256.0;
        g_tw256[i] = make_float2((float)cos(a), (float)sin(a));
    }
}

// ----------------------------- radix-4 Stockham FFT kernels ------------------------
// FFT-256 along last axis, optional fused p_logmap0 (per row). 4 rows per block.
__global__ void k_fft256(const float* __restrict__ in, float2* __restrict__ out, int do_log){
    __shared__ float2 bufA[4][256];
    __shared__ float2 bufB[4][256];
    __shared__ float2 tws[256];
    __shared__ float  rsum[4][2];
    int tx = threadIdx.x;                      // 64
    int ty = threadIdx.y;                      // 4
    int tid = ty*64 + tx;
    size_t row = (size_t)blockIdx.x*4 + ty;
    tws[tid] = g_tw256[tid];

    const float* x = in + row*256;
    float v0 = x[tx], v1 = x[tx+64], v2 = x[tx+128], v3 = x[tx+192];
    float ss = v0*v0 + v1*v1 + v2*v2 + v3*v3;
    #pragma unroll
    for (int o = 16; o; o >>= 1) ss += __shfl_down_sync(0xffffffffu, ss, o);
    if ((tx & 31) == 0) rsum[ty][tx >> 5] = ss;
    __syncthreads();
    if (do_log){
        float tot = rsum[ty][0] + rsum[ty][1];
        float yn = sqrtf(fmaxf(tot, 1e-15f));
        float f = atanhc(yn) / yn;
        v0 *= f; v1 *= f; v2 *= f; v3 *= f;
    }
    bufA[ty][tx]       = make_float2(v0, 0.f);
    bufA[ty][tx + 64]  = make_float2(v1, 0.f);
    bufA[ty][tx + 128] = make_float2(v2, 0.f);
    bufA[ty][tx + 192] = make_float2(v3, 0.f);
    __syncthreads();

    float2* X = &bufA[ty][0];
    float2* Y = &bufB[ty][0];
    #pragma unroll
    for (int s = 0; s < 4; s++){
        int Ns = 1 << (2*s);
        int p = tx & (Ns - 1);
        float2 w1 = tws[p * (64/Ns)];
        float2 w2 = cmul(w1, w1);
        float2 w3 = cmul(w2, w1);
        float2 a0 = X[tx];
        float2 a1 = cmul(X[tx + 64],  w1);
        float2 a2 = cmul(X[tx + 128], w2);
        float2 a3 = cmul(X[tx + 192], w3);
        float2 pa = cadd(a0, a2), pb = csub(a0, a2);
        float2 pc = cadd(a1, a3), pd = csub(a1, a3);
        float2 dneg = make_float2(pd.y, -pd.x);   // -i*d
        float2 dpos = make_float2(-pd.y, pd.x);   //  i*d
        int idxD = ((tx >> (2*s)) << (2*s + 2)) + p;
        Y[idxD]          = cadd(pa, pc);
        Y[idxD + Ns]     = cadd(pb, dneg);
        Y[idxD + 2*Ns]   = csub(pa, pc);
        Y[idxD + 3*Ns]   = cadd(pb, dpos);
        __syncthreads();
        float2* tmp = X; X = Y; Y = tmp;
    }
    out[row*256 + tx]       = X[tx];
    out[row*256 + tx + 64]  = X[tx + 64];
    out[row*256 + tx + 128] = X[tx + 128];
    out[row*256 + tx + 192] = X[tx + 192];
}

// FFT-1024 on complex rows; emit real part only.
__global__ void k_fft1024(const float2* __restrict__ in, float* __restrict__ outr){
    __shared__ float2 bufA[1024];
    __shared__ float2 bufB[1024];
    __shared__ float2 tws[1024];
    int t = threadIdx.x;                       // 256
    size_t row = blockIdx.x;
    const float2* src = in + row*1024;
    #pragma unroll
    for (int i = 0; i < 4; i++){
        tws[t + i*256]  = g_tw1024[t + i*256];
        bufA[t + i*256] = src[t + i*256];
    }
    __syncthreads();
    float2* X = bufA;
    float2* Y = bufB;
    #pragma unroll
    for (int s = 0; s < 5; s++){
        int Ns = 1 << (2*s);
        int p = t & (Ns - 1);
        float2 w1 = tws[p * (256/Ns)];
        float2 w2 = cmul(w1, w1);
        float2 w3 = cmul(w2, w1);
        float2 a0 = X[t];
        float2 a1 = cmul(X[t + 256], w1);
        float2 a2 = cmul(X[t + 512], w2);
        float2 a3 = cmul(X[t + 768], w3);
        float2 pa = cadd(a0, a2), pb = csub(a0, a2);
        float2 pc = cadd(a1, a3), pd = csub(a1, a3);
        float2 dneg = make_float2(pd.y, -pd.x);
        float2 dpos = make_float2(-pd.y, pd.x);
        int idxD = ((t >> (2*s)) << (2*s + 2)) + p;
        Y[idxD]        = cadd(pa, pc);
        Y[idxD + Ns]   = cadd(pb, dneg);
        Y[idxD + 2*Ns] = csub(pa, pc);
        Y[idxD + 3*Ns] = cadd(pb, dpos);
        __syncthreads();
        float2* tmp = X; X = Y; Y = tmp;
    }
    #pragma unroll
    for (int i = 0; i < 4; i++)
        outr[row*1024 + t + i*256] = X[t + i*256].x;
}

// tiled transposes: per batch (R,C) -> (C,R)
__global__ void k_transpose_c(const float2* __restrict__ in, float2* __restrict__ out, int R, int C){
    __shared__ float2 tile[32][33];
    int b = blockIdx.z;
    size_t base = (size_t)b * R * C;
    int c0 = blockIdx.x * 32, r0 = blockIdx.y * 32;
    for (int i = threadIdx.y; i < 32; i += 8)
        tile[i][threadIdx.x] = in[base + (size_t)(r0+i)*C + (c0+threadIdx.x)];
    __syncthreads();
    for (int i = threadIdx.y; i < 32; i += 8)
        out[base + (size_t)(c0+i)*R + (r0+threadIdx.x)] = tile[threadIdx.x][i];
}
__global__ void k_transpose_f(const float* __restrict__ in, float* __restrict__ out, int R, int C){
    __shared__ float tile[32][33];
    int b = blockIdx.z;
    size_t base = (size_t)b * R * C;
    int c0 = blockIdx.x * 32, r0 = blockIdx.y * 32;
    for (int i = threadIdx.y; i < 32; i += 8)
        tile[i][threadIdx.x] = in[base + (size_t)(r0+i)*C + (c0+threadIdx.x)];
    __syncthreads();
    for (int i = threadIdx.y; i < 32; i += 8)
        out[base + (size_t)(c0+i)*R + (r0+threadIdx.x)] = tile[threadIdx.x][i];
}

// euclid_to_lorentz: 256-wide row -> 257-wide Lorentz row
__global__ void k_e2l(const float* __restrict__ in, float* __restrict__ out){
    size_t row = blockIdx.x;
    int t = threadIdx.x;                       // 256
    float v = in[row*256 + t];
    float ss = blockReduceSum(v*v);
    float xn = sqrtf(fmaxf(ss, 1e-15f)) + 1e-5f;
    float scl = fminf(1.f, 2.0f / xn);
    v *= scl;
    float vn = sqrtf(fmaxf(ss*scl*scl, 1e-15f));
    float f = sinhf(vn) / vn;
    if (t == 0) out[row*DP1] = coshf(vn);
    out[row*DP1 + 1 + t] = f * v;
}

// ----------------------------- tensor-core GEMM (3xTF32) ---------------------------
template<int ATRANS, int BTRANS, int MODE>
__global__ void k_tgemm(const float* __restrict__ A, const float* __restrict__ Bm,
                        const float* __restrict__ bias, float* __restrict__ C,
                        int M, int N, int Klen, int lda, int ldb, int ldc,
                        long sA, long sB, long sC)
{
    __shared__ uint32_t AshH[128][20];
    __shared__ uint32_t AshL[128][20];
    __shared__ uint32_t BshH[128][20];
    __shared__ uint32_t BshL[128][20];

    int bz = blockIdx.z;
    A  += (size_t)bz * sA;
    Bm += (size_t)bz * sB;
    C  += (size_t)bz * sC;
    int bm = blockIdx.y * 128, bn = blockIdx.x * 128;
    int tid = threadIdx.x;
    int wid = tid >> 5, lane = tid & 31;
    int wm = (wid >> 2) * 64;
    int wn = (wid & 3) * 32;
    int g = lane >> 2, tg = lane & 3;

    float acc[4][4][4];
    #pragma unroll
    for (int mi = 0; mi < 4; mi++)
        #pragma unroll
        for (int ni = 0; ni < 4; ni++)
            #pragma unroll
            for (int r = 0; r < 4; r++) acc[mi][ni][r] = 0.f;

    for (int k0 = 0; k0 < Klen; k0 += 16){
        #pragma unroll
        for (int i = 0; i < 8; i++){
            int e = tid + i*256;
            int mm, kk;
            if (ATRANS == 0){ kk = e & 15; mm = e >> 4; }
            else            { mm = e & 127; kk = e >> 7; }
            int gm = bm + mm, gk = k0 + kk;
            float av = 0.f;
            if (gm < M && gk < Klen)
                av = (ATRANS == 0) ? A[(size_t)gm*lda + gk] : A[(size_t)gk*lda + gm];
            uint32_t ah = f2tf32(av);
            uint32_t al = f2tf32(av - __uint_as_float(ah));
            AshH[mm][kk] = ah; AshL[mm][kk] = al;

            int nn, kb;
            if (BTRANS == 1){ kb = e & 15; nn = e >> 4; }
            else            { nn = e & 127; kb = e >> 7; }
            int gn = bn + nn, gk2 = k0 + kb;
            float bv = 0.f;
            if (gn < N && gk2 < Klen)
                bv = (BTRANS == 1) ? Bm[(size_t)gn*ldb + gk2] : Bm[(size_t)gk2*ldb + gn];
            uint32_t bh = f2tf32(bv);
            uint32_t bl = f2tf32(bv - __uint_as_float(bh));
            BshH[nn][kb] = bh; BshL[nn][kb] = bl;
        }
        __syncthreads();

        #pragma unroll
        for (int ks = 0; ks < 2; ks++){
            int kk = ks*8;
            uint32_t bhf[4][2], blf[4][2];
            #pragma unroll
            for (int ni = 0; ni < 4; ni++){
                int n = wn + ni*8 + g;
                bhf[ni][0] = BshH[n][kk+tg];   bhf[ni][1] = BshH[n][kk+tg+4];
                blf[ni][0] = BshL[n][kk+tg];   blf[ni][1] = BshL[n][kk+tg+4];
            }
            #pragma unroll
            for (int mi = 0; mi < 4; mi++){
                int m = wm + mi*16;
                uint32_t ahf[4], alf[4];
                ahf[0] = AshH[m+g  ][kk+tg];   ahf[1] = AshH[m+g+8][kk+tg];
                ahf[2] = AshH[m+g  ][kk+tg+4]; ahf[3] = AshH[m+g+8][kk+tg+4];
                alf[0] = AshL[m+g  ][kk+tg];   alf[1] = AshL[m+g+8][kk+tg];
                alf[2] = AshL[m+g  ][kk+tg+4]; alf[3] = AshL[m+g+8][kk+tg+4];
                #pragma unroll
                for (int ni = 0; ni < 4; ni++){
                    mma_tf32(acc[mi][ni], alf, bhf[ni]);
                    mma_tf32(acc[mi][ni], ahf, blf[ni]);
                    mma_tf32(acc[mi][ni], ahf, bhf[ni]);
                }
            }
        }
        __syncthreads();
    }

    #pragma unroll
    for (int mi = 0; mi < 4; mi++){
        #pragma unroll
        for (int ni = 0; ni < 4; ni++){
            int col = bn + wn + ni*8 + 2*tg;
            #pragma unroll
            for (int r = 0; r < 4; r++){
                int gm = bm + wm + mi*16 + g + (r >= 2 ? 8 : 0);
                int gn = col + (r & 1);
                if (gm >= M || gn >= N) continue;
                float v = acc[mi][ni][r];
                if (MODE == 1) v += bias[gn];
                if (MODE == 2) v = (gn == 0) ? 0.f : gelu_exact(v);
                C[(size_t)gm*ldc + gn] = v;
            }
        }
    }
}

// ----------------------------- row-wise kernels ------------------------------------
__global__ void k_fix_time(float* __restrict__ Y){
    size_t row = blockIdx.x;
    int t = threadIdx.x;                                  // 256
    float sp = Y[row*DP1 + 1 + t];
    float S = blockReduceSum(sp*sp);
    if (t == 0) Y[row*DP1] = sqrtf(S + 1.f);
}
__global__ void k_poincare(const float* __restrict__ Y, float* __restrict__ out){
    size_t row = blockIdx.x;
    int t = threadIdx.x;                                  // 128
    float sp = Y[row*KP1 + 1 + t];
    float S = blockReduceSum(sp*sp);
    float time = sqrtf(S + 1.f);
    out[row*KKW + t] = sp / (time + 1.f);
}
__global__ void k_rowfix(float* __restrict__ L, float* __restrict__ xnr){
    size_t row = blockIdx.x;
    int t = threadIdx.x;                                  // 256
    float* p = L + row*1024;
    float s = 0.f;
    #pragma unroll
    for (int i = 0; i < 4; i++){ float v = p[t + i*256]; s += v*v; }
    float S = blockReduceSum(s);
    if (t == 0){
        p[0] = sqrtf(S + 1.f);
        xnr[row] = sqrtf(fmaxf(2.f*S + 1.f, 1e-15f));
    }
}
__global__ void k_colnorm(const float* __restrict__ L, float* __restrict__ xnc){
    int b = blockIdx.y;
    int m = blockIdx.x*256 + threadIdx.x;
    const float* base = L + (size_t)b*NSQ*NCQ + m;
    float cs = 0.f;
    for (int n = 0; n < NSQ; n++){ float v = base[(size_t)n*NCQ]; cs += v*v; }
    xnc[b*NCQ + m] = sqrtf(fmaxf(cs, 1e-15f));
}
__global__ void k_mfin(float* __restrict__ Mx, const float* __restrict__ xna){
    size_t row = blockIdx.x;
    int t = threadIdx.x;                                  // 128
    float v = Mx[row*KKW + t];
    float mm = blockReduceSum(v*v);
    float mxn = sqrtf(fmaxf(mm, 1e-15f));
    float xn = xna[row];
    float s = tanhf(mxn / xn * atanhc(xn)) / mxn;
    Mx[row*KKW + t] = v * s;
}
__global__ void k_hs(const float* __restrict__ Hsa, const float* __restrict__ MxRaw,
                     const float* __restrict__ xnr,
                     const float* __restrict__ whs, float* __restrict__ lg){
    size_t row = blockIdx.x;
    int t = threadIdx.x;                                  // 128
    float yr = MxRaw[row*KKW + t];
    float mm = blockReduceSum(yr*yr);
    float mxn = sqrtf(fmaxf(mm, 1e-15f));
    float xnb = xnr[row];
    float y = yr * (tanhf(mxn / xnb * atanhc(xnb)) / mxn);

    float x = Hsa[row*KKW + t];
    float xy = x*y, x2 = x*x, y2 = y*y;
    blockReduceSum3(xy, x2, y2);
    float den = fmaxf(1.f + 2.f*xy + x2*y2, 1e-15f);
    float h = ((1.f + 2.f*xy + y2)*x + (1.f - x2)*y) / den;
    float hn = sqrtf(fmaxf(blockReduceSum(h*h), 1e-15f));
    float u = atanhc(hn) / hn * h;
    float gv = gelu_exact(u);
    float gn = sqrtf(fmaxf(blockReduceSum(gv*gv), 1e-15f));
    float hs = tanhf(gn) / gn * gv;
    float mx = hs * whs[t], xn2 = hs*hs, dmy = 0.f;
    blockReduceSum3(mx, xn2, dmy);
    if (t == 0){
        float xn = sqrtf(fmaxf(xn2, 1e-15f));
        float mxn2 = sqrtf(fmaxf(mx*mx, 1e-15f));
        lg[row] = tanhf(mxn2 / xn * atanhc(xn)) * mx / mxn2;
    }
}
__global__ void k_hc(const float* __restrict__ Hca, const float* __restrict__ Yb,
                     float* __restrict__ Hc){
    int bj = blockIdx.x;
    int b = bj >> 7, j = bj & 127;
    int t = threadIdx.x;                                  // 256
    float x[4], y[4];
    #pragma unroll
    for (int i = 0; i < 4; i++){
        int m = t + i*256;
        size_t idx = ((size_t)(b*NCQ + m))*KKW + j;
        x[i] = Hca[idx]; y[i] = Yb[idx];
    }
    float sxy = 0.f, sx2 = 0.f, sy2 = 0.f;
    #pragma unroll
    for (int i = 0; i < 4; i++){ sxy += x[i]*y[i]; sx2 += x[i]*x[i]; sy2 += y[i]*y[i]; }
    blockReduceSum3(sxy, sx2, sy2);
    float xy = sxy, x2 = sx2, y2 = sy2;
    float den = fmaxf(1.f + 2.f*xy + x2*y2, 1e-15f);
    float c1 = 1.f + 2.f*xy + y2, c2 = 1.f - x2;
    float h[4], hh = 0.f;
    #pragma unroll
    for (int i = 0; i < 4; i++){ h[i] = (c1*x[i] + c2*y[i]) / den; hh += h[i]*h[i]; }
    float hn = sqrtf(fmaxf(blockReduceSum(hh), 1e-15f));
    float fa = atanhc(hn) / hn;
    float g[4], gg = 0.f;
    #pragma unroll
    for (int i = 0; i < 4; i++){ g[i] = gelu_exact(fa*h[i]); gg += g[i]*g[i]; }
    float gn = sqrtf(fmaxf(blockReduceSum(gg), 1e-15f));
    float fb = tanhf(gn) / gn;
    #pragma unroll
    for (int i = 0; i < 4; i++)
        Hc[((size_t)(b*KKW + j))*NCQ + (t + i*256)] = fb * g[i];
}
__global__ void k_ac(const float* __restrict__ Hc, const float* __restrict__ whc,
                     float* __restrict__ lg){
    __shared__ float wsh[KKW];
    int b = blockIdx.y;
    int m = blockIdx.x*256 + threadIdx.x;
    if (threadIdx.x < KKW) wsh[threadIdx.x] = whc[threadIdx.x];
    __syncthreads();
    const float* base = Hc + (size_t)b*KKW*NCQ + m;
    float mx = 0.f, ss = 0.f;
    #pragma unroll 4
    for (int j = 0; j < KKW; j++){
        float v = base[(size_t)j*NCQ];
        mx += v * wsh[j]; ss += v*v;
    }
    float xn = sqrtf(fmaxf(ss, 1e-15f));
    float mxn = sqrtf(fmaxf(mx*mx, 1e-15f));
    lg[b*NCQ + m] = tanhf(mxn / xn * atanhc(xn)) * mx / mxn;
}
__global__ void k_softmax(const float* __restrict__ lg, float* __restrict__ out){
    int b = blockIdx.x, t = threadIdx.x;                  // 256
    float l[4];
    float lm = -3.4e38f;
    #pragma unroll
    for (int i = 0; i < 4; i++){ l[i] = lg[b*1024 + t + i*256]; lm = fmaxf(lm, l[i]); }
    float M = blockReduceMax(lm);
    float es = 0.f, e[4];
    #pragma unroll
    for (int i = 0; i < 4; i++){ e[i] = expf(l[i] - M); es += e[i]; }
    float S = blockReduceSum(es);
    #pragma unroll
    for (int i = 0; i < 4; i++) out[b*1024 + t + i*256] = e[i] / S;
}
__global__ void k_centroid(const float* __restrict__ Lx, const float* __restrict__ w,
                           float* __restrict__ co){
    __shared__ float wsh[NSQ];
    __shared__ float t0sh;
    int b = blockIdx.x, t = threadIdx.x;                  // 288, t<257 active
    for (int i = t; i < NSQ; i += blockDim.x) wsh[i] = w[(size_t)b*NSQ + i];
    __syncthreads();
    float acc = 0.f;
    if (t < DP1){
        const float* base = Lx + (size_t)b*NSQ*DP1 + t;
        for (int n = 0; n < NSQ; n++) acc += wsh[n] * base[(size_t)n*DP1];
    }
    float sp = (t >= 1 && t < DP1) ? acc*acc : 0.f;
    float ssp = blockReduceSum(sp);
    if (t == 0) t0sh = acc;
    __syncthreads();
    float inner = -t0sh*t0sh + ssp;
    float den = sqrtf(fmaxf(fabsf(inner), 1e-8f));
    if (t < DP1) co[(size_t)b*DP1 + t] = acc / den;
}
__global__ void k_concat(const float* __restrict__ cs, const float* __restrict__ cc,
                         float* __restrict__ out){
    int b = blockIdx.x, t = threadIdx.x;                  // 256
    float t0s = cs[(size_t)b*DP1];
    float t0c = cc[(size_t)b*DP1];
    float sps = cs[(size_t)b*DP1 + 1 + t];
    float spc = cc[(size_t)b*DP1 + 1 + t];
    float ns  = sqrtf(fmaxf(blockReduceSum(sps*sps), 1e-15f));
    float ncv = sqrtf(fmaxf(blockReduceSum(spc*spc), 1e-15f));
    float zs = acoshf(fmaxf(t0s, 1.f + 1e-7f)) * sps / ns;
    float zc = acoshf(fmaxf(t0c, 1.f + 1e-7f)) * spc / ncv;
    float vn = sqrtf(fmaxf(blockReduceSum(zs*zs + zc*zc), 1e-15f));
    float f = sinhf(vn) / vn;
    float* o = out + (size_t)b*513;
    if (t == 0) o[0] = coshf(vn);
    o[1 + t]       = f * zs;
    o[1 + DD + t]  = f * zc;
}

// ----------------------------- launch ----------------------------------------------
extern "C" void kernel_launch(void* const* d_in, const int* in_sizes, int n_in,
                              void* d_out, int out_size)
{
    const float* sent = (const float*)d_in[0];
    const float* comm = (const float*)d_in[1];
    const float* WlW  = (const float*)d_in[2];
    const float* Wlb  = (const float*)d_in[3];
    const float* WcW  = (const float*)d_in[4];
    const float* Wcb  = (const float*)d_in[5];
    const float* WsW  = (const float*)d_in[6];
    const float* Wsb  = (const float*)d_in[7];
    const float* whs  = (const float*)d_in[8];
    const float* whc  = (const float*)d_in[9];
    float* out = (float*)d_out;
    (void)in_sizes; (void)n_in; (void)out_size;

    float2 *c1, *c1T;
    float *sT, *rl, *Ls, *Lc, *Llin, *Yt, *Lb, *xnr, *xnc, *Hsa, *Hca, *Mxs, *Mxc, *Hcm,
          *lgs, *lgc, *cs, *cc;
    cudaGetSymbolAddress((void**)&c1,  g_c1);
    cudaGetSymbolAddress((void**)&c1T, g_c1T);
    cudaGetSymbolAddress((void**)&sT,  g_sT);
    cudaGetSymbolAddress((void**)&rl,  g_real);
    cudaGetSymbolAddress((void**)&Ls,  g_Ls);
    cudaGetSymbolAddress((void**)&Lc,  g_Lc);
    cudaGetSymbolAddress((void**)&Llin,g_Llin);
    cudaGetSymbolAddress((void**)&Yt,  g_Yt);
    cudaGetSymbolAddress((void**)&Lb,  g_Lb);
    cudaGetSymbolAddress((void**)&xnr, g_xnr);
    cudaGetSymbolAddress((void**)&xnc, g_xnc);
    cudaGetSymbolAddress((void**)&Hsa, g_Hsa);
    cudaGetSymbolAddress((void**)&Hca, g_Hca);
    cudaGetSymbolAddress((void**)&Mxs, g_Mxs);
    cudaGetSymbolAddress((void**)&Mxc, g_Mxc);
    cudaGetSymbolAddress((void**)&Hcm, g_Hcm);
    cudaGetSymbolAddress((void**)&lgs, g_lgs);
    cudaGetSymbolAddress((void**)&lgc, g_lgc);
    cudaGetSymbolAddress((void**)&cs,  g_cs);
    cudaGetSymbolAddress((void**)&cc,  g_cc);

    const int AS_OFF = BB*513;             // 16416
    const int AC_OFF = AS_OFF + BB*NSQ;    // 49184

    k_twfill<<<1, 1024>>>();

    // ---- FFT2 + euclid_to_lorentz, both branches ----
    for (int branch = 0; branch < 2; branch++){
        const float* inp = branch ? comm : sent;
        float* Lout = branch ? Lc : Ls;
        int dolog = branch ? 1 : 0;
        k_fft256<<<BB*NSQ/4, dim3(64,4)>>>(inp, c1, dolog);
        k_transpose_c<<<dim3(DD/32, NSQ/32, BB), dim3(32,8)>>>(c1, c1T, NSQ, DD);
        k_fft1024<<<BB*DD, 256>>>(c1T, sT);
        k_transpose_f<<<dim3(NSQ/32, DD/32, BB), dim3(32,8)>>>(sT, rl, DD, NSQ);
        k_e2l<<<BB*NSQ, 256>>>(rl, Lout);
    }

    // ---- linear layers (tensor cores) ----
    k_tgemm<0,1,1><<<dim3(3,256,1),256>>>(Lc, WlW, Wlb, Llin,
        BB*NCQ, DP1, DP1, DP1, DP1, DP1, 0, 0, 0);
    k_fix_time<<<BB*NCQ, 256>>>(Llin);

    k_tgemm<0,1,1><<<dim3(2,256,1),256>>>(Ls, WsW, Wsb, Yt,
        BB*NSQ, KP1, DP1, DP1, DP1, KP1, 0, 0, 0);
    k_poincare<<<BB*NSQ, 128>>>(Yt, Hsa);

    k_tgemm<0,1,1><<<dim3(2,256,1),256>>>(Lc, WcW, Wcb, Yt,
        BB*NCQ, KP1, DP1, DP1, DP1, KP1, 0, 0, 0);
    k_poincare<<<BB*NCQ, 128>>>(Yt, Hca);

    // ---- big einsum + lorentz_act (fused gelu epilogue) ----
    k_tgemm<0,1,2><<<dim3(8,8,BB),256>>>(Ls, Llin, nullptr, Lb,
        NSQ, NCQ, DP1, DP1, DP1, NCQ,
        (long)NSQ*DP1, (long)NCQ*DP1, (long)NSQ*NCQ);
    k_rowfix<<<BB*NSQ, 256>>>(Lb, xnr);
    k_colnorm<<<dim3(NCQ/256, BB), 256>>>(Lb, xnc);

    // ---- mobius_matvec GEMMs ----
    k_tgemm<0,0,0><<<dim3(1,8,BB),256>>>(Lb, Hca, nullptr, Mxs,
        NSQ, KKW, NCQ, NCQ, KKW, KKW,
        (long)NSQ*NCQ, (long)NCQ*KKW, (long)NSQ*KKW);
    k_tgemm<1,0,0><<<dim3(1,8,BB),256>>>(Lb, Hsa, nullptr, Mxc,
        NCQ, KKW, NSQ, NCQ, KKW, KKW,
        (long)NSQ*NCQ, (long)NSQ*KKW, (long)NCQ*KKW);
    k_mfin<<<BB*NCQ, 128>>>(Mxc, xnc);

    // ---- mobius_add + gelu pipeline + attention logits ----
    k_hs<<<BB*NSQ, 128>>>(Hsa, Mxs, xnr, whs, lgs);
    k_hc<<<BB*KKW, 256>>>(Hca, Mxc, Hcm);
    k_ac<<<dim3(NCQ/256, BB), 256>>>(Hcm, whc, lgc);

    // ---- softmaxes straight into output ----
    k_softmax<<<BB, 256>>>(lgs, out + AS_OFF);
    k_softmax<<<BB, 256>>>(lgc, out + AC_OFF);

    // ---- centroids + concat ----
    k_centroid<<<BB, 288>>>(Ls, out + AS_OFF, cs);
    k_centroid<<<BB, 288>>>(Lc, out + AC_OFF, cc);
    k_concat<<<BB, 256>>>(cs, cc, out);
}

// round 4
// speedup vs baseline: 1.5109x; 1.3446x over previous
#include <cuda_runtime.h>
#include <math.h>
#include <stdint.h>

#define BB  32
#define NSQ 1024
#define NCQ 1024
#define DD  256
#define DP1 257
#define DPAD 272
#define KKW 128
#define KP1 129

// ----------------------------- scratch (static device globals; no runtime alloc) ---
static __device__ float2 g_c1 [(size_t)BB*NSQ*DD];
static __device__ float2 g_c1T[(size_t)BB*DD*NSQ];
static __device__ float  g_sT [(size_t)BB*DD*NSQ];
static __device__ float  g_real[(size_t)BB*NSQ*DD];
static __device__ float  g_Ls [(size_t)BB*NSQ*DPAD];
static __device__ float  g_Lc [(size_t)BB*NCQ*DPAD];
static __device__ float  g_Llin[(size_t)BB*NCQ*DPAD];
static __device__ float  g_Yt [(size_t)BB*NSQ*KP1];
static __device__ float  g_Lb [(size_t)BB*NSQ*NCQ];
static __device__ float  g_xnr[BB*NSQ];
static __device__ float  g_xnc[BB*NCQ];
static __device__ float  g_Hsa[(size_t)BB*NSQ*KKW];
static __device__ float  g_Hca[(size_t)BB*NCQ*KKW];
static __device__ float  g_Mxs[(size_t)BB*NSQ*KKW];
static __device__ float  g_Mxc[(size_t)BB*NCQ*KKW];
static __device__ float  g_Hcm[(size_t)BB*KKW*NCQ];
static __device__ float  g_lgs[BB*NSQ];
static __device__ float  g_lgc[BB*NCQ];
static __device__ float  g_cs [BB*DP1];
static __device__ float  g_cc [BB*DP1];
static __device__ float  g_part[BB*8*DP1];
static __device__ float2 g_tw1024[1024];
static __device__ float2 g_tw256[256];

// ----------------------------- helpers ---------------------------------------------
__device__ __forceinline__ float atanhc(float x){
    x = fminf(fmaxf(x, -1.f + 1e-5f), 1.f - 1e-5f);
    return 0.5f * (log1pf(x) - log1pf(-x));
}
__device__ __forceinline__ float gelu_exact(float v){
    return 0.5f * v * (1.f + erff(v * 0.70710678118654752f));
}
__device__ __forceinline__ float2 cmul(float2 a, float2 b){
    return make_float2(a.x*b.x - a.y*b.y, a.x*b.y + a.y*b.x);
}
__device__ __forceinline__ float2 cadd(float2 a, float2 b){ return make_float2(a.x+b.x, a.y+b.y); }
__device__ __forceinline__ float2 csub(float2 a, float2 b){ return make_float2(a.x-b.x, a.y-b.y); }

__device__ __forceinline__ float blockReduceSum(float v){
    __shared__ float sh[32];
    #pragma unroll
    for (int o = 16; o; o >>= 1) v += __shfl_down_sync(0xffffffffu, v, o);
    int lane = threadIdx.x & 31, w = threadIdx.x >> 5;
    if (lane == 0) sh[w] = v;
    __syncthreads();
    int nw = (blockDim.x + 31) >> 5;
    v = (threadIdx.x < (unsigned)nw) ? sh[threadIdx.x] : 0.f;
    if (w == 0){
        #pragma unroll
        for (int o = 16; o; o >>= 1) v += __shfl_down_sync(0xffffffffu, v, o);
        if (lane == 0) sh[0] = v;
    }
    __syncthreads();
    float r = sh[0];
    __syncthreads();
    return r;
}
__device__ __forceinline__ void blockReduceSum3(float& a, float& b, float& c){
    __shared__ float sh3[32][3];
    #pragma unroll
    for (int o = 16; o; o >>= 1){
        a += __shfl_down_sync(0xffffffffu, a, o);
        b += __shfl_down_sync(0xffffffffu, b, o);
        c += __shfl_down_sync(0xffffffffu, c, o);
    }
    int lane = threadIdx.x & 31, w = threadIdx.x >> 5;
    if (lane == 0){ sh3[w][0] = a; sh3[w][1] = b; sh3[w][2] = c; }
    __syncthreads();
    int nw = (blockDim.x + 31) >> 5;
    a = (threadIdx.x < (unsigned)nw) ? sh3[threadIdx.x][0] : 0.f;
    b = (threadIdx.x < (unsigned)nw) ? sh3[threadIdx.x][1] : 0.f;
    c = (threadIdx.x < (unsigned)nw) ? sh3[threadIdx.x][2] : 0.f;
    if (w == 0){
        #pragma unroll
        for (int o = 16; o; o >>= 1){
            a += __shfl_down_sync(0xffffffffu, a, o);
            b += __shfl_down_sync(0xffffffffu, b, o);
            c += __shfl_down_sync(0xffffffffu, c, o);
        }
        if (lane == 0){ sh3[0][0] = a; sh3[0][1] = b; sh3[0][2] = c; }
    }
    __syncthreads();
    a = sh3[0][0]; b = sh3[0][1]; c = sh3[0][2];
    __syncthreads();
}
__device__ __forceinline__ float blockReduceMax(float v){
    __shared__ float sh[32];
    #pragma unroll
    for (int o = 16; o; o >>= 1) v = fmaxf(v, __shfl_down_sync(0xffffffffu, v, o));
    int lane = threadIdx.x & 31, w = threadIdx.x >> 5;
    if (lane == 0) sh[w] = v;
    __syncthreads();
    int nw = (blockDim.x + 31) >> 5;
    v = (threadIdx.x < (unsigned)nw) ? sh[threadIdx.x] : -3.4e38f;
    if (w == 0){
        #pragma unroll
        for (int o = 16; o; o >>= 1) v = fmaxf(v, __shfl_down_sync(0xffffffffu, v, o));
        if (lane == 0) sh[0] = v;
    }
    __syncthreads();
    float r = sh[0];
    __syncthreads();
    return r;
}
__device__ __forceinline__ uint32_t f2tf32(float v){
    uint32_t r;
    asm("cvt.rna.tf32.f32 %0, %1;" : "=r"(r) : "f"(v));
    return r;
}
__device__ __forceinline__ void split_tf32(float v, uint32_t& hi, uint32_t& lo){
    hi = f2tf32(v);
    lo = f2tf32(v - __uint_as_float(hi));
}
__device__ __forceinline__ void mma_tf32(float* c, const uint32_t* a, const uint32_t* b){
    asm volatile("mma.sync.aligned.m16n8k8.row.col.f32.tf32.tf32.f32 "
        "{%0,%1,%2,%3}, {%4,%5,%6,%7}, {%8,%9}, {%0,%1,%2,%3};"
        : "+f"(c[0]), "+f"(c[1]), "+f"(c[2]), "+f"(c[3])
        : "r"(a[0]), "r"(a[1]), "r"(a[2]), "r"(a[3]), "r"(b[0]), "r"(b[1]));
}
__device__ __forceinline__ void cpa16(uint32_t dsh, const void* src){
    asm volatile("cp.async.ca.shared.global [%0], [%1], 16;" :: "r"(dsh), "l"(src));
}
__device__ __forceinline__ void cpa4z(uint32_t dsh, const void* src, bool pred){
    int sz = pred ? 4 : 0;
    asm volatile("cp.async.ca.shared.global [%0], [%1], 4, %2;" :: "r"(dsh), "l"(src), "r"(sz));
}
#define CP_COMMIT() asm volatile("cp.async.commit_group;" ::: "memory")
#define CP_WAIT1()  asm volatile("cp.async.wait_group 1;" ::: "memory")
#define CP_WAIT0()  asm volatile("cp.async.wait_group 0;" ::: "memory")

// ----------------------------- twiddle fill ----------------------------------------
__global__ void k_twfill(){
    int i = threadIdx.x;
    if (i < 1024){
        double a = -6.283185307179586476925287 * (double)i / 1024.0;
        g_tw1024[i] = make_float2((float)cos(a), (float)sin(a));
    }
    if (i < 256){
        double a = -6.283185307179586476925287 * (double)i / 256.0;
        g_tw256[i] = make_float2((float)cos(a), (float)sin(a));
    }
}

// ----------------------------- radix-4 Stockham FFT kernels ------------------------
__global__ void k_fft256(const float* __restrict__ in, float2* __restrict__ out, int do_log){
    __shared__ float2 bufA[4][256];
    __shared__ float2 bufB[4][256];
    __shared__ float2 tws[256];
    __shared__ float  rsum[4][2];
    int tx = threadIdx.x;                      // 64
    int ty = threadIdx.y;                      // 4
    int tid = ty*64 + tx;
    size_t row = (size_t)blockIdx.x*4 + ty;
    tws[tid] = g_tw256[tid];

    const float* x = in + row*256;
    float v0 = x[tx], v1 = x[tx+64], v2 = x[tx+128], v3 = x[tx+192];
    float ss = v0*v0 + v1*v1 + v2*v2 + v3*v3;
    #pragma unroll
    for (int o = 16; o; o >>= 1) ss += __shfl_down_sync(0xffffffffu, ss, o);
    if ((tx & 31) == 0) rsum[ty][tx >> 5] = ss;
    __syncthreads();
    if (do_log){
        float tot = rsum[ty][0] + rsum[ty][1];
        float yn = sqrtf(fmaxf(tot, 1e-15f));
        float f = atanhc(yn) / yn;
        v0 *= f; v1 *= f; v2 *= f; v3 *= f;
    }
    bufA[ty][tx]       = make_float2(v0, 0.f);
    bufA[ty][tx + 64]  = make_float2(v1, 0.f);
    bufA[ty][tx + 128] = make_float2(v2, 0.f);
    bufA[ty][tx + 192] = make_float2(v3, 0.f);
    __syncthreads();

    float2* X = &bufA[ty][0];
    float2* Y = &bufB[ty][0];
    #pragma unroll
    for (int s = 0; s < 4; s++){
        int Ns = 1 << (2*s);
        int p = tx & (Ns - 1);
        float2 w1 = tws[p * (64/Ns)];
        float2 w2 = cmul(w1, w1);
        float2 w3 = cmul(w2, w1);
        float2 a0 = X[tx];
        float2 a1 = cmul(X[tx + 64],  w1);
        float2 a2 = cmul(X[tx + 128], w2);
        float2 a3 = cmul(X[tx + 192], w3);
        float2 pa = cadd(a0, a2), pb = csub(a0, a2);
        float2 pc = cadd(a1, a3), pd = csub(a1, a3);
        float2 dneg = make_float2(pd.y, -pd.x);
        float2 dpos = make_float2(-pd.y, pd.x);
        int idxD = ((tx >> (2*s)) << (2*s + 2)) + p;
        Y[idxD]          = cadd(pa, pc);
        Y[idxD + Ns]     = cadd(pb, dneg);
        Y[idxD + 2*Ns]   = csub(pa, pc);
        Y[idxD + 3*Ns]   = cadd(pb, dpos);
        __syncthreads();
        float2* tmp = X; X = Y; Y = tmp;
    }
    out[row*256 + tx]       = X[tx];
    out[row*256 + tx + 64]  = X[tx + 64];
    out[row*256 + tx + 128] = X[tx + 128];
    out[row*256 + tx + 192] = X[tx + 192];
}

__global__ void k_fft1024(const float2* __restrict__ in, float* __restrict__ outr){
    __shared__ float2 bufA[1024];
    __shared__ float2 bufB[1024];
    __shared__ float2 tws[1024];
    int t = threadIdx.x;                       // 256
    size_t row = blockIdx.x;
    const float2* src = in + row*1024;
    #pragma unroll
    for (int i = 0; i < 4; i++){
        tws[t + i*256]  = g_tw1024[t + i*256];
        bufA[t + i*256] = src[t + i*256];
    }
    __syncthreads();
    float2* X = bufA;
    float2* Y = bufB;
    #pragma unroll
    for (int s = 0; s < 5; s++){
        int Ns = 1 << (2*s);
        int p = t & (Ns - 1);
        float2 w1 = tws[p * (256/Ns)];
        float2 w2 = cmul(w1, w1);
        float2 w3 = cmul(w2, w1);
        float2 a0 = X[t];
        float2 a1 = cmul(X[t + 256], w1);
        float2 a2 = cmul(X[t + 512], w2);
        float2 a3 = cmul(X[t + 768], w3);
        float2 pa = cadd(a0, a2), pb = csub(a0, a2);
        float2 pc = cadd(a1, a3), pd = csub(a1, a3);
        float2 dneg = make_float2(pd.y, -pd.x);
        float2 dpos = make_float2(-pd.y, pd.x);
        int idxD = ((t >> (2*s)) << (2*s + 2)) + p;
        Y[idxD]        = cadd(pa, pc);
        Y[idxD + Ns]   = cadd(pb, dneg);
        Y[idxD + 2*Ns] = csub(pa, pc);
        Y[idxD + 3*Ns] = cadd(pb, dpos);
        __syncthreads();
        float2* tmp = X; X = Y; Y = tmp;
    }
    #pragma unroll
    for (int i = 0; i < 4; i++)
        outr[row*1024 + t + i*256] = X[t + i*256].x;
}

__global__ void k_transpose_c(const float2* __restrict__ in, float2* __restrict__ out, int R, int C){
    __shared__ float2 tile[32][33];
    int b = blockIdx.z;
    size_t base = (size_t)b * R * C;
    int c0 = blockIdx.x * 32, r0 = blockIdx.y * 32;
    for (int i = threadIdx.y; i < 32; i += 8)
        tile[i][threadIdx.x] = in[base + (size_t)(r0+i)*C + (c0+threadIdx.x)];
    __syncthreads();
    for (int i = threadIdx.y; i < 32; i += 8)
        out[base + (size_t)(c0+i)*R + (r0+threadIdx.x)] = tile[threadIdx.x][i];
}
__global__ void k_transpose_f(const float* __restrict__ in, float* __restrict__ out, int R, int C){
    __shared__ float tile[32][33];
    int b = blockIdx.z;
    size_t base = (size_t)b * R * C;
    int c0 = blockIdx.x * 32, r0 = blockIdx.y * 32;
    for (int i = threadIdx.y; i < 32; i += 8)
        tile[i][threadIdx.x] = in[base + (size_t)(r0+i)*C + (c0+threadIdx.x)];
    __syncthreads();
    for (int i = threadIdx.y; i < 32; i += 8)
        out[base + (size_t)(c0+i)*R + (r0+threadIdx.x)] = tile[threadIdx.x][i];
}

// euclid_to_lorentz: 256-wide row -> DPAD-wide Lorentz row (pad zeroed)
__global__ void k_e2l(const float* __restrict__ in, float* __restrict__ out){
    size_t row = blockIdx.x;
    int t = threadIdx.x;                       // 256
    float v = in[row*256 + t];
    float ss = blockReduceSum(v*v);
    float xn = sqrtf(fmaxf(ss, 1e-15f)) + 1e-5f;
    float scl = fminf(1.f, 2.0f / xn);
    v *= scl;
    float vn = sqrtf(fmaxf(ss*scl*scl, 1e-15f));
    float f = sinhf(vn) / vn;
    if (t == 0) out[row*DPAD] = coshf(vn);
    out[row*DPAD + 1 + t] = f * v;
    if (t < DPAD - DP1) out[row*DPAD + DP1 + t] = 0.f;
}

// zero pad columns [257,272) of a DPAD-stride matrix
__global__ void k_zpad(float* __restrict__ p, int rows){
    int idx = blockIdx.x*1024 + threadIdx.x;
    int r = idx / 15, c = idx % 15;
    if (r < rows) p[(size_t)r*DPAD + DP1 + c] = 0.f;
}

// --------------- pipelined tensor-core GEMM (3xTF32, cp.async double-buffered) -----
//  ATRANS=0: A is M x K (lda)    ATRANS=1: A is K x M (lda)
//  BTRANS=1: B is N x K (ldb)    BTRANS=0: B is K x N (ldb)
//  VECA/VECB: 4 = guard-free float4 cp.async (operands padded/aligned), 1 = 4B+zfill
//  MODE: 0 plain, 1 +bias[n], 2 gelu except global col 0 (col0 -> 0)
template<int ATRANS, int BTRANS, int MODE, int VECA, int VECB>
__global__ void k_pgemm(const float* __restrict__ A, const float* __restrict__ Bm,
                        const float* __restrict__ bias, float* __restrict__ C,
                        int M, int N, int Klen, int lda, int ldb, int ldc,
                        long sA, long sB, long sC)
{
    constexpr int A_ELE = (ATRANS == 0) ? 128*20 : 16*132;
    constexpr int B_ELE = (BTRANS == 1) ? 128*20 : 16*132;
    __shared__ __align__(16) float As[2][A_ELE];
    __shared__ __align__(16) float Bs[2][B_ELE];

    int bz = blockIdx.z;
    A  += (size_t)bz * sA;
    Bm += (size_t)bz * sB;
    C  += (size_t)bz * sC;
    int bm = blockIdx.y * 128, bn = blockIdx.x * 128;
    int tid = threadIdx.x;
    int wid = tid >> 5, lane = tid & 31;
    int wm = (wid >> 2) * 64;
    int wn = (wid & 3) * 32;
    int g = lane >> 2, tg = lane & 3;

    int KT = (Klen + 15) >> 4;

    uint32_t asBase = (uint32_t)__cvta_generic_to_shared(&As[0][0]);
    uint32_t bsBase = (uint32_t)__cvta_generic_to_shared(&Bs[0][0]);

    auto issueA = [&](int st, int k0){
        uint32_t base = asBase + (uint32_t)(st * A_ELE * 4);
        if (ATRANS == 0){
            if (VECA == 4){
                #pragma unroll
                for (int i = 0; i < 2; i++){
                    int idx = tid + i*256;
                    int mm = idx >> 2, k4 = idx & 3;
                    cpa16(base + (mm*20 + k4*4)*4, A + (size_t)(bm+mm)*lda + k0 + k4*4);
                }
            } else {
                #pragma unroll
                for (int i = 0; i < 8; i++){
                    int idx = tid + i*256;
                    int mm = idx >> 4, kk = idx & 15;
                    int gm = bm + mm, gk = k0 + kk;
                    bool ok = (gm < M) && (gk < Klen);
                    const float* src = A + (ok ? ((size_t)gm*lda + gk) : 0);
                    cpa4z(base + (mm*20 + kk)*4, src, ok);
                }
            }
        } else {
            if (VECA == 4){
                #pragma unroll
                for (int i = 0; i < 2; i++){
                    int idx = tid + i*256;
                    int kk = idx >> 5, m4 = idx & 31;
                    cpa16(base + (kk*132 + m4*4)*4, A + (size_t)(k0+kk)*lda + bm + m4*4);
                }
            } else {
                #pragma unroll
                for (int i = 0; i < 8; i++){
                    int idx = tid + i*256;
                    int kk = idx >> 7, mm = idx & 127;
                    int gm = bm + mm, gk = k0 + kk;
                    bool ok = (gm < M) && (gk < Klen);
                    const float* src = A + (ok ? ((size_t)gk*lda + gm) : 0);
                    cpa4z(base + (kk*132 + mm)*4, src, ok);
                }
            }
        }
    };
    auto issueB = [&](int st, int k0){
        uint32_t base = bsBase + (uint32_t)(st * B_ELE * 4);
        if (BTRANS == 1){
            if (VECB == 4){
                #pragma unroll
                for (int i = 0; i < 2; i++){
                    int idx = tid + i*256;
                    int nn = idx >> 2, k4 = idx & 3;
                    cpa16(base + (nn*20 + k4*4)*4, Bm + (size_t)(bn+nn)*ldb + k0 + k4*4);
                }
            } else {
                #pragma unroll
                for (int i = 0; i < 8; i++){
                    int idx = tid + i*256;
                    int nn = idx >> 4, kk = idx & 15;
                    int gn = bn + nn, gk = k0 + kk;
                    bool ok = (gn < N) && (gk < Klen);
                    const float* src = Bm + (ok ? ((size_t)gn*ldb + gk) : 0);
                    cpa4z(base + (nn*20 + kk)*4, src, ok);
                }
            }
        } else {
            if (VECB == 4){
                #pragma unroll
                for (int i = 0; i < 2; i++){
                    int idx = tid + i*256;
                    int kk = idx >> 5, n4 = idx & 31;
                    cpa16(base + (kk*132 + n4*4)*4, Bm + (size_t)(k0+kk)*ldb + bn + n4*4);
                }
            } else {
                #pragma unroll
                for (int i = 0; i < 8; i++){
                    int idx = tid + i*256;
                    int kk = idx >> 7, nn = idx & 127;
                    int gn = bn + nn, gk = k0 + kk;
                    bool ok = (gn < N) && (gk < Klen);
                    const float* src = Bm + (ok ? ((size_t)gk*ldb + gn) : 0);
                    cpa4z(base + (kk*132 + nn)*4, src, ok);
                }
            }
        }
    };
    auto A_at = [&](int st, int m, int k)->float{
        return (ATRANS == 0) ? As[st][m*20 + k] : As[st][k*132 + m];
    };
    auto B_at = [&](int st, int n, int k)->float{
        return (BTRANS == 1) ? Bs[st][n*20 + k] : Bs[st][k*132 + n];
    };

    float acc[4][4][4];
    #pragma unroll
    for (int mi = 0; mi < 4; mi++)
        #pragma unroll
        for (int ni = 0; ni < 4; ni++)
            #pragma unroll
            for (int r = 0; r < 4; r++) acc[mi][ni][r] = 0.f;

    issueA(0, 0); issueB(0, 0);
    CP_COMMIT();

    for (int kt = 0; kt < KT; kt++){
        int st = kt & 1;
        if (kt + 1 < KT){
            issueA(st ^ 1, (kt+1)*16);
            issueB(st ^ 1, (kt+1)*16);
            CP_COMMIT();
            CP_WAIT1();
        } else {
            CP_WAIT0();
        }
        __syncthreads();

        #pragma unroll
        for (int ks = 0; ks < 2; ks++){
            int kk = ks*8;
            uint32_t bhf[4][2], blf[4][2];
            #pragma unroll
            for (int ni = 0; ni < 4; ni++){
                int n = wn + ni*8 + g;
                split_tf32(B_at(st, n, kk+tg),   bhf[ni][0], blf[ni][0]);
                split_tf32(B_at(st, n, kk+tg+4), bhf[ni][1], blf[ni][1]);
            }
            #pragma unroll
            for (int mi = 0; mi < 4; mi++){
                int m = wm + mi*16;
                uint32_t ahf[4], alf[4];
                split_tf32(A_at(st, m+g,   kk+tg),   ahf[0], alf[0]);
                split_tf32(A_at(st, m+g+8, kk+tg),   ahf[1], alf[1]);
                split_tf32(A_at(st, m+g,   kk+tg+4), ahf[2], alf[2]);
                split_tf32(A_at(st, m+g+8, kk+tg+4), ahf[3], alf[3]);
                #pragma unroll
                for (int ni = 0; ni < 4; ni++){
                    mma_tf32(acc[mi][ni], alf, bhf[ni]);
                    mma_tf32(acc[mi][ni], ahf, blf[ni]);
                    mma_tf32(acc[mi][ni], ahf, bhf[ni]);
                }
            }
        }
        __syncthreads();
    }

    #pragma unroll
    for (int mi = 0; mi < 4; mi++){
        #pragma unroll
        for (int ni = 0; ni < 4; ni++){
            int col = bn + wn + ni*8 + 2*tg;
            #pragma unroll
            for (int r = 0; r < 4; r++){
                int gm = bm + wm + mi*16 + g + (r >= 2 ? 8 : 0);
                int gn = col + (r & 1);
                if (gn >= N) continue;
                float v = acc[mi][ni][r];
                if (MODE == 1) v += bias[gn];
                if (MODE == 2) v = (gn == 0) ? 0.f : gelu_exact(v);
                C[(size_t)gm*ldc + gn] = v;
            }
        }
    }
}

// ----------------------------- row-wise kernels ------------------------------------
__global__ void k_fix_time(float* __restrict__ Y){        // DPAD stride
    size_t row = blockIdx.x;
    int t = threadIdx.x;                                  // 256
    float sp = Y[row*DPAD + 1 + t];
    float S = blockReduceSum(sp*sp);
    if (t == 0) Y[row*DPAD] = sqrtf(S + 1.f);
}
__global__ void k_poincare(const float* __restrict__ Y, float* __restrict__ out){
    size_t row = blockIdx.x;
    int t = threadIdx.x;                                  // 128
    float sp = Y[row*KP1 + 1 + t];
    float S = blockReduceSum(sp*sp);
    float time = sqrtf(S + 1.f);
    out[row*KKW + t] = sp / (time + 1.f);
}
__global__ void k_rowfix(float* __restrict__ L, float* __restrict__ xnr){
    size_t row = blockIdx.x;
    int t = threadIdx.x;                                  // 256
    float* p = L + row*1024;
    float s = 0.f;
    #pragma unroll
    for (int i = 0; i < 4; i++){ float v = p[t + i*256]; s += v*v; }
    float S = blockReduceSum(s);
    if (t == 0){
        p[0] = sqrtf(S + 1.f);
        xnr[row] = sqrtf(fmaxf(2.f*S + 1.f, 1e-15f));
    }
}
__global__ void k_colnorm(const float* __restrict__ L, float* __restrict__ xnc){
    int b = blockIdx.y;
    int m = blockIdx.x*256 + threadIdx.x;
    const float* base = L + (size_t)b*NSQ*NCQ + m;
    float cs = 0.f;
    for (int n = 0; n < NSQ; n++){ float v = base[(size_t)n*NCQ]; cs += v*v; }
    xnc[b*NCQ + m] = sqrtf(fmaxf(cs, 1e-15f));
}
__global__ void k_mfin(float* __restrict__ Mx, const float* __restrict__ xna){
    size_t row = blockIdx.x;
    int t = threadIdx.x;                                  // 128
    float v = Mx[row*KKW + t];
    float mm = blockReduceSum(v*v);
    float mxn = sqrtf(fmaxf(mm, 1e-15f));
    float xn = xna[row];
    float s = tanhf(mxn / xn * atanhc(xn)) / mxn;
    Mx[row*KKW + t] = v * s;
}
__global__ void k_hs(const float* __restrict__ Hsa, const float* __restrict__ MxRaw,
                     const float* __restrict__ xnr,
                     const float* __restrict__ whs, float* __restrict__ lg){
    size_t row = blockIdx.x;
    int t = threadIdx.x;                                  // 128
    float yr = MxRaw[row*KKW + t];
    float mm = blockReduceSum(yr*yr);
    float mxn = sqrtf(fmaxf(mm, 1e-15f));
    float xnb = xnr[row];
    float y = yr * (tanhf(mxn / xnb * atanhc(xnb)) / mxn);

    float x = Hsa[row*KKW + t];
    float xy = x*y, x2 = x*x, y2 = y*y;
    blockReduceSum3(xy, x2, y2);
    float den = fmaxf(1.f + 2.f*xy + x2*y2, 1e-15f);
    float h = ((1.f + 2.f*xy + y2)*x + (1.f - x2)*y) / den;
    float hn = sqrtf(fmaxf(blockReduceSum(h*h), 1e-15f));
    float u = atanhc(hn) / hn * h;
    float gv = gelu_exact(u);
    float gn = sqrtf(fmaxf(blockReduceSum(gv*gv), 1e-15f));
    float hs = tanhf(gn) / gn * gv;
    float mx = hs * whs[t], xn2 = hs*hs, dmy = 0.f;
    blockReduceSum3(mx, xn2, dmy);
    if (t == 0){
        float xn = sqrtf(fmaxf(xn2, 1e-15f));
        float mxn2 = sqrtf(fmaxf(mx*mx, 1e-15f));
        lg[row] = tanhf(mxn2 / xn * atanhc(xn)) * mx / mxn2;
    }
}
__global__ void k_hc(const float* __restrict__ Hca, const float* __restrict__ Yb,
                     float* __restrict__ Hc){
    int bj = blockIdx.x;
    int b = bj >> 7, j = bj & 127;
    int t = threadIdx.x;                                  // 256
    float x[4], y[4];
    #pragma unroll
    for (int i = 0; i < 4; i++){
        int m = t + i*256;
        size_t idx = ((size_t)(b*NCQ + m))*KKW + j;
        x[i] = Hca[idx]; y[i] = Yb[idx];
    }
    float sxy = 0.f, sx2 = 0.f, sy2 = 0.f;
    #pragma unroll
    for (int i = 0; i < 4; i++){ sxy += x[i]*y[i]; sx2 += x[i]*x[i]; sy2 += y[i]*y[i]; }
    blockReduceSum3(sxy, sx2, sy2);
    float xy = sxy, x2 = sx2, y2 = sy2;
    float den = fmaxf(1.f + 2.f*xy + x2*y2, 1e-15f);
    float c1 = 1.f + 2.f*xy + y2, c2 = 1.f - x2;
    float h[4], hh = 0.f;
    #pragma unroll
    for (int i = 0; i < 4; i++){ h[i] = (c1*x[i] + c2*y[i]) / den; hh += h[i]*h[i]; }
    float hn = sqrtf(fmaxf(blockReduceSum(hh), 1e-15f));
    float fa = atanhc(hn) / hn;
    float g[4], gg = 0.f;
    #pragma unroll
    for (int i = 0; i < 4; i++){ g[i] = gelu_exact(fa*h[i]); gg += g[i]*g[i]; }
    float gn = sqrtf(fmaxf(blockReduceSum(gg), 1e-15f));
    float fb = tanhf(gn) / gn;
    #pragma unroll
    for (int i = 0; i < 4; i++)
        Hc[((size_t)(b*KKW + j))*NCQ + (t + i*256)] = fb * g[i];
}
__global__ void k_ac(const float* __restrict__ Hc, const float* __restrict__ whc,
                     float* __restrict__ lg){
    __shared__ float wsh[KKW];
    int b = blockIdx.y;
    int m = blockIdx.x*256 + threadIdx.x;
    if (threadIdx.x < KKW) wsh[threadIdx.x] = whc[threadIdx.x];
    __syncthreads();
    const float* base = Hc + (size_t)b*KKW*NCQ + m;
    float mx = 0.f, ss = 0.f;
    #pragma unroll 4
    for (int j = 0; j < KKW; j++){
        float v = base[(size_t)j*NCQ];
        mx += v * wsh[j]; ss += v*v;
    }
    float xn = sqrtf(fmaxf(ss, 1e-15f));
    float mxn = sqrtf(fmaxf(mx*mx, 1e-15f));
    lg[b*NCQ + m] = tanhf(mxn / xn * atanhc(xn)) * mx / mxn;
}
__global__ void k_softmax(const float* __restrict__ lg, float* __restrict__ out){
    int b = blockIdx.x, t = threadIdx.x;                  // 256
    float l[4];
    float lm = -3.4e38f;
    #pragma unroll
    for (int i = 0; i < 4; i++){ l[i] = lg[b*1024 + t + i*256]; lm = fmaxf(lm, l[i]); }
    float M = blockReduceMax(lm);
    float es = 0.f, e[4];
    #pragma unroll
    for (int i = 0; i < 4; i++){ e[i] = expf(l[i] - M); es += e[i]; }
    float S = blockReduceSum(es);
    #pragma unroll
    for (int i = 0; i < 4; i++) out[b*1024 + t + i*256] = e[i] / S;
}
// centroid: partial sums over n-chunks of 128
__global__ void k_centroid_part(const float* __restrict__ Lx, const float* __restrict__ w,
                                float* __restrict__ part){
    __shared__ float wsh[128];
    int ch = blockIdx.x, b = blockIdx.y;
    int t = threadIdx.x;                                  // 288, t<257 active
    for (int i = t; i < 128; i += blockDim.x) wsh[i] = w[(size_t)b*NSQ + ch*128 + i];
    __syncthreads();
    if (t < DP1){
        const float* base = Lx + ((size_t)b*NSQ + (size_t)ch*128)*DPAD + t;
        float acc = 0.f;
        for (int n = 0; n < 128; n++) acc += wsh[n] * base[(size_t)n*DPAD];
        part[(b*8 + ch)*DP1 + t] = acc;
    }
}
__global__ void k_centroid_fin(const float* __restrict__ part, float* __restrict__ co){
    __shared__ float t0sh;
    int b = blockIdx.x, t = threadIdx.x;                  // 288
    float acc = 0.f;
    if (t < DP1){
        #pragma unroll
        for (int c = 0; c < 8; c++) acc += part[(b*8 + c)*DP1 + t];
    }
    float sp = (t >= 1 && t < DP1) ? acc*acc : 0.f;
    float ssp = blockReduceSum(sp);
    if (t == 0) t0sh = acc;
    __syncthreads();
    float inner = -t0sh*t0sh + ssp;
    float den = sqrtf(fmaxf(fabsf(inner), 1e-8f));
    if (t < DP1) co[(size_t)b*DP1 + t] = acc / den;
}
__global__ void k_concat(const float* __restrict__ cs, const float* __restrict__ cc,
                         float* __restrict__ out){
    int b = blockIdx.x, t = threadIdx.x;                  // 256
    float t0s = cs[(size_t)b*DP1];
    float t0c = cc[(size_t)b*DP1];
    float sps = cs[(size_t)b*DP1 + 1 + t];
    float spc = cc[(size_t)b*DP1 + 1 + t];
    float ns  = sqrtf(fmaxf(blockReduceSum(sps*sps), 1e-15f));
    float ncv = sqrtf(fmaxf(blockReduceSum(spc*spc), 1e-15f));
    float zs = acoshf(fmaxf(t0s, 1.f + 1e-7f)) * sps / ns;
    float zc = acoshf(fmaxf(t0c, 1.f + 1e-7f)) * spc / ncv;
    float vn = sqrtf(fmaxf(blockReduceSum(zs*zs + zc*zc), 1e-15f));
    float f = sinhf(vn) / vn;
    float* o = out + (size_t)b*513;
    if (t == 0) o[0] = coshf(vn);
    o[1 + t]       = f * zs;
    o[1 + DD + t]  = f * zc;
}

// ----------------------------- launch ----------------------------------------------
extern "C" void kernel_launch(void* const* d_in, const int* in_sizes, int n_in,
                              void* d_out, int out_size)
{
    const float* sent = (const float*)d_in[0];
    const float* comm = (const float*)d_in[1];
    const float* WlW  = (const float*)d_in[2];
    const float* Wlb  = (const float*)d_in[3];
    const float* WcW  = (const float*)d_in[4];
    const float* Wcb  = (const float*)d_in[5];
    const float* WsW  = (const float*)d_in[6];
    const float* Wsb  = (const float*)d_in[7];
    const float* whs  = (const float*)d_in[8];
    const float* whc  = (const float*)d_in[9];
    float* out = (float*)d_out;
    (void)in_sizes; (void)n_in; (void)out_size;

    float2 *c1, *c1T;
    float *sT, *rl, *Ls, *Lc, *Llin, *Yt, *Lb, *xnr, *xnc, *Hsa, *Hca, *Mxs, *Mxc, *Hcm,
          *lgs, *lgc, *cs, *cc, *part;
    cudaGetSymbolAddress((void**)&c1,  g_c1);
    cudaGetSymbolAddress((void**)&c1T, g_c1T);
    cudaGetSymbolAddress((void**)&sT,  g_sT);
    cudaGetSymbolAddress((void**)&rl,  g_real);
    cudaGetSymbolAddress((void**)&Ls,  g_Ls);
    cudaGetSymbolAddress((void**)&Lc,  g_Lc);
    cudaGetSymbolAddress((void**)&Llin,g_Llin);
    cudaGetSymbolAddress((void**)&Yt,  g_Yt);
    cudaGetSymbolAddress((void**)&Lb,  g_Lb);
    cudaGetSymbolAddress((void**)&xnr, g_xnr);
    cudaGetSymbolAddress((void**)&xnc, g_xnc);
    cudaGetSymbolAddress((void**)&Hsa, g_Hsa);
    cudaGetSymbolAddress((void**)&Hca, g_Hca);
    cudaGetSymbolAddress((void**)&Mxs, g_Mxs);
    cudaGetSymbolAddress((void**)&Mxc, g_Mxc);
    cudaGetSymbolAddress((void**)&Hcm, g_Hcm);
    cudaGetSymbolAddress((void**)&lgs, g_lgs);
    cudaGetSymbolAddress((void**)&lgc, g_lgc);
    cudaGetSymbolAddress((void**)&cs,  g_cs);
    cudaGetSymbolAddress((void**)&cc,  g_cc);
    cudaGetSymbolAddress((void**)&part,g_part);

    const int AS_OFF = BB*513;             // 16416
    const int AC_OFF = AS_OFF + BB*NSQ;    // 49184

    k_twfill<<<1, 1024>>>();

    // ---- FFT2 + euclid_to_lorentz, both branches ----
    for (int branch = 0; branch < 2; branch++){
        const float* inp = branch ? comm : sent;
        float* Lout = branch ? Lc : Ls;
        int dolog = branch ? 1 : 0;
        k_fft256<<<BB*NSQ/4, dim3(64,4)>>>(inp, c1, dolog);
        k_transpose_c<<<dim3(DD/32, NSQ/32, BB), dim3(32,8)>>>(c1, c1T, NSQ, DD);
        k_fft1024<<<BB*DD, 256>>>(c1T, sT);
        k_transpose_f<<<dim3(NSQ/32, DD/32, BB), dim3(32,8)>>>(sT, rl, DD, NSQ);
        k_e2l<<<BB*NSQ, 256>>>(rl, Lout);
    }

    // ---- linear layers (pipelined tensor cores) ----
    k_pgemm<0,1,1,4,1><<<dim3(3,256,1),256>>>(Lc, WlW, Wlb, Llin,
        BB*NCQ, DP1, DP1, DPAD, DP1, DPAD, 0, 0, 0);
    k_zpad<<<(BB*NCQ*15 + 1023)/1024, 1024>>>(Llin, BB*NCQ);
    k_fix_time<<<BB*NCQ, 256>>>(Llin);

    k_pgemm<0,1,1,4,1><<<dim3(2,256,1),256>>>(Ls, WsW, Wsb, Yt,
        BB*NSQ, KP1, DP1, DPAD, DP1, KP1, 0, 0, 0);
    k_poincare<<<BB*NSQ, 128>>>(Yt, Hsa);

    k_pgemm<0,1,1,4,1><<<dim3(2,256,1),256>>>(Lc, WcW, Wcb, Yt,
        BB*NCQ, KP1, DP1, DPAD, DP1, KP1, 0, 0, 0);
    k_poincare<<<BB*NCQ, 128>>>(Yt, Hca);

    // ---- big einsum + lorentz_act (fused gelu epilogue) ----
    k_pgemm<0,1,2,4,4><<<dim3(8,8,BB),256>>>(Ls, Llin, nullptr, Lb,
        NSQ, NCQ, DP1, DPAD, DPAD, NCQ,
        (long)NSQ*DPAD, (long)NCQ*DPAD, (long)NSQ*NCQ);
    k_rowfix<<<BB*NSQ, 256>>>(Lb, xnr);
    k_colnorm<<<dim3(NCQ/256, BB), 256>>>(Lb, xnc);

    // ---- mobius_matvec GEMMs ----
    k_pgemm<0,0,0,4,4><<<dim3(1,8,BB),256>>>(Lb, Hca, nullptr, Mxs,
        NSQ, KKW, NCQ, NCQ, KKW, KKW,
        (long)NSQ*NCQ, (long)NCQ*KKW, (long)NSQ*KKW);
    k_pgemm<1,0,0,4,4><<<dim3(1,8,BB),256>>>(Lb, Hsa, nullptr, Mxc,
        NCQ, KKW, NSQ, NCQ, KKW, KKW,
        (long)NSQ*NCQ, (long)NSQ*KKW, (long)NCQ*KKW);
    k_mfin<<<BB*NCQ, 128>>>(Mxc, xnc);

    // ---- mobius_add + gelu pipeline + attention logits ----
    k_hs<<<BB*NSQ, 128>>>(Hsa, Mxs, xnr, whs, lgs);
    k_hc<<<BB*KKW, 256>>>(Hca, Mxc, Hcm);
    k_ac<<<dim3(NCQ/256, BB), 256>>>(Hcm, whc, lgc);

    // ---- softmaxes straight into output ----
    k_softmax<<<BB, 256>>>(lgs, out + AS_OFF);
    k_softmax<<<BB, 256>>>(lgc, out + AC_OFF);

    // ---- centroids + concat ----
    k_centroid_part<<<dim3(8,BB), 288>>>(Ls, out + AS_OFF, part);
    k_centroid_fin<<<BB, 288>>>(part, cs);
    k_centroid_part<<<dim3(8,BB), 288>>>(Lc, out + AC_OFF, part);
    k_centroid_fin<<<BB, 288>>>(part, cc);
    k_concat<<<BB, 256>>>(cs, cc, out);
}

// round 5
// speedup vs baseline: 1.7958x; 1.1885x over previous
#include <cuda_runtime.h>
#include <math.h>
#include <stdint.h>

#define BB  32
#define NSQ 1024
#define NCQ 1024
#define DD  256
#define DP1 257
#define DPAD 272
#define KKW 128
#define KP1 129

// ----------------------------- scratch (static device globals; no runtime alloc) ---
static __device__ float2 g_c1 [(size_t)BB*NSQ*DD];
static __device__ float2 g_c1T[(size_t)BB*DD*NSQ];
static __device__ float  g_sT [(size_t)BB*DD*NSQ];
static __device__ float  g_real[(size_t)BB*NSQ*DD];
static __device__ float  g_Ls [(size_t)BB*NSQ*DPAD];
static __device__ float  g_Lc [(size_t)BB*NCQ*DPAD];
static __device__ float  g_Llin[(size_t)BB*NCQ*DPAD];
static __device__ float  g_Yt [(size_t)BB*NSQ*KP1];
static __device__ float  g_Lb [(size_t)BB*NSQ*NCQ];
static __device__ float  g_xnr[BB*NSQ];
static __device__ float  g_xnc[BB*NCQ];
static __device__ float  g_msc[BB*NCQ];
static __device__ float  g_Hsa[(size_t)BB*NSQ*KKW];
static __device__ float  g_Hca[(size_t)BB*NCQ*KKW];
static __device__ float  g_Mxs[(size_t)BB*NSQ*KKW];
static __device__ float  g_Mxc[(size_t)BB*NCQ*KKW];
static __device__ float  g_Hcm[(size_t)BB*KKW*NCQ];
static __device__ float  g_lgs[BB*NSQ];
static __device__ float  g_lgc[BB*NCQ];
static __device__ float  g_cs [BB*DP1];
static __device__ float  g_cc [BB*DP1];
static __device__ float  g_part[BB*8*DP1];
static __device__ float2 g_tw1024[1024];
static __device__ float2 g_tw256[256];

// ----------------------------- helpers ---------------------------------------------
__device__ __forceinline__ float atanhc(float x){
    x = fminf(fmaxf(x, -1.f + 1e-5f), 1.f - 1e-5f);
    return 0.5f * (log1pf(x) - log1pf(-x));
}
__device__ __forceinline__ float gelu_exact(float v){
    return 0.5f * v * (1.f + erff(v * 0.70710678118654752f));
}
__device__ __forceinline__ float2 cmul(float2 a, float2 b){
    return make_float2(a.x*b.x - a.y*b.y, a.x*b.y + a.y*b.x);
}
__device__ __forceinline__ float2 cadd(float2 a, float2 b){ return make_float2(a.x+b.x, a.y+b.y); }
__device__ __forceinline__ float2 csub(float2 a, float2 b){ return make_float2(a.x-b.x, a.y-b.y); }

__device__ __forceinline__ float blockReduceSum(float v){
    __shared__ float sh[32];
    #pragma unroll
    for (int o = 16; o; o >>= 1) v += __shfl_down_sync(0xffffffffu, v, o);
    int lane = threadIdx.x & 31, w = threadIdx.x >> 5;
    if (lane == 0) sh[w] = v;
    __syncthreads();
    int nw = (blockDim.x + 31) >> 5;
    v = (threadIdx.x < (unsigned)nw) ? sh[threadIdx.x] : 0.f;
    if (w == 0){
        #pragma unroll
        for (int o = 16; o; o >>= 1) v += __shfl_down_sync(0xffffffffu, v, o);
        if (lane == 0) sh[0] = v;
    }
    __syncthreads();
    float r = sh[0];
    __syncthreads();
    return r;
}
__device__ __forceinline__ void blockReduceSum3(float& a, float& b, float& c){
    __shared__ float sh3[32][3];
    #pragma unroll
    for (int o = 16; o; o >>= 1){
        a += __shfl_down_sync(0xffffffffu, a, o);
        b += __shfl_down_sync(0xffffffffu, b, o);
        c += __shfl_down_sync(0xffffffffu, c, o);
    }
    int lane = threadIdx.x & 31, w = threadIdx.x >> 5;
    if (lane == 0){ sh3[w][0] = a; sh3[w][1] = b; sh3[w][2] = c; }
    __syncthreads();
    int nw = (blockDim.x + 31) >> 5;
    a = (threadIdx.x < (unsigned)nw) ? sh3[threadIdx.x][0] : 0.f;
    b = (threadIdx.x < (unsigned)nw) ? sh3[threadIdx.x][1] : 0.f;
    c = (threadIdx.x < (unsigned)nw) ? sh3[threadIdx.x][2] : 0.f;
    if (w == 0){
        #pragma unroll
        for (int o = 16; o; o >>= 1){
            a += __shfl_down_sync(0xffffffffu, a, o);
            b += __shfl_down_sync(0xffffffffu, b, o);
            c += __shfl_down_sync(0xffffffffu, c, o);
        }
        if (lane == 0){ sh3[0][0] = a; sh3[0][1] = b; sh3[0][2] = c; }
    }
    __syncthreads();
    a = sh3[0][0]; b = sh3[0][1]; c = sh3[0][2];
    __syncthreads();
}
__device__ __forceinline__ float blockReduceMax(float v){
    __shared__ float sh[32];
    #pragma unroll
    for (int o = 16; o; o >>= 1) v = fmaxf(v, __shfl_down_sync(0xffffffffu, v, o));
    int lane = threadIdx.x & 31, w = threadIdx.x >> 5;
    if (lane == 0) sh[w] = v;
    __syncthreads();
    int nw = (blockDim.x + 31) >> 5;
    v = (threadIdx.x < (unsigned)nw) ? sh[threadIdx.x] : -3.4e38f;
    if (w == 0){
        #pragma unroll
        for (int o = 16; o; o >>= 1) v = fmaxf(v, __shfl_down_sync(0xffffffffu, v, o));
        if (lane == 0) sh[0] = v;
    }
    __syncthreads();
    float r = sh[0];
    __syncthreads();
    return r;
}
__device__ __forceinline__ uint32_t f2tf32(float v){
    uint32_t r;
    asm("cvt.rna.tf32.f32 %0, %1;" : "=r"(r) : "f"(v));
    return r;
}
__device__ __forceinline__ void split_tf32(float v, uint32_t& hi, uint32_t& lo){
    hi = f2tf32(v);
    lo = f2tf32(v - __uint_as_float(hi));
}
__device__ __forceinline__ void mma_tf32(float* c, const uint32_t* a, const uint32_t* b){
    asm volatile("mma.sync.aligned.m16n8k8.row.col.f32.tf32.tf32.f32 "
        "{%0,%1,%2,%3}, {%4,%5,%6,%7}, {%8,%9}, {%0,%1,%2,%3};"
        : "+f"(c[0]), "+f"(c[1]), "+f"(c[2]), "+f"(c[3])
        : "r"(a[0]), "r"(a[1]), "r"(a[2]), "r"(a[3]), "r"(b[0]), "r"(b[1]));
}
__device__ __forceinline__ void cpa16(uint32_t dsh, const void* src){
    asm volatile("cp.async.ca.shared.global [%0], [%1], 16;" :: "r"(dsh), "l"(src));
}
__device__ __forceinline__ void cpa4z(uint32_t dsh, const void* src, bool pred){
    int sz = pred ? 4 : 0;
    asm volatile("cp.async.ca.shared.global [%0], [%1], 4, %2;" :: "r"(dsh), "l"(src), "r"(sz));
}
#define CP_COMMIT() asm volatile("cp.async.commit_group;" ::: "memory")
#define CP_WAIT1()  asm volatile("cp.async.wait_group 1;" ::: "memory")
#define CP_WAIT0()  asm volatile("cp.async.wait_group 0;" ::: "memory")

// ----------------------------- twiddle fill ----------------------------------------
__global__ void k_twfill(){
    int i = threadIdx.x;
    if (i < 1024){
        double a = -6.283185307179586476925287 * (double)i / 1024.0;
        g_tw1024[i] = make_float2((float)cos(a), (float)sin(a));
    }
    if (i < 256){
        double a = -6.283185307179586476925287 * (double)i / 256.0;
        g_tw256[i] = make_float2((float)cos(a), (float)sin(a));
    }
}

// ----------------------------- radix-4 Stockham FFT kernels ------------------------
__global__ void k_fft256(const float* __restrict__ in, float2* __restrict__ out, int do_log){
    __shared__ float2 bufA[4][256];
    __shared__ float2 bufB[4][256];
    __shared__ float2 tws[256];
    __shared__ float  rsum[4][2];
    int tx = threadIdx.x;                      // 64
    int ty = threadIdx.y;                      // 4
    int tid = ty*64 + tx;
    size_t row = (size_t)blockIdx.x*4 + ty;
    tws[tid] = g_tw256[tid];

    const float* x = in + row*256;
    float v0 = x[tx], v1 = x[tx+64], v2 = x[tx+128], v3 = x[tx+192];
    float ss = v0*v0 + v1*v1 + v2*v2 + v3*v3;
    #pragma unroll
    for (int o = 16; o; o >>= 1) ss += __shfl_down_sync(0xffffffffu, ss, o);
    if ((tx & 31) == 0) rsum[ty][tx >> 5] = ss;
    __syncthreads();
    if (do_log){
        float tot = rsum[ty][0] + rsum[ty][1];
        float yn = sqrtf(fmaxf(tot, 1e-15f));
        float f = atanhc(yn) / yn;
        v0 *= f; v1 *= f; v2 *= f; v3 *= f;
    }
    bufA[ty][tx]       = make_float2(v0, 0.f);
    bufA[ty][tx + 64]  = make_float2(v1, 0.f);
    bufA[ty][tx + 128] = make_float2(v2, 0.f);
    bufA[ty][tx + 192] = make_float2(v3, 0.f);
    __syncthreads();

    float2* X = &bufA[ty][0];
    float2* Y = &bufB[ty][0];
    #pragma unroll
    for (int s = 0; s < 4; s++){
        int Ns = 1 << (2*s);
        int p = tx & (Ns - 1);
        float2 w1 = tws[p * (64/Ns)];
        float2 w2 = cmul(w1, w1);
        float2 w3 = cmul(w2, w1);
        float2 a0 = X[tx];
        float2 a1 = cmul(X[tx + 64],  w1);
        float2 a2 = cmul(X[tx + 128], w2);
        float2 a3 = cmul(X[tx + 192], w3);
        float2 pa = cadd(a0, a2), pb = csub(a0, a2);
        float2 pc = cadd(a1, a3), pd = csub(a1, a3);
        float2 dneg = make_float2(pd.y, -pd.x);
        float2 dpos = make_float2(-pd.y, pd.x);
        int idxD = ((tx >> (2*s)) << (2*s + 2)) + p;
        Y[idxD]          = cadd(pa, pc);
        Y[idxD + Ns]     = cadd(pb, dneg);
        Y[idxD + 2*Ns]   = csub(pa, pc);
        Y[idxD + 3*Ns]   = cadd(pb, dpos);
        __syncthreads();
        float2* tmp = X; X = Y; Y = tmp;
    }
    out[row*256 + tx]       = X[tx];
    out[row*256 + tx + 64]  = X[tx + 64];
    out[row*256 + tx + 128] = X[tx + 128];
    out[row*256 + tx + 192] = X[tx + 192];
}

__global__ void k_fft1024(const float2* __restrict__ in, float* __restrict__ outr){
    __shared__ float2 bufA[1024];
    __shared__ float2 bufB[1024];
    __shared__ float2 tws[1024];
    int t = threadIdx.x;                       // 256
    size_t row = blockIdx.x;
    const float2* src = in + row*1024;
    #pragma unroll
    for (int i = 0; i < 4; i++){
        tws[t + i*256]  = g_tw1024[t + i*256];
        bufA[t + i*256] = src[t + i*256];
    }
    __syncthreads();
    float2* X = bufA;
    float2* Y = bufB;
    #pragma unroll
    for (int s = 0; s < 5; s++){
        int Ns = 1 << (2*s);
        int p = t & (Ns - 1);
        float2 w1 = tws[p * (256/Ns)];
        float2 w2 = cmul(w1, w1);
        float2 w3 = cmul(w2, w1);
        float2 a0 = X[t];
        float2 a1 = cmul(X[t + 256], w1);
        float2 a2 = cmul(X[t + 512], w2);
        float2 a3 = cmul(X[t + 768], w3);
        float2 pa = cadd(a0, a2), pb = csub(a0, a2);
        float2 pc = cadd(a1, a3), pd = csub(a1, a3);
        float2 dneg = make_float2(pd.y, -pd.x);
        float2 dpos = make_float2(-pd.y, pd.x);
        int idxD = ((t >> (2*s)) << (2*s + 2)) + p;
        Y[idxD]        = cadd(pa, pc);
        Y[idxD + Ns]   = cadd(pb, dneg);
        Y[idxD + 2*Ns] = csub(pa, pc);
        Y[idxD + 3*Ns] = cadd(pb, dpos);
        __syncthreads();
        float2* tmp = X; X = Y; Y = tmp;
    }
    #pragma unroll
    for (int i = 0; i < 4; i++)
        outr[row*1024 + t + i*256] = X[t + i*256].x;
}

__global__ void k_transpose_c(const float2* __restrict__ in, float2* __restrict__ out, int R, int C){
    __shared__ float2 tile[32][33];
    int b = blockIdx.z;
    size_t base = (size_t)b * R * C;
    int c0 = blockIdx.x * 32, r0 = blockIdx.y * 32;
    for (int i = threadIdx.y; i < 32; i += 8)
        tile[i][threadIdx.x] = in[base + (size_t)(r0+i)*C + (c0+threadIdx.x)];
    __syncthreads();
    for (int i = threadIdx.y; i < 32; i += 8)
        out[base + (size_t)(c0+i)*R + (r0+threadIdx.x)] = tile[threadIdx.x][i];
}
__global__ void k_transpose_f(const float* __restrict__ in, float* __restrict__ out, int R, int C){
    __shared__ float tile[32][33];
    int b = blockIdx.z;
    size_t base = (size_t)b * R * C;
    int c0 = blockIdx.x * 32, r0 = blockIdx.y * 32;
    for (int i = threadIdx.y; i < 32; i += 8)
        tile[i][threadIdx.x] = in[base + (size_t)(r0+i)*C + (c0+threadIdx.x)];
    __syncthreads();
    for (int i = threadIdx.y; i < 32; i += 8)
        out[base + (size_t)(c0+i)*R + (r0+threadIdx.x)] = tile[threadIdx.x][i];
}

// euclid_to_lorentz: 256-wide row -> DPAD-wide Lorentz row (pad zeroed)
__global__ void k_e2l(const float* __restrict__ in, float* __restrict__ out){
    size_t row = blockIdx.x;
    int t = threadIdx.x;                       // 256
    float v = in[row*256 + t];
    float ss = blockReduceSum(v*v);
    float xn = sqrtf(fmaxf(ss, 1e-15f)) + 1e-5f;
    float scl = fminf(1.f, 2.0f / xn);
    v *= scl;
    float vn = sqrtf(fmaxf(ss*scl*scl, 1e-15f));
    float f = sinhf(vn) / vn;
    if (t == 0) out[row*DPAD] = coshf(vn);
    out[row*DPAD + 1 + t] = f * v;
    if (t < DPAD - DP1) out[row*DPAD + DP1 + t] = 0.f;
}

// zero pad columns [257,272) of a DPAD-stride matrix
__global__ void k_zpad(float* __restrict__ p, int rows){
    int idx = blockIdx.x*1024 + threadIdx.x;
    int r = idx / 15, c = idx % 15;
    if (r < rows) p[(size_t)r*DPAD + DP1 + c] = 0.f;
}

// --------------- pipelined tensor-core GEMM (2xTF32, cp.async double-buffered) -----
//  D = ah*bh + ah*bl  (al dropped; ~1e-4 rel accuracy, threshold 1e-3)
template<int ATRANS, int BTRANS, int MODE, int VECA, int VECB>
__global__ void k_pgemm(const float* __restrict__ A, const float* __restrict__ Bm,
                        const float* __restrict__ bias, float* __restrict__ C,
                        int M, int N, int Klen, int lda, int ldb, int ldc,
                        long sA, long sB, long sC)
{
    constexpr int A_ELE = (ATRANS == 0) ? 128*20 : 16*132;
    constexpr int B_ELE = (BTRANS == 1) ? 128*20 : 16*132;
    __shared__ __align__(16) float As[2][A_ELE];
    __shared__ __align__(16) float Bs[2][B_ELE];

    int bz = blockIdx.z;
    A  += (size_t)bz * sA;
    Bm += (size_t)bz * sB;
    C  += (size_t)bz * sC;
    int bm = blockIdx.y * 128, bn = blockIdx.x * 128;
    int tid = threadIdx.x;
    int wid = tid >> 5, lane = tid & 31;
    int wm = (wid >> 2) * 64;
    int wn = (wid & 3) * 32;
    int g = lane >> 2, tg = lane & 3;

    int KT = (Klen + 15) >> 4;

    uint32_t asBase = (uint32_t)__cvta_generic_to_shared(&As[0][0]);
    uint32_t bsBase = (uint32_t)__cvta_generic_to_shared(&Bs[0][0]);

    auto issueA = [&](int st, int k0){
        uint32_t base = asBase + (uint32_t)(st * A_ELE * 4);
        if (ATRANS == 0){
            if (VECA == 4){
                #pragma unroll
                for (int i = 0; i < 2; i++){
                    int idx = tid + i*256;
                    int mm = idx >> 2, k4 = idx & 3;
                    cpa16(base + (mm*20 + k4*4)*4, A + (size_t)(bm+mm)*lda + k0 + k4*4);
                }
            } else {
                #pragma unroll
                for (int i = 0; i < 8; i++){
                    int idx = tid + i*256;
                    int mm = idx >> 4, kk = idx & 15;
                    int gm = bm + mm, gk = k0 + kk;
                    bool ok = (gm < M) && (gk < Klen);
                    const float* src = A + (ok ? ((size_t)gm*lda + gk) : 0);
                    cpa4z(base + (mm*20 + kk)*4, src, ok);
                }
            }
        } else {
            if (VECA == 4){
                #pragma unroll
                for (int i = 0; i < 2; i++){
                    int idx = tid + i*256;
                    int kk = idx >> 5, m4 = idx & 31;
                    cpa16(base + (kk*132 + m4*4)*4, A + (size_t)(k0+kk)*lda + bm + m4*4);
                }
            } else {
                #pragma unroll
                for (int i = 0; i < 8; i++){
                    int idx = tid + i*256;
                    int kk = idx >> 7, mm = idx & 127;
                    int gm = bm + mm, gk = k0 + kk;
                    bool ok = (gm < M) && (gk < Klen);
                    const float* src = A + (ok ? ((size_t)gk*lda + gm) : 0);
                    cpa4z(base + (kk*132 + mm)*4, src, ok);
                }
            }
        }
    };
    auto issueB = [&](int st, int k0){
        uint32_t base = bsBase + (uint32_t)(st * B_ELE * 4);
        if (BTRANS == 1){
            if (VECB == 4){
                #pragma unroll
                for (int i = 0; i < 2; i++){
                    int idx = tid + i*256;
                    int nn = idx >> 2, k4 = idx & 3;
                    cpa16(base + (nn*20 + k4*4)*4, Bm + (size_t)(bn+nn)*ldb + k0 + k4*4);
                }
            } else {
                #pragma unroll
                for (int i = 0; i < 8; i++){
                    int idx = tid + i*256;
                    int nn = idx >> 4, kk = idx & 15;
                    int gn = bn + nn, gk = k0 + kk;
                    bool ok = (gn < N) && (gk < Klen);
                    const float* src = Bm + (ok ? ((size_t)gn*ldb + gk) : 0);
                    cpa4z(base + (nn*20 + kk)*4, src, ok);
                }
            }
        } else {
            if (VECB == 4){
                #pragma unroll
                for (int i = 0; i < 2; i++){
                    int idx = tid + i*256;
                    int kk = idx >> 5, n4 = idx & 31;
                    cpa16(base + (kk*132 + n4*4)*4, Bm + (size_t)(k0+kk)*ldb + bn + n4*4);
                }
            } else {
                #pragma unroll
                for (int i = 0; i < 8; i++){
                    int idx = tid + i*256;
                    int kk = idx >> 7, nn = idx & 127;
                    int gn = bn + nn, gk = k0 + kk;
                    bool ok = (gn < N) && (gk < Klen);
                    const float* src = Bm + (ok ? ((size_t)gk*ldb + gn) : 0);
                    cpa4z(base + (kk*132 + nn)*4, src, ok);
                }
            }
        }
    };
    auto A_at = [&](int st, int m, int k)->float{
        return (ATRANS == 0) ? As[st][m*20 + k] : As[st][k*132 + m];
    };
    auto B_at = [&](int st, int n, int k)->float{
        return (BTRANS == 1) ? Bs[st][n*20 + k] : Bs[st][k*132 + n];
    };

    float acc[4][4][4];
    #pragma unroll
    for (int mi = 0; mi < 4; mi++)
        #pragma unroll
        for (int ni = 0; ni < 4; ni++)
            #pragma unroll
            for (int r = 0; r < 4; r++) acc[mi][ni][r] = 0.f;

    issueA(0, 0); issueB(0, 0);
    CP_COMMIT();

    for (int kt = 0; kt < KT; kt++){
        int st = kt & 1;
        if (kt + 1 < KT){
            issueA(st ^ 1, (kt+1)*16);
            issueB(st ^ 1, (kt+1)*16);
            CP_COMMIT();
            CP_WAIT1();
        } else {
            CP_WAIT0();
        }
        __syncthreads();

        #pragma unroll
        for (int ks = 0; ks < 2; ks++){
            int kk = ks*8;
            uint32_t bhf[4][2], blf[4][2];
            #pragma unroll
            for (int ni = 0; ni < 4; ni++){
                int n = wn + ni*8 + g;
                split_tf32(B_at(st, n, kk+tg),   bhf[ni][0], blf[ni][0]);
                split_tf32(B_at(st, n, kk+tg+4), bhf[ni][1], blf[ni][1]);
            }
            #pragma unroll
            for (int mi = 0; mi < 4; mi++){
                int m = wm + mi*16;
                uint32_t ahf[4];
                ahf[0] = f2tf32(A_at(st, m+g,   kk+tg));
                ahf[1] = f2tf32(A_at(st, m+g+8, kk+tg));
                ahf[2] = f2tf32(A_at(st, m+g,   kk+tg+4));
                ahf[3] = f2tf32(A_at(st, m+g+8, kk+tg+4));
                #pragma unroll
                for (int ni = 0; ni < 4; ni++){
                    mma_tf32(acc[mi][ni], ahf, blf[ni]);
                    mma_tf32(acc[mi][ni], ahf, bhf[ni]);
                }
            }
        }
        __syncthreads();
    }

    #pragma unroll
    for (int mi = 0; mi < 4; mi++){
        #pragma unroll
        for (int ni = 0; ni < 4; ni++){
            int col = bn + wn + ni*8 + 2*tg;
            #pragma unroll
            for (int r = 0; r < 4; r++){
                int gm = bm + wm + mi*16 + g + (r >= 2 ? 8 : 0);
                int gn = col + (r & 1);
                if (gn >= N) continue;
                float v = acc[mi][ni][r];
                if (MODE == 1) v += bias[gn];
                if (MODE == 2) v = (gn == 0) ? 0.f : gelu_exact(v);
                C[(size_t)gm*ldc + gn] = v;
            }
        }
    }
}

// ----------------------------- row-wise kernels ------------------------------------
__global__ void k_fix_time(float* __restrict__ Y){        // DPAD stride
    size_t row = blockIdx.x;
    int t = threadIdx.x;                                  // 256
    float sp = Y[row*DPAD + 1 + t];
    float S = blockReduceSum(sp*sp);
    if (t == 0) Y[row*DPAD] = sqrtf(S + 1.f);
}
__global__ void k_poincare(const float* __restrict__ Y, float* __restrict__ out){
    size_t row = blockIdx.x;
    int t = threadIdx.x;                                  // 128
    float sp = Y[row*KP1 + 1 + t];
    float S = blockReduceSum(sp*sp);
    float time = sqrtf(S + 1.f);
    out[row*KKW + t] = sp / (time + 1.f);
}
__global__ void k_rowfix(float* __restrict__ L, float* __restrict__ xnr){
    size_t row = blockIdx.x;
    int t = threadIdx.x;                                  // 256
    float* p = L + row*1024;
    float s = 0.f;
    #pragma unroll
    for (int i = 0; i < 4; i++){ float v = p[t + i*256]; s += v*v; }
    float S = blockReduceSum(s);
    if (t == 0){
        p[0] = sqrtf(S + 1.f);
        xnr[row] = sqrtf(fmaxf(2.f*S + 1.f, 1e-15f));
    }
}
__global__ void k_colnorm(const float* __restrict__ L, float* __restrict__ xnc){
    int b = blockIdx.y;
    int m = blockIdx.x*256 + threadIdx.x;
    const float* base = L + (size_t)b*NSQ*NCQ + m;
    float cs = 0.f;
    for (int n = 0; n < NSQ; n++){ float v = base[(size_t)n*NCQ]; cs += v*v; }
    xnc[b*NCQ + m] = sqrtf(fmaxf(cs, 1e-15f));
}
// per-row mobius_matvec scale factor (no writeback of the matrix)
__global__ void k_mscale(const float* __restrict__ Mx, const float* __restrict__ xna,
                         float* __restrict__ sc){
    size_t row = blockIdx.x;
    int t = threadIdx.x;                                  // 128
    float v = Mx[row*KKW + t];
    float mm = blockReduceSum(v*v);
    if (t == 0){
        float mxn = sqrtf(fmaxf(mm, 1e-15f));
        float xn = xna[row];
        sc[row] = tanhf(mxn / xn * atanhc(xn)) / mxn;
    }
}
__global__ void k_hs(const float* __restrict__ Hsa, const float* __restrict__ MxRaw,
                     const float* __restrict__ xnr,
                     const float* __restrict__ whs, float* __restrict__ lg){
    size_t row = blockIdx.x;
    int t = threadIdx.x;                                  // 128
    float yr = MxRaw[row*KKW + t];
    float mm = blockReduceSum(yr*yr);
    float mxn = sqrtf(fmaxf(mm, 1e-15f));
    float xnb = xnr[row];
    float y = yr * (tanhf(mxn / xnb * atanhc(xnb)) / mxn);

    float x = Hsa[row*KKW + t];
    float xy = x*y, x2 = x*x, y2 = y*y;
    blockReduceSum3(xy, x2, y2);
    float den = fmaxf(1.f + 2.f*xy + x2*y2, 1e-15f);
    float h = ((1.f + 2.f*xy + y2)*x + (1.f - x2)*y) / den;
    float hn = sqrtf(fmaxf(blockReduceSum(h*h), 1e-15f));
    float u = atanhc(hn) / hn * h;
    float gv = gelu_exact(u);
    float gn = sqrtf(fmaxf(blockReduceSum(gv*gv), 1e-15f));
    float hs = tanhf(gn) / gn * gv;
    float mx = hs * whs[t], xn2 = hs*hs, dmy = 0.f;
    blockReduceSum3(mx, xn2, dmy);
    if (t == 0){
        float xn = sqrtf(fmaxf(xn2, 1e-15f));
        float mxn2 = sqrtf(fmaxf(mx*mx, 1e-15f));
        lg[row] = tanhf(mxn2 / xn * atanhc(xn)) * mx / mxn2;
    }
}
__global__ void k_hc(const float* __restrict__ Hca, const float* __restrict__ Yb,
                     const float* __restrict__ sc, float* __restrict__ Hc){
    int bj = blockIdx.x;
    int b = bj >> 7, j = bj & 127;
    int t = threadIdx.x;                                  // 256
    float x[4], y[4];
    #pragma unroll
    for (int i = 0; i < 4; i++){
        int m = t + i*256;
        size_t idx = ((size_t)(b*NCQ + m))*KKW + j;
        x[i] = Hca[idx]; y[i] = Yb[idx] * sc[b*NCQ + m];
    }
    float sxy = 0.f, sx2 = 0.f, sy2 = 0.f;
    #pragma unroll
    for (int i = 0; i < 4; i++){ sxy += x[i]*y[i]; sx2 += x[i]*x[i]; sy2 += y[i]*y[i]; }
    blockReduceSum3(sxy, sx2, sy2);
    float xy = sxy, x2 = sx2, y2 = sy2;
    float den = fmaxf(1.f + 2.f*xy + x2*y2, 1e-15f);
    float c1 = 1.f + 2.f*xy + y2, c2 = 1.f - x2;
    float h[4], hh = 0.f;
    #pragma unroll
    for (int i = 0; i < 4; i++){ h[i] = (c1*x[i] + c2*y[i]) / den; hh += h[i]*h[i]; }
    float hn = sqrtf(fmaxf(blockReduceSum(hh), 1e-15f));
    float fa = atanhc(hn) / hn;
    float g[4], gg = 0.f;
    #pragma unroll
    for (int i = 0; i < 4; i++){ g[i] = gelu_exact(fa*h[i]); gg += g[i]*g[i]; }
    float gn = sqrtf(fmaxf(blockReduceSum(gg), 1e-15f));
    float fb = tanhf(gn) / gn;
    #pragma unroll
    for (int i = 0; i < 4; i++)
        Hc[((size_t)(b*KKW + j))*NCQ + (t + i*256)] = fb * g[i];
}
__global__ void k_ac(const float* __restrict__ Hc, const float* __restrict__ whc,
                     float* __restrict__ lg){
    __shared__ float wsh[KKW];
    int b = blockIdx.y;
    int m = blockIdx.x*256 + threadIdx.x;
    if (threadIdx.x < KKW) wsh[threadIdx.x] = whc[threadIdx.x];
    __syncthreads();
    const float* base = Hc + (size_t)b*KKW*NCQ + m;
    float mx = 0.f, ss = 0.f;
    #pragma unroll 4
    for (int j = 0; j < KKW; j++){
        float v = base[(size_t)j*NCQ];
        mx += v * wsh[j]; ss += v*v;
    }
    float xn = sqrtf(fmaxf(ss, 1e-15f));
    float mxn = sqrtf(fmaxf(mx*mx, 1e-15f));
    lg[b*NCQ + m] = tanhf(mxn / xn * atanhc(xn)) * mx / mxn;
}
__global__ void k_softmax(const float* __restrict__ lg, float* __restrict__ out){
    int b = blockIdx.x, t = threadIdx.x;                  // 256
    float l[4];
    float lm = -3.4e38f;
    #pragma unroll
    for (int i = 0; i < 4; i++){ l[i] = lg[b*1024 + t + i*256]; lm = fmaxf(lm, l[i]); }
    float M = blockReduceMax(lm);
    float es = 0.f, e[4];
    #pragma unroll
    for (int i = 0; i < 4; i++){ e[i] = expf(l[i] - M); es += e[i]; }
    float S = blockReduceSum(es);
    #pragma unroll
    for (int i = 0; i < 4; i++) out[b*1024 + t + i*256] = e[i] / S;
}
__global__ void k_centroid_part(const float* __restrict__ Lx, const float* __restrict__ w,
                                float* __restrict__ part){
    __shared__ float wsh[128];
    int ch = blockIdx.x, b = blockIdx.y;
    int t = threadIdx.x;                                  // 288, t<257 active
    for (int i = t; i < 128; i += blockDim.x) wsh[i] = w[(size_t)b*NSQ + ch*128 + i];
    __syncthreads();
    if (t < DP1){
        const float* base = Lx + ((size_t)b*NSQ + (size_t)ch*128)*DPAD + t;
        float acc = 0.f;
        for (int n = 0; n < 128; n++) acc += wsh[n] * base[(size_t)n*DPAD];
        part[(b*8 + ch)*DP1 + t] = acc;
    }
}
__global__ void k_centroid_fin(const float* __restrict__ part, float* __restrict__ co){
    __shared__ float t0sh;
    int b = blockIdx.x, t = threadIdx.x;                  // 288
    float acc = 0.f;
    if (t < DP1){
        #pragma unroll
        for (int c = 0; c < 8; c++) acc += part[(b*8 + c)*DP1 + t];
    }
    float sp = (t >= 1 && t < DP1) ? acc*acc : 0.f;
    float ssp = blockReduceSum(sp);
    if (t == 0) t0sh = acc;
    __syncthreads();
    float inner = -t0sh*t0sh + ssp;
    float den = sqrtf(fmaxf(fabsf(inner), 1e-8f));
    if (t < DP1) co[(size_t)b*DP1 + t] = acc / den;
}
__global__ void k_concat(const float* __restrict__ cs, const float* __restrict__ cc,
                         float* __restrict__ out){
    int b = blockIdx.x, t = threadIdx.x;                  // 256
    float t0s = cs[(size_t)b*DP1];
    float t0c = cc[(size_t)b*DP1];
    float sps = cs[(size_t)b*DP1 + 1 + t];
    float spc = cc[(size_t)b*DP1 + 1 + t];
    float ns  = sqrtf(fmaxf(blockReduceSum(sps*sps), 1e-15f));
    float ncv = sqrtf(fmaxf(blockReduceSum(spc*spc), 1e-15f));
    float zs = acoshf(fmaxf(t0s, 1.f + 1e-7f)) * sps / ns;
    float zc = acoshf(fmaxf(t0c, 1.f + 1e-7f)) * spc / ncv;
    float vn = sqrtf(fmaxf(blockReduceSum(zs*zs + zc*zc), 1e-15f));
    float f = sinhf(vn) / vn;
    float* o = out + (size_t)b*513;
    if (t == 0) o[0] = coshf(vn);
    o[1 + t]       = f * zs;
    o[1 + DD + t]  = f * zc;
}

// ----------------------------- launch ----------------------------------------------
extern "C" void kernel_launch(void* const* d_in, const int* in_sizes, int n_in,
                              void* d_out, int out_size)
{
    const float* sent = (const float*)d_in[0];
    const float* comm = (const float*)d_in[1];
    const float* WlW  = (const float*)d_in[2];
    const float* Wlb  = (const float*)d_in[3];
    const float* WcW  = (const float*)d_in[4];
    const float* Wcb  = (const float*)d_in[5];
    const float* WsW  = (const float*)d_in[6];
    const float* Wsb  = (const float*)d_in[7];
    const float* whs  = (const float*)d_in[8];
    const float* whc  = (const float*)d_in[9];
    float* out = (float*)d_out;
    (void)in_sizes; (void)n_in; (void)out_size;

    float2 *c1, *c1T;
    float *sT, *rl, *Ls, *Lc, *Llin, *Yt, *Lb, *xnr, *xnc, *msc, *Hsa, *Hca, *Mxs, *Mxc,
          *Hcm, *lgs, *lgc, *cs, *cc, *part;
    cudaGetSymbolAddress((void**)&c1,  g_c1);
    cudaGetSymbolAddress((void**)&c1T, g_c1T);
    cudaGetSymbolAddress((void**)&sT,  g_sT);
    cudaGetSymbolAddress((void**)&rl,  g_real);
    cudaGetSymbolAddress((void**)&Ls,  g_Ls);
    cudaGetSymbolAddress((void**)&Lc,  g_Lc);
    cudaGetSymbolAddress((void**)&Llin,g_Llin);
    cudaGetSymbolAddress((void**)&Yt,  g_Yt);
    cudaGetSymbolAddress((void**)&Lb,  g_Lb);
    cudaGetSymbolAddress((void**)&xnr, g_xnr);
    cudaGetSymbolAddress((void**)&xnc, g_xnc);
    cudaGetSymbolAddress((void**)&msc, g_msc);
    cudaGetSymbolAddress((void**)&Hsa, g_Hsa);
    cudaGetSymbolAddress((void**)&Hca, g_Hca);
    cudaGetSymbolAddress((void**)&Mxs, g_Mxs);
    cudaGetSymbolAddress((void**)&Mxc, g_Mxc);
    cudaGetSymbolAddress((void**)&Hcm, g_Hcm);
    cudaGetSymbolAddress((void**)&lgs, g_lgs);
    cudaGetSymbolAddress((void**)&lgc, g_lgc);
    cudaGetSymbolAddress((void**)&cs,  g_cs);
    cudaGetSymbolAddress((void**)&cc,  g_cc);
    cudaGetSymbolAddress((void**)&part,g_part);

    const int AS_OFF = BB*513;             // 16416
    const int AC_OFF = AS_OFF + BB*NSQ;    // 49184

    k_twfill<<<1, 1024>>>();

    // ---- FFT2 + euclid_to_lorentz, both branches ----
    for (int branch = 0; branch < 2; branch++){
        const float* inp = branch ? comm : sent;
        float* Lout = branch ? Lc : Ls;
        int dolog = branch ? 1 : 0;
        k_fft256<<<BB*NSQ/4, dim3(64,4)>>>(inp, c1, dolog);
        k_transpose_c<<<dim3(DD/32, NSQ/32, BB), dim3(32,8)>>>(c1, c1T, NSQ, DD);
        k_fft1024<<<BB*DD, 256>>>(c1T, sT);
        k_transpose_f<<<dim3(NSQ/32, DD/32, BB), dim3(32,8)>>>(sT, rl, DD, NSQ);
        k_e2l<<<BB*NSQ, 256>>>(rl, Lout);
    }

    // ---- linear layers (pipelined tensor cores) ----
    k_pgemm<0,1,1,4,1><<<dim3(3,256,1),256>>>(Lc, WlW, Wlb, Llin,
        BB*NCQ, DP1, DP1, DPAD, DP1, DPAD, 0, 0, 0);
    k_zpad<<<(BB*NCQ*15 + 1023)/1024, 1024>>>(Llin, BB*NCQ);
    k_fix_time<<<BB*NCQ, 256>>>(Llin);

    k_pgemm<0,1,1,4,1><<<dim3(2,256,1),256>>>(Ls, WsW, Wsb, Yt,
        BB*NSQ, KP1, DP1, DPAD, DP1, KP1, 0, 0, 0);
    k_poincare<<<BB*NSQ, 128>>>(Yt, Hsa);

    k_pgemm<0,1,1,4,1><<<dim3(2,256,1),256>>>(Lc, WcW, Wcb, Yt,
        BB*NCQ, KP1, DP1, DPAD, DP1, KP1, 0, 0, 0);
    k_poincare<<<BB*NCQ, 128>>>(Yt, Hca);

    // ---- big einsum + lorentz_act (fused gelu epilogue) ----
    k_pgemm<0,1,2,4,4><<<dim3(8,8,BB),256>>>(Ls, Llin, nullptr, Lb,
        NSQ, NCQ, DP1, DPAD, DPAD, NCQ,
        (long)NSQ*DPAD, (long)NCQ*DPAD, (long)NSQ*NCQ);
    k_rowfix<<<BB*NSQ, 256>>>(Lb, xnr);
    k_colnorm<<<dim3(NCQ/256, BB), 256>>>(Lb, xnc);

    // ---- mobius_matvec GEMMs ----
    k_pgemm<0,0,0,4,4><<<dim3(1,8,BB),256>>>(Lb, Hca, nullptr, Mxs,
        NSQ, KKW, NCQ, NCQ, KKW, KKW,
        (long)NSQ*NCQ, (long)NCQ*KKW, (long)NSQ*KKW);
    k_pgemm<1,0,0,4,4><<<dim3(1,8,BB),256>>>(Lb, Hsa, nullptr, Mxc,
        NCQ, KKW, NSQ, NCQ, KKW, KKW,
        (long)NSQ*NCQ, (long)NSQ*KKW, (long)NCQ*KKW);
    k_mscale<<<BB*NCQ, 128>>>(Mxc, xnc, msc);

    // ---- mobius_add + gelu pipeline + attention logits ----
    k_hs<<<BB*NSQ, 128>>>(Hsa, Mxs, xnr, whs, lgs);
    k_hc<<<BB*KKW, 256>>>(Hca, Mxc, msc, Hcm);
    k_ac<<<dim3(NCQ/256, BB), 256>>>(Hcm, whc, lgc);

    // ---- softmaxes straight into output ----
    k_softmax<<<BB, 256>>>(lgs, out + AS_OFF);
    k_softmax<<<BB, 256>>>(lgc, out + AC_OFF);

    // ---- centroids + concat ----
    k_centroid_part<<<dim3(8,BB), 288>>>(Ls, out + AS_OFF, part);
    k_centroid_fin<<<BB, 288>>>(part, cs);
    k_centroid_part<<<dim3(8,BB), 288>>>(Lc, out + AC_OFF, part);
    k_centroid_fin<<<BB, 288>>>(part, cc);
    k_concat<<<BB, 256>>>(cs, cc, out);
}

// round 6
// speedup vs baseline: 2.4700x; 1.3755x over previous
#include <cuda_runtime.h>
#include <math.h>
#include <stdint.h>

#define BB  32
#define NSQ 1024
#define NCQ 1024
#define DD  256
#define DP1 257
#define DPAD 272
#define KKW 128
#define KP1 129
#define DH  129   // Hermitian-reduced column count

// ----------------------------- scratch (static device globals; no runtime alloc) ---
static __device__ float2 g_c1 [(size_t)BB*NSQ*DD];
static __device__ float2 g_c1T[(size_t)BB*DH*NSQ];
static __device__ float  g_sT [(size_t)BB*DH*NSQ];
static __device__ float  g_real[(size_t)BB*NSQ*DD];
static __device__ float  g_Ls [(size_t)BB*NSQ*DPAD];
static __device__ float  g_Lc [(size_t)BB*NCQ*DPAD];
static __device__ float  g_Llin[(size_t)BB*NCQ*DPAD];
static __device__ float  g_Yt [(size_t)BB*NSQ*KP1];
static __device__ float  g_Lb [(size_t)BB*NSQ*NCQ];
static __device__ float  g_rss[BB*NSQ];
static __device__ float  g_css[BB*NCQ];
static __device__ float  g_xnr[BB*NSQ];
static __device__ float  g_xnc[BB*NCQ];
static __device__ float  g_msc[BB*NCQ];
static __device__ float  g_Hsa[(size_t)BB*NSQ*KKW];
static __device__ float  g_Hca[(size_t)BB*NCQ*KKW];
static __device__ float  g_Mxs[(size_t)BB*NSQ*KKW];
static __device__ float  g_Mxc[(size_t)BB*NCQ*KKW];
static __device__ float  g_Hcm[(size_t)BB*KKW*NCQ];
static __device__ float  g_lgs[BB*NSQ];
static __device__ float  g_lgc[BB*NCQ];
static __device__ float  g_cs [BB*DP1];
static __device__ float  g_cc [BB*DP1];
static __device__ float  g_part[BB*8*DP1];
static __device__ float2 g_tw1024[1024];
static __device__ float2 g_tw256[256];

// ----------------------------- helpers ---------------------------------------------
__device__ __forceinline__ float atanhc(float x){
    x = fminf(fmaxf(x, -1.f + 1e-5f), 1.f - 1e-5f);
    return 0.5f * (log1pf(x) - log1pf(-x));
}
__device__ __forceinline__ float gelu_exact(float v){
    return 0.5f * v * (1.f + erff(v * 0.70710678118654752f));
}
__device__ __forceinline__ float2 cmul(float2 a, float2 b){
    return make_float2(a.x*b.x - a.y*b.y, a.x*b.y + a.y*b.x);
}
__device__ __forceinline__ float2 cadd(float2 a, float2 b){ return make_float2(a.x+b.x, a.y+b.y); }
__device__ __forceinline__ float2 csub(float2 a, float2 b){ return make_float2(a.x-b.x, a.y-b.y); }

__device__ __forceinline__ float blockReduceSum(float v){
    __shared__ float sh[32];
    #pragma unroll
    for (int o = 16; o; o >>= 1) v += __shfl_down_sync(0xffffffffu, v, o);
    int lane = threadIdx.x & 31, w = threadIdx.x >> 5;
    if (lane == 0) sh[w] = v;
    __syncthreads();
    int nw = (blockDim.x + 31) >> 5;
    v = (threadIdx.x < (unsigned)nw) ? sh[threadIdx.x] : 0.f;
    if (w == 0){
        #pragma unroll
        for (int o = 16; o; o >>= 1) v += __shfl_down_sync(0xffffffffu, v, o);
        if (lane == 0) sh[0] = v;
    }
    __syncthreads();
    float r = sh[0];
    __syncthreads();
    return r;
}
__device__ __forceinline__ void blockReduceSum3(float& a, float& b, float& c){
    __shared__ float sh3[32][3];
    #pragma unroll
    for (int o = 16; o; o >>= 1){
        a += __shfl_down_sync(0xffffffffu, a, o);
        b += __shfl_down_sync(0xffffffffu, b, o);
        c += __shfl_down_sync(0xffffffffu, c, o);
    }
    int lane = threadIdx.x & 31, w = threadIdx.x >> 5;
    if (lane == 0){ sh3[w][0] = a; sh3[w][1] = b; sh3[w][2] = c; }
    __syncthreads();
    int nw = (blockDim.x + 31) >> 5;
    a = (threadIdx.x < (unsigned)nw) ? sh3[threadIdx.x][0] : 0.f;
    b = (threadIdx.x < (unsigned)nw) ? sh3[threadIdx.x][1] : 0.f;
    c = (threadIdx.x < (unsigned)nw) ? sh3[threadIdx.x][2] : 0.f;
    if (w == 0){
        #pragma unroll
        for (int o = 16; o; o >>= 1){
            a += __shfl_down_sync(0xffffffffu, a, o);
            b += __shfl_down_sync(0xffffffffu, b, o);
            c += __shfl_down_sync(0xffffffffu, c, o);
        }
        if (lane == 0){ sh3[0][0] = a; sh3[0][1] = b; sh3[0][2] = c; }
    }
    __syncthreads();
    a = sh3[0][0]; b = sh3[0][1]; c = sh3[0][2];
    __syncthreads();
}
__device__ __forceinline__ float blockReduceMax(float v){
    __shared__ float sh[32];
    #pragma unroll
    for (int o = 16; o; o >>= 1) v = fmaxf(v, __shfl_down_sync(0xffffffffu, v, o));
    int lane = threadIdx.x & 31, w = threadIdx.x >> 5;
    if (lane == 0) sh[w] = v;
    __syncthreads();
    int nw = (blockDim.x + 31) >> 5;
    v = (threadIdx.x < (unsigned)nw) ? sh[threadIdx.x] : -3.4e38f;
    if (w == 0){
        #pragma unroll
        for (int o = 16; o; o >>= 1) v = fmaxf(v, __shfl_down_sync(0xffffffffu, v, o));
        if (lane == 0) sh[0] = v;
    }
    __syncthreads();
    float r = sh[0];
    __syncthreads();
    return r;
}
__device__ __forceinline__ uint32_t f2tf32(float v){
    uint32_t r;
    asm("cvt.rna.tf32.f32 %0, %1;" : "=r"(r) : "f"(v));
    return r;
}
__device__ __forceinline__ void mma_tf32(float* c, const uint32_t* a, const uint32_t* b){
    asm volatile("mma.sync.aligned.m16n8k8.row.col.f32.tf32.tf32.f32 "
        "{%0,%1,%2,%3}, {%4,%5,%6,%7}, {%8,%9}, {%0,%1,%2,%3};"
        : "+f"(c[0]), "+f"(c[1]), "+f"(c[2]), "+f"(c[3])
        : "r"(a[0]), "r"(a[1]), "r"(a[2]), "r"(a[3]), "r"(b[0]), "r"(b[1]));
}
__device__ __forceinline__ void cpa16(uint32_t dsh, const void* src){
    asm volatile("cp.async.ca.shared.global [%0], [%1], 16;" :: "r"(dsh), "l"(src));
}
__device__ __forceinline__ void cpa4z(uint32_t dsh, const void* src, bool pred){
    int sz = pred ? 4 : 0;
    asm volatile("cp.async.ca.shared.global [%0], [%1], 4, %2;" :: "r"(dsh), "l"(src), "r"(sz));
}
#define CP_COMMIT() asm volatile("cp.async.commit_group;" ::: "memory")
#define CP_WAIT1()  asm volatile("cp.async.wait_group 1;" ::: "memory")
#define CP_WAIT0()  asm volatile("cp.async.wait_group 0;" ::: "memory")

// ----------------------------- twiddle fill ----------------------------------------
__global__ void k_twfill(){
    int i = threadIdx.x;
    if (i < 1024){
        double a = -6.283185307179586476925287 * (double)i / 1024.0;
        g_tw1024[i] = make_float2((float)cos(a), (float)sin(a));
    }
    if (i < 256){
        double a = -6.283185307179586476925287 * (double)i / 256.0;
        g_tw256[i] = make_float2((float)cos(a), (float)sin(a));
    }
}
__global__ void k_zero(float* __restrict__ a, float* __restrict__ b){
    int i = blockIdx.x*1024 + threadIdx.x;
    a[i] = 0.f; b[i] = 0.f;
}

// ----------------------------- radix-4 Stockham FFT kernels ------------------------
__global__ void k_fft256(const float* __restrict__ in, float2* __restrict__ out, int do_log){
    __shared__ float2 bufA[4][256];
    __shared__ float2 bufB[4][256];
    __shared__ float2 tws[256];
    __shared__ float  rsum[4][2];
    int tx = threadIdx.x;                      // 64
    int ty = threadIdx.y;                      // 4
    int tid = ty*64 + tx;
    size_t row = (size_t)blockIdx.x*4 + ty;
    tws[tid] = g_tw256[tid];

    const float* x = in + row*256;
    float v0 = x[tx], v1 = x[tx+64], v2 = x[tx+128], v3 = x[tx+192];
    float ss = v0*v0 + v1*v1 + v2*v2 + v3*v3;
    #pragma unroll
    for (int o = 16; o; o >>= 1) ss += __shfl_down_sync(0xffffffffu, ss, o);
    if ((tx & 31) == 0) rsum[ty][tx >> 5] = ss;
    __syncthreads();
    if (do_log){
        float tot = rsum[ty][0] + rsum[ty][1];
        float yn = sqrtf(fmaxf(tot, 1e-15f));
        float f = atanhc(yn) / yn;
        v0 *= f; v1 *= f; v2 *= f; v3 *= f;
    }
    bufA[ty][tx]       = make_float2(v0, 0.f);
    bufA[ty][tx + 64]  = make_float2(v1, 0.f);
    bufA[ty][tx + 128] = make_float2(v2, 0.f);
    bufA[ty][tx + 192] = make_float2(v3, 0.f);
    __syncthreads();

    float2* X = &bufA[ty][0];
    float2* Y = &bufB[ty][0];
    #pragma unroll
    for (int s = 0; s < 4; s++){
        int Ns = 1 << (2*s);
        int p = tx & (Ns - 1);
        float2 w1 = tws[p * (64/Ns)];
        float2 w2 = cmul(w1, w1);
        float2 w3 = cmul(w2, w1);
        float2 a0 = X[tx];
        float2 a1 = cmul(X[tx + 64],  w1);
        float2 a2 = cmul(X[tx + 128], w2);
        float2 a3 = cmul(X[tx + 192], w3);
        float2 pa = cadd(a0, a2), pb = csub(a0, a2);
        float2 pc = cadd(a1, a3), pd = csub(a1, a3);
        float2 dneg = make_float2(pd.y, -pd.x);
        float2 dpos = make_float2(-pd.y, pd.x);
        int idxD = ((tx >> (2*s)) << (2*s + 2)) + p;
        Y[idxD]          = cadd(pa, pc);
        Y[idxD + Ns]     = cadd(pb, dneg);
        Y[idxD + 2*Ns]   = csub(pa, pc);
        Y[idxD + 3*Ns]   = cadd(pb, dpos);
        __syncthreads();
        float2* tmp = X; X = Y; Y = tmp;
    }
    out[row*256 + tx]       = X[tx];
    out[row*256 + tx + 64]  = X[tx + 64];
    out[row*256 + tx + 128] = X[tx + 128];
    out[row*256 + tx + 192] = X[tx + 192];
}

__global__ void k_fft1024(const float2* __restrict__ in, float* __restrict__ outr){
    __shared__ float2 bufA[1024];
    __shared__ float2 bufB[1024];
    __shared__ float2 tws[1024];
    int t = threadIdx.x;                       // 256
    size_t row = blockIdx.x;
    const float2* src = in + row*1024;
    #pragma unroll
    for (int i = 0; i < 4; i++){
        tws[t + i*256]  = g_tw1024[t + i*256];
        bufA[t + i*256] = src[t + i*256];
    }
    __syncthreads();
    float2* X = bufA;
    float2* Y = bufB;
    #pragma unroll
    for (int s = 0; s < 5; s++){
        int Ns = 1 << (2*s);
        int p = t & (Ns - 1);
        float2 w1 = tws[p * (256/Ns)];
        float2 w2 = cmul(w1, w1);
        float2 w3 = cmul(w2, w1);
        float2 a0 = X[t];
        float2 a1 = cmul(X[t + 256], w1);
        float2 a2 = cmul(X[t + 512], w2);
        float2 a3 = cmul(X[t + 768], w3);
        float2 pa = cadd(a0, a2), pb = csub(a0, a2);
        float2 pc = cadd(a1, a3), pd = csub(a1, a3);
        float2 dneg = make_float2(pd.y, -pd.x);
        float2 dpos = make_float2(-pd.y, pd.x);
        int idxD = ((t >> (2*s)) << (2*s + 2)) + p;
        Y[idxD]        = cadd(pa, pc);
        Y[idxD + Ns]   = cadd(pb, dneg);
        Y[idxD + 2*Ns] = csub(pa, pc);
        Y[idxD + 3*Ns] = cadd(pb, dpos);
        __syncthreads();
        float2* tmp = X; X = Y; Y = tmp;
    }
    #pragma unroll
    for (int i = 0; i < 4; i++)
        outr[row*1024 + t + i*256] = X[t + i*256].x;
}

// transpose (B, NS, 256)complex -> (B, 129, NS)complex  (only cols 0..128 kept)
__global__ void k_transpose_ch(const float2* __restrict__ in, float2* __restrict__ out){
    __shared__ float2 tile[32][33];
    int b = blockIdx.z;
    int c0 = blockIdx.x*32, r0 = blockIdx.y*32;
    const float2* src = in + (size_t)b*NSQ*DD;
    for (int i = threadIdx.y; i < 32; i += 8)
        tile[i][threadIdx.x] = src[(size_t)(r0+i)*DD + c0 + threadIdx.x];
    __syncthreads();
    float2* dst = out + (size_t)b*DH*NSQ;
    for (int i = threadIdx.y; i < 32; i += 8){
        int d = c0 + i;
        if (d < DH) dst[(size_t)d*NSQ + r0 + threadIdx.x] = tile[threadIdx.x][i];
    }
}
// transpose (B, 129, NS) -> (B, NS, 256) cols 0..128 only
__global__ void k_transpose_fh(const float* __restrict__ in, float* __restrict__ out){
    __shared__ float tile[32][33];
    int b = blockIdx.z;
    int d0 = blockIdx.x*32, n0 = blockIdx.y*32;
    const float* src = in + (size_t)b*DH*NSQ;
    for (int i = threadIdx.y; i < 32; i += 8){
        int d = d0 + i;
        tile[i][threadIdx.x] = (d < DH) ? src[(size_t)d*NSQ + n0 + threadIdx.x] : 0.f;
    }
    __syncthreads();
    float* dst = out + (size_t)b*NSQ*DD;
    int d = d0 + threadIdx.x;
    if (d < DH)
        for (int i = threadIdx.y; i < 32; i += 8)
            dst[(size_t)(n0+i)*DD + d] = tile[threadIdx.x][i];
}
// fill cols 129..255 using real-FFT Hermitian symmetry:
// rl[n][d] = rl[(1024-n)%1024][256-d]
__global__ void k_mirror(float* __restrict__ rl){
    int n = blockIdx.x, b = blockIdx.y, t = threadIdx.x;   // 128
    if (t >= 127) return;
    int srcn = (1024 - n) & 1023;
    float v = rl[((size_t)b*NSQ + srcn)*DD + (127 - t)];
    rl[((size_t)b*NSQ + n)*DD + 129 + t] = v;
}

// euclid_to_lorentz: 256-wide row -> DPAD-wide Lorentz row (pad zeroed)
__global__ void k_e2l(const float* __restrict__ in, float* __restrict__ out){
    size_t row = blockIdx.x;
    int t = threadIdx.x;                       // 256
    float v = in[row*256 + t];
    float ss = blockReduceSum(v*v);
    float xn = sqrtf(fmaxf(ss, 1e-15f)) + 1e-5f;
    float scl = fminf(1.f, 2.0f / xn);
    v *= scl;
    float vn = sqrtf(fmaxf(ss*scl*scl, 1e-15f));
    float f = sinhf(vn) / vn;
    if (t == 0) out[row*DPAD] = coshf(vn);
    out[row*DPAD + 1 + t] = f * v;
    if (t < DPAD - DP1) out[row*DPAD + DP1 + t] = 0.f;
}

// zero pad columns [257,272) of a DPAD-stride matrix
__global__ void k_zpad(float* __restrict__ p, int rows){
    int idx = blockIdx.x*1024 + threadIdx.x;
    int r = idx / 15, c = idx % 15;
    if (r < rows) p[(size_t)r*DPAD + DP1 + c] = 0.f;
}

// --------------- pipelined tensor-core GEMM (pure TF32, cp.async double-buffered) ---
//  MODE: 0 plain, 1 +bias[n], 2 gelu except col0 (->0) + fused row/col SSQ atomics
template<int ATRANS, int BTRANS, int MODE, int VECA, int VECB>
__global__ void k_pgemm(const float* __restrict__ A, const float* __restrict__ Bm,
                        const float* __restrict__ bias, float* __restrict__ C,
                        int M, int N, int Klen, int lda, int ldb, int ldc,
                        long sA, long sB, long sC,
                        float* __restrict__ rss, float* __restrict__ css)
{
    constexpr int A_ELE = (ATRANS == 0) ? 128*20 : 16*132;
    constexpr int B_ELE = (BTRANS == 1) ? 128*20 : 16*132;
    __shared__ __align__(16) float As[2][A_ELE];
    __shared__ __align__(16) float Bs[2][B_ELE];

    int bz = blockIdx.z;
    A  += (size_t)bz * sA;
    Bm += (size_t)bz * sB;
    C  += (size_t)bz * sC;
    int bm = blockIdx.y * 128, bn = blockIdx.x * 128;
    int tid = threadIdx.x;
    int wid = tid >> 5, lane = tid & 31;
    int wm = (wid >> 2) * 64;
    int wn = (wid & 3) * 32;
    int g = lane >> 2, tg = lane & 3;

    int KT = (Klen + 15) >> 4;

    uint32_t asBase = (uint32_t)__cvta_generic_to_shared(&As[0][0]);
    uint32_t bsBase = (uint32_t)__cvta_generic_to_shared(&Bs[0][0]);

    auto issueA = [&](int st, int k0){
        uint32_t base = asBase + (uint32_t)(st * A_ELE * 4);
        if (ATRANS == 0){
            if (VECA == 4){
                #pragma unroll
                for (int i = 0; i < 2; i++){
                    int idx = tid + i*256;
                    int mm = idx >> 2, k4 = idx & 3;
                    cpa16(base + (mm*20 + k4*4)*4, A + (size_t)(bm+mm)*lda + k0 + k4*4);
                }
            } else {
                #pragma unroll
                for (int i = 0; i < 8; i++){
                    int idx = tid + i*256;
                    int mm = idx >> 4, kk = idx & 15;
                    int gm = bm + mm, gk = k0 + kk;
                    bool ok = (gm < M) && (gk < Klen);
                    const float* src = A + (ok ? ((size_t)gm*lda + gk) : 0);
                    cpa4z(base + (mm*20 + kk)*4, src, ok);
                }
            }
        } else {
            if (VECA == 4){
                #pragma unroll
                for (int i = 0; i < 2; i++){
                    int idx = tid + i*256;
                    int kk = idx >> 5, m4 = idx & 31;
                    cpa16(base + (kk*132 + m4*4)*4, A + (size_t)(k0+kk)*lda + bm + m4*4);
                }
            } else {
                #pragma unroll
                for (int i = 0; i < 8; i++){
                    int idx = tid + i*256;
                    int kk = idx >> 7, mm = idx & 127;
                    int gm = bm + mm, gk = k0 + kk;
                    bool ok = (gm < M) && (gk < Klen);
                    const float* src = A + (ok ? ((size_t)gk*lda + gm) : 0);
                    cpa4z(base + (kk*132 + mm)*4, src, ok);
                }
            }
        }
    };
    auto issueB = [&](int st, int k0){
        uint32_t base = bsBase + (uint32_t)(st * B_ELE * 4);
        if (BTRANS == 1){
            if (VECB == 4){
                #pragma unroll
                for (int i = 0; i < 2; i++){
                    int idx = tid + i*256;
                    int nn = idx >> 2, k4 = idx & 3;
                    cpa16(base + (nn*20 + k4*4)*4, Bm + (size_t)(bn+nn)*ldb + k0 + k4*4);
                }
            } else {
                #pragma unroll
                for (int i = 0; i < 8; i++){
                    int idx = tid + i*256;
                    int nn = idx >> 4, kk = idx & 15;
                    int gn = bn + nn, gk = k0 + kk;
                    bool ok = (gn < N) && (gk < Klen);
                    const float* src = Bm + (ok ? ((size_t)gn*ldb + gk) : 0);
                    cpa4z(base + (nn*20 + kk)*4, src, ok);
                }
            }
        } else {
            if (VECB == 4){
                #pragma unroll
                for (int i = 0; i < 2; i++){
                    int idx = tid + i*256;
                    int kk = idx >> 5, n4 = idx & 31;
                    cpa16(base + (kk*132 + n4*4)*4, Bm + (size_t)(k0+kk)*ldb + bn + n4*4);
                }
            } else {
                #pragma unroll
                for (int i = 0; i < 8; i++){
                    int idx = tid + i*256;
                    int kk = idx >> 7, nn = idx & 127;
                    int gn = bn + nn, gk = k0 + kk;
                    bool ok = (gn < N) && (gk < Klen);
                    const float* src = Bm + (ok ? ((size_t)gk*ldb + gn) : 0);
                    cpa4z(base + (kk*132 + nn)*4, src, ok);
                }
            }
        }
    };
    auto A_at = [&](int st, int m, int k)->float{
        return (ATRANS == 0) ? As[st][m*20 + k] : As[st][k*132 + m];
    };
    auto B_at = [&](int st, int n, int k)->float{
        return (BTRANS == 1) ? Bs[st][n*20 + k] : Bs[st][k*132 + n];
    };

    float acc[4][4][4];
    #pragma unroll
    for (int mi = 0; mi < 4; mi++)
        #pragma unroll
        for (int ni = 0; ni < 4; ni++)
            #pragma unroll
            for (int r = 0; r < 4; r++) acc[mi][ni][r] = 0.f;

    issueA(0, 0); issueB(0, 0);
    CP_COMMIT();

    for (int kt = 0; kt < KT; kt++){
        int st = kt & 1;
        if (kt + 1 < KT){
            issueA(st ^ 1, (kt+1)*16);
            issueB(st ^ 1, (kt+1)*16);
            CP_COMMIT();
            CP_WAIT1();
        } else {
            CP_WAIT0();
        }
        __syncthreads();

        #pragma unroll
        for (int ks = 0; ks < 2; ks++){
            int kk = ks*8;
            uint32_t bhf[4][2];
            #pragma unroll
            for (int ni = 0; ni < 4; ni++){
                int n = wn + ni*8 + g;
                bhf[ni][0] = f2tf32(B_at(st, n, kk+tg));
                bhf[ni][1] = f2tf32(B_at(st, n, kk+tg+4));
            }
            #pragma unroll
            for (int mi = 0; mi < 4; mi++){
                int m = wm + mi*16;
                uint32_t ahf[4];
                ahf[0] = f2tf32(A_at(st, m+g,   kk+tg));
                ahf[1] = f2tf32(A_at(st, m+g+8, kk+tg));
                ahf[2] = f2tf32(A_at(st, m+g,   kk+tg+4));
                ahf[3] = f2tf32(A_at(st, m+g+8, kk+tg+4));
                #pragma unroll
                for (int ni = 0; ni < 4; ni++)
                    mma_tf32(acc[mi][ni], ahf, bhf[ni]);
            }
        }
        __syncthreads();
    }

    // epilogue value transform
    #pragma unroll
    for (int mi = 0; mi < 4; mi++)
        #pragma unroll
        for (int ni = 0; ni < 4; ni++){
            int col = bn + wn + ni*8 + 2*tg;
            #pragma unroll
            for (int r = 0; r < 4; r++){
                int gn = col + (r & 1);
                float v = acc[mi][ni][r];
                if (MODE == 1) v += bias[gn];
                if (MODE == 2) v = (gn == 0) ? 0.f : gelu_exact(v);
                acc[mi][ni][r] = v;
            }
        }
    // store
    #pragma unroll
    for (int mi = 0; mi < 4; mi++)
        #pragma unroll
        for (int ni = 0; ni < 4; ni++){
            int col = bn + wn + ni*8 + 2*tg;
            #pragma unroll
            for (int r = 0; r < 4; r++){
                int gm = bm + wm + mi*16 + g + (r >= 2 ? 8 : 0);
                int gn = col + (r & 1);
                if (gn >= N) continue;
                C[(size_t)gm*ldc + gn] = acc[mi][ni][r];
            }
        }
    if (MODE == 2){
        // fused row SSQ (over this block's 128 cols)
        #pragma unroll
        for (int mi = 0; mi < 4; mi++){
            #pragma unroll
            for (int half = 0; half < 2; half++){
                float rp = 0.f;
                #pragma unroll
                for (int ni = 0; ni < 4; ni++){
                    float a0 = acc[mi][ni][half*2], a1 = acc[mi][ni][half*2+1];
                    rp += a0*a0 + a1*a1;
                }
                rp += __shfl_down_sync(0xffffffffu, rp, 1);
                rp += __shfl_down_sync(0xffffffffu, rp, 2);
                if (tg == 0)
                    atomicAdd(&rss[(size_t)bz*1024 + bm + wm + mi*16 + g + half*8], rp);
            }
        }
        // fused col SSQ (over this block's 128 rows)
        #pragma unroll
        for (int ni = 0; ni < 4; ni++){
            #pragma unroll
            for (int cb = 0; cb < 2; cb++){
                float cp = 0.f;
                #pragma unroll
                for (int mi = 0; mi < 4; mi++){
                    float a0 = acc[mi][ni][cb], a1 = acc[mi][ni][2+cb];
                    cp += a0*a0 + a1*a1;
                }
                cp += __shfl_down_sync(0xffffffffu, cp, 4);
                cp += __shfl_down_sync(0xffffffffu, cp, 8);
                cp += __shfl_down_sync(0xffffffffu, cp, 16);
                if (g == 0)
                    atomicAdd(&css[(size_t)bz*1024 + bn + wn + ni*8 + 2*tg + cb], cp);
            }
        }
    }
}

// ----------------------------- row-wise kernels ------------------------------------
__global__ void k_fix_time(float* __restrict__ Y){        // DPAD stride
    size_t row = blockIdx.x;
    int t = threadIdx.x;                                  // 256
    float sp = Y[row*DPAD + 1 + t];
    float S = blockReduceSum(sp*sp);
    if (t == 0) Y[row*DPAD] = sqrtf(S + 1.f);
}
__global__ void k_poincare(const float* __restrict__ Y, float* __restrict__ out){
    size_t row = blockIdx.x;
    int t = threadIdx.x;                                  // 128
    float sp = Y[row*KP1 + 1 + t];
    float S = blockReduceSum(sp*sp);
    float time = sqrtf(S + 1.f);
    out[row*KKW + t] = sp / (time + 1.f);
}
// finalize norms from fused SSQ: write Lb col0, xnr, xnc
__global__ void k_nfin(const float* __restrict__ rss, const float* __restrict__ css,
                       float* __restrict__ Lb, float* __restrict__ xnr,
                       float* __restrict__ xnc){
    int b = blockIdx.x, n = threadIdx.x;                  // 1024
    float S = rss[b*1024 + n];
    Lb[((size_t)b*1024 + n)*1024] = sqrtf(S + 1.f);
    xnr[b*1024 + n] = sqrtf(fmaxf(2.f*S + 1.f, 1e-15f));
    float ts = blockReduceSum(S + 1.f);                   // sum of time^2 over rows
    float c = css[b*1024 + n];
    xnc[b*1024 + n] = (n == 0) ? sqrtf(ts) : sqrtf(fmaxf(c, 1e-15f));
}
// per-row mobius_matvec scale factor (no writeback of the matrix)
__global__ void k_mscale(const float* __restrict__ Mx, const float* __restrict__ xna,
                         float* __restrict__ sc){
    size_t row = blockIdx.x;
    int t = threadIdx.x;                                  // 128
    float v = Mx[row*KKW + t];
    float mm = blockReduceSum(v*v);
    if (t == 0){
        float mxn = sqrtf(fmaxf(mm, 1e-15f));
        float xn = xna[row];
        sc[row] = tanhf(mxn / xn * atanhc(xn)) / mxn;
    }
}
__global__ void k_hs(const float* __restrict__ Hsa, const float* __restrict__ MxRaw,
                     const float* __restrict__ xnr,
                     const float* __restrict__ whs, float* __restrict__ lg){
    size_t row = blockIdx.x;
    int t = threadIdx.x;                                  // 128
    float yr = MxRaw[row*KKW + t];
    float mm = blockReduceSum(yr*yr);
    float mxn = sqrtf(fmaxf(mm, 1e-15f));
    float xnb = xnr[row];
    float y = yr * (tanhf(mxn / xnb * atanhc(xnb)) / mxn);

    float x = Hsa[row*KKW + t];
    float xy = x*y, x2 = x*x, y2 = y*y;
    blockReduceSum3(xy, x2, y2);
    float den = fmaxf(1.f + 2.f*xy + x2*y2, 1e-15f);
    float h = ((1.f + 2.f*xy + y2)*x + (1.f - x2)*y) / den;
    float hn = sqrtf(fmaxf(blockReduceSum(h*h), 1e-15f));
    float u = atanhc(hn) / hn * h;
    float gv = gelu_exact(u);
    float gn = sqrtf(fmaxf(blockReduceSum(gv*gv), 1e-15f));
    float hs = tanhf(gn) / gn * gv;
    float mx = hs * whs[t], xn2 = hs*hs, dmy = 0.f;
    blockReduceSum3(mx, xn2, dmy);
    if (t == 0){
        float xn = sqrtf(fmaxf(xn2, 1e-15f));
        float mxn2 = sqrtf(fmaxf(mx*mx, 1e-15f));
        lg[row] = tanhf(mxn2 / xn * atanhc(xn)) * mx / mxn2;
    }
}
__global__ void k_hc(const float* __restrict__ Hca, const float* __restrict__ Yb,
                     const float* __restrict__ sc, float* __restrict__ Hc){
    int bj = blockIdx.x;
    int b = bj >> 7, j = bj & 127;
    int t = threadIdx.x;                                  // 256
    float x[4], y[4];
    #pragma unroll
    for (int i = 0; i < 4; i++){
        int m = t + i*256;
        size_t idx = ((size_t)(b*NCQ + m))*KKW + j;
        x[i] = Hca[idx]; y[i] = Yb[idx] * sc[b*NCQ + m];
    }
    float sxy = 0.f, sx2 = 0.f, sy2 = 0.f;
    #pragma unroll
    for (int i = 0; i < 4; i++){ sxy += x[i]*y[i]; sx2 += x[i]*x[i]; sy2 += y[i]*y[i]; }
    blockReduceSum3(sxy, sx2, sy2);
    float xy = sxy, x2 = sx2, y2 = sy2;
    float den = fmaxf(1.f + 2.f*xy + x2*y2, 1e-15f);
    float c1 = 1.f + 2.f*xy + y2, c2 = 1.f - x2;
    float h[4], hh = 0.f;
    #pragma unroll
    for (int i = 0; i < 4; i++){ h[i] = (c1*x[i] + c2*y[i]) / den; hh += h[i]*h[i]; }
    float hn = sqrtf(fmaxf(blockReduceSum(hh), 1e-15f));
    float fa = atanhc(hn) / hn;
    float g[4], gg = 0.f;
    #pragma unroll
    for (int i = 0; i < 4; i++){ g[i] = gelu_exact(fa*h[i]); gg += g[i]*g[i]; }
    float gn = sqrtf(fmaxf(blockReduceSum(gg), 1e-15f));
    float fb = tanhf(gn) / gn;
    #pragma unroll
    for (int i = 0; i < 4; i++)
        Hc[((size_t)(b*KKW + j))*NCQ + (t + i*256)] = fb * g[i];
}
__global__ void k_ac(const float* __restrict__ Hc, const float* __restrict__ whc,
                     float* __restrict__ lg){
    __shared__ float wsh[KKW];
    int b = blockIdx.y;
    int m = blockIdx.x*256 + threadIdx.x;
    if (threadIdx.x < KKW) wsh[threadIdx.x] = whc[threadIdx.x];
    __syncthreads();
    const float* base = Hc + (size_t)b*KKW*NCQ + m;
    float mx = 0.f, ss = 0.f;
    #pragma unroll 4
    for (int j = 0; j < KKW; j++){
        float v = base[(size_t)j*NCQ];
        mx += v * wsh[j]; ss += v*v;
    }
    float xn = sqrtf(fmaxf(ss, 1e-15f));
    float mxn = sqrtf(fmaxf(mx*mx, 1e-15f));
    lg[b*NCQ + m] = tanhf(mxn / xn * atanhc(xn)) * mx / mxn;
}
__global__ void k_softmax(const float* __restrict__ lg, float* __restrict__ out){
    int b = blockIdx.x, t = threadIdx.x;                  // 256
    float l[4];
    float lm = -3.4e38f;
    #pragma unroll
    for (int i = 0; i < 4; i++){ l[i] = lg[b*1024 + t + i*256]; lm = fmaxf(lm, l[i]); }
    float M = blockReduceMax(lm);
    float es = 0.f, e[4];
    #pragma unroll
    for (int i = 0; i < 4; i++){ e[i] = expf(l[i] - M); es += e[i]; }
    float S = blockReduceSum(es);
    #pragma unroll
    for (int i = 0; i < 4; i++) out[b*1024 + t + i*256] = e[i] / S;
}
__global__ void k_centroid_part(const float* __restrict__ Lx, const float* __restrict__ w,
                                float* __restrict__ part){
    __shared__ float wsh[128];
    int ch = blockIdx.x, b = blockIdx.y;
    int t = threadIdx.x;                                  // 288, t<257 active
    for (int i = t; i < 128; i += blockDim.x) wsh[i] = w[(size_t)b*NSQ + ch*128 + i];
    __syncthreads();
    if (t < DP1){
        const float* base = Lx + ((size_t)b*NSQ + (size_t)ch*128)*DPAD + t;
        float acc = 0.f;
        for (int n = 0; n < 128; n++) acc += wsh[n] * base[(size_t)n*DPAD];
        part[(b*8 + ch)*DP1 + t] = acc;
    }
}
__global__ void k_centroid_fin(const float* __restrict__ part, float* __restrict__ co){
    __shared__ float t0sh;
    int b = blockIdx.x, t = threadIdx.x;                  // 288
    float acc = 0.f;
    if (t < DP1){
        #pragma unroll
        for (int c = 0; c < 8; c++) acc += part[(b*8 + c)*DP1 + t];
    }
    float sp = (t >= 1 && t < DP1) ? acc*acc : 0.f;
    float ssp = blockReduceSum(sp);
    if (t == 0) t0sh = acc;
    __syncthreads();
    float inner = -t0sh*t0sh + ssp;
    float den = sqrtf(fmaxf(fabsf(inner), 1e-8f));
    if (t < DP1) co[(size_t)b*DP1 + t] = acc / den;
}
__global__ void k_concat(const float* __restrict__ cs, const float* __restrict__ cc,
                         float* __restrict__ out){
    int b = blockIdx.x, t = threadIdx.x;                  // 256
    float t0s = cs[(size_t)b*DP1];
    float t0c = cc[(size_t)b*DP1];
    float sps = cs[(size_t)b*DP1 + 1 + t];
    float spc = cc[(size_t)b*DP1 + 1 + t];
    float ns  = sqrtf(fmaxf(blockReduceSum(sps*sps), 1e-15f));
    float ncv = sqrtf(fmaxf(blockReduceSum(spc*spc), 1e-15f));
    float zs = acoshf(fmaxf(t0s, 1.f + 1e-7f)) * sps / ns;
    float zc = acoshf(fmaxf(t0c, 1.f + 1e-7f)) * spc / ncv;
    float vn = sqrtf(fmaxf(blockReduceSum(zs*zs + zc*zc), 1e-15f));
    float f = sinhf(vn) / vn;
    float* o = out + (size_t)b*513;
    if (t == 0) o[0] = coshf(vn);
    o[1 + t]       = f * zs;
    o[1 + DD + t]  = f * zc;
}

// ----------------------------- launch ----------------------------------------------
extern "C" void kernel_launch(void* const* d_in, const int* in_sizes, int n_in,
                              void* d_out, int out_size)
{
    const float* sent = (const float*)d_in[0];
    const float* comm = (const float*)d_in[1];
    const float* WlW  = (const float*)d_in[2];
    const float* Wlb  = (const float*)d_in[3];
    const float* WcW  = (const float*)d_in[4];
    const float* Wcb  = (const float*)d_in[5];
    const float* WsW  = (const float*)d_in[6];
    const float* Wsb  = (const float*)d_in[7];
    const float* whs  = (const float*)d_in[8];
    const float* whc  = (const float*)d_in[9];
    float* out = (float*)d_out;
    (void)in_sizes; (void)n_in; (void)out_size;

    float2 *c1, *c1T;
    float *sT, *rl, *Ls, *Lc, *Llin, *Yt, *Lb, *rss, *css, *xnr, *xnc, *msc,
          *Hsa, *Hca, *Mxs, *Mxc, *Hcm, *lgs, *lgc, *cs, *cc, *part;
    cudaGetSymbolAddress((void**)&c1,  g_c1);
    cudaGetSymbolAddress((void**)&c1T, g_c1T);
    cudaGetSymbolAddress((void**)&sT,  g_sT);
    cudaGetSymbolAddress((void**)&rl,  g_real);
    cudaGetSymbolAddress((void**)&Ls,  g_Ls);
    cudaGetSymbolAddress((void**)&Lc,  g_Lc);
    cudaGetSymbolAddress((void**)&Llin,g_Llin);
    cudaGetSymbolAddress((void**)&Yt,  g_Yt);
    cudaGetSymbolAddress((void**)&Lb,  g_Lb);
    cudaGetSymbolAddress((void**)&rss, g_rss);
    cudaGetSymbolAddress((void**)&css, g_css);
    cudaGetSymbolAddress((void**)&xnr, g_xnr);
    cudaGetSymbolAddress((void**)&xnc, g_xnc);
    cudaGetSymbolAddress((void**)&msc, g_msc);
    cudaGetSymbolAddress((void**)&Hsa, g_Hsa);
    cudaGetSymbolAddress((void**)&Hca, g_Hca);
    cudaGetSymbolAddress((void**)&Mxs, g_Mxs);
    cudaGetSymbolAddress((void**)&Mxc, g_Mxc);
    cudaGetSymbolAddress((void**)&Hcm, g_Hcm);
    cudaGetSymbolAddress((void**)&lgs, g_lgs);
    cudaGetSymbolAddress((void**)&lgc, g_lgc);
    cudaGetSymbolAddress((void**)&cs,  g_cs);
    cudaGetSymbolAddress((void**)&cc,  g_cc);
    cudaGetSymbolAddress((void**)&part,g_part);

    const int AS_OFF = BB*513;             // 16416
    const int AC_OFF = AS_OFF + BB*NSQ;    // 49184

    k_twfill<<<1, 1024>>>();
    k_zero<<<32, 1024>>>(rss, css);

    // ---- FFT2 (Hermitian-reduced second pass) + euclid_to_lorentz ----
    for (int branch = 0; branch < 2; branch++){
        const float* inp = branch ? comm : sent;
        float* Lout = branch ? Lc : Ls;
        int dolog = branch ? 1 : 0;
        k_fft256<<<BB*NSQ/4, dim3(64,4)>>>(inp, c1, dolog);
        k_transpose_ch<<<dim3(5, NSQ/32, BB), dim3(32,8)>>>(c1, c1T);
        k_fft1024<<<BB*DH, 256>>>(c1T, sT);
        k_transpose_fh<<<dim3(5, NSQ/32, BB), dim3(32,8)>>>(sT, rl);
        k_mirror<<<dim3(NSQ, BB), 128>>>(rl);
        k_e2l<<<BB*NSQ, 256>>>(rl, Lout);
    }

    // ---- linear layers ----
    k_pgemm<0,1,1,4,1><<<dim3(3,256,1),256>>>(Lc, WlW, Wlb, Llin,
        BB*NCQ, DP1, DP1, DPAD, DP1, DPAD, 0, 0, 0, nullptr, nullptr);
    k_zpad<<<(BB*NCQ*15 + 1023)/1024, 1024>>>(Llin, BB*NCQ);
    k_fix_time<<<BB*NCQ, 256>>>(Llin);

    k_pgemm<0,1,1,4,1><<<dim3(2,256,1),256>>>(Ls, WsW, Wsb, Yt,
        BB*NSQ, KP1, DP1, DPAD, DP1, KP1, 0, 0, 0, nullptr, nullptr);
    k_poincare<<<BB*NSQ, 128>>>(Yt, Hsa);

    k_pgemm<0,1,1,4,1><<<dim3(2,256,1),256>>>(Lc, WcW, Wcb, Yt,
        BB*NCQ, KP1, DP1, DPAD, DP1, KP1, 0, 0, 0, nullptr, nullptr);
    k_poincare<<<BB*NCQ, 128>>>(Yt, Hca);

    // ---- big einsum + lorentz_act + fused norms ----
    k_pgemm<0,1,2,4,4><<<dim3(8,8,BB),256>>>(Ls, Llin, nullptr, Lb,
        NSQ, NCQ, DP1, DPAD, DPAD, NCQ,
        (long)NSQ*DPAD, (long)NCQ*DPAD, (long)NSQ*NCQ, rss, css);
    k_nfin<<<BB, 1024>>>(rss, css, Lb, xnr, xnc);

    // ---- mobius_matvec GEMMs ----
    k_pgemm<0,0,0,4,4><<<dim3(1,8,BB),256>>>(Lb, Hca, nullptr, Mxs,
        NSQ, KKW, NCQ, NCQ, KKW, KKW,
        (long)NSQ*NCQ, (long)NCQ*KKW, (long)NSQ*KKW, nullptr, nullptr);
    k_pgemm<1,0,0,4,4><<<dim3(1,8,BB),256>>>(Lb, Hsa, nullptr, Mxc,
        NCQ, KKW, NSQ, NCQ, KKW, KKW,
        (long)NSQ*NCQ, (long)NSQ*KKW, (long)NCQ*KKW, nullptr, nullptr);
    k_mscale<<<BB*NCQ, 128>>>(Mxc, xnc, msc);

    // ---- mobius_add + gelu pipeline + attention logits ----
    k_hs<<<BB*NSQ, 128>>>(Hsa, Mxs, xnr, whs, lgs);
    k_hc<<<BB*KKW, 256>>>(Hca, Mxc, msc, Hcm);
    k_ac<<<dim3(NCQ/256, BB), 256>>>(Hcm, whc, lgc);

    // ---- softmaxes straight into output ----
    k_softmax<<<BB, 256>>>(lgs, out + AS_OFF);
    k_softmax<<<BB, 256>>>(lgc, out + AC_OFF);

    // ---- centroids + concat ----
    k_centroid_part<<<dim3(8,BB), 288>>>(Ls, out + AS_OFF, part);
    k_centroid_fin<<<BB, 288>>>(part, cs);
    k_centroid_part<<<dim3(8,BB), 288>>>(Lc, out + AC_OFF, part);
    k_centroid_fin<<<BB, 288>>>(part, cc);
    k_concat<<<BB, 256>>>(cs, cc, out);
}

// round 7
// speedup vs baseline: 2.7370x; 1.1081x over previous
#include <cuda_runtime.h>
#include <math.h>
#include <stdint.h>

#define BB  32
#define NSQ 1024
#define NCQ 1024
#define DD  256
#define DP1 257
#define DPAD 272
#define KKW 128
#define KP1 129
#define DH  129   // Hermitian-reduced column count

// ----------------------------- scratch (static device globals; no runtime alloc) ---
static __device__ float2 g_c1 [(size_t)2*BB*NSQ*DD];
static __device__ float2 g_c1T[(size_t)2*BB*DH*NSQ];
static __device__ float  g_sT [(size_t)2*BB*DH*NSQ];
static __device__ float  g_real[(size_t)2*BB*NSQ*DH];
static __device__ float  g_Ls [(size_t)BB*NSQ*DPAD];
static __device__ float  g_Lc [(size_t)BB*NCQ*DPAD];
static __device__ float  g_Llin[(size_t)BB*NCQ*DPAD];
static __device__ float  g_Yt [(size_t)BB*NSQ*KP1];
static __device__ float  g_Lb [(size_t)BB*NSQ*NCQ];
static __device__ float  g_rss[BB*NSQ];
static __device__ float  g_css[BB*NCQ];
static __device__ float  g_xnr[BB*NSQ];
static __device__ float  g_xnc[BB*NCQ];
static __device__ float  g_msc[BB*NCQ];
static __device__ float  g_Hsa[(size_t)BB*NSQ*KKW];
static __device__ float  g_Hca[(size_t)BB*NCQ*KKW];
static __device__ float  g_Mxs[(size_t)BB*NSQ*KKW];
static __device__ float  g_Mxc[(size_t)BB*NCQ*KKW];
static __device__ float  g_Hcm[(size_t)BB*KKW*NCQ];
static __device__ float  g_lgs[BB*NSQ];
static __device__ float  g_lgc[BB*NCQ];
static __device__ float  g_cs [BB*DP1];
static __device__ float  g_cc [BB*DP1];
static __device__ float  g_part[BB*8*DP1];
static __device__ float2 g_tw1024[1024];
static __device__ float2 g_tw256[256];

// ----------------------------- helpers ---------------------------------------------
__device__ __forceinline__ float atanhc(float x){
    x = fminf(fmaxf(x, -1.f + 1e-5f), 1.f - 1e-5f);
    return 0.5f * (log1pf(x) - log1pf(-x));
}
__device__ __forceinline__ float gelu_exact(float v){
    return 0.5f * v * (1.f + erff(v * 0.70710678118654752f));
}
__device__ __forceinline__ float2 cmul(float2 a, float2 b){
    return make_float2(a.x*b.x - a.y*b.y, a.x*b.y + a.y*b.x);
}
__device__ __forceinline__ float2 cadd(float2 a, float2 b){ return make_float2(a.x+b.x, a.y+b.y); }
__device__ __forceinline__ float2 csub(float2 a, float2 b){ return make_float2(a.x-b.x, a.y-b.y); }

__device__ __forceinline__ float wsum(float v){
    #pragma unroll
    for (int o = 16; o; o >>= 1) v += __shfl_xor_sync(0xffffffffu, v, o);
    return v;
}
__device__ __forceinline__ float blockReduceSum(float v){
    __shared__ float sh[32];
    #pragma unroll
    for (int o = 16; o; o >>= 1) v += __shfl_down_sync(0xffffffffu, v, o);
    int lane = threadIdx.x & 31, w = threadIdx.x >> 5;
    if (lane == 0) sh[w] = v;
    __syncthreads();
    int nw = (blockDim.x + 31) >> 5;
    v = (threadIdx.x < (unsigned)nw) ? sh[threadIdx.x] : 0.f;
    if (w == 0){
        #pragma unroll
        for (int o = 16; o; o >>= 1) v += __shfl_down_sync(0xffffffffu, v, o);
        if (lane == 0) sh[0] = v;
    }
    __syncthreads();
    float r = sh[0];
    __syncthreads();
    return r;
}
__device__ __forceinline__ void blockReduceSum3(float& a, float& b, float& c){
    __shared__ float sh3[32][3];
    #pragma unroll
    for (int o = 16; o; o >>= 1){
        a += __shfl_down_sync(0xffffffffu, a, o);
        b += __shfl_down_sync(0xffffffffu, b, o);
        c += __shfl_down_sync(0xffffffffu, c, o);
    }
    int lane = threadIdx.x & 31, w = threadIdx.x >> 5;
    if (lane == 0){ sh3[w][0] = a; sh3[w][1] = b; sh3[w][2] = c; }
    __syncthreads();
    int nw = (blockDim.x + 31) >> 5;
    a = (threadIdx.x < (unsigned)nw) ? sh3[threadIdx.x][0] : 0.f;
    b = (threadIdx.x < (unsigned)nw) ? sh3[threadIdx.x][1] : 0.f;
    c = (threadIdx.x < (unsigned)nw) ? sh3[threadIdx.x][2] : 0.f;
    if (w == 0){
        #pragma unroll
        for (int o = 16; o; o >>= 1){
            a += __shfl_down_sync(0xffffffffu, a, o);
            b += __shfl_down_sync(0xffffffffu, b, o);
            c += __shfl_down_sync(0xffffffffu, c, o);
        }
        if (lane == 0){ sh3[0][0] = a; sh3[0][1] = b; sh3[0][2] = c; }
    }
    __syncthreads();
    a = sh3[0][0]; b = sh3[0][1]; c = sh3[0][2];
    __syncthreads();
}
__device__ __forceinline__ float blockReduceMax(float v){
    __shared__ float sh[32];
    #pragma unroll
    for (int o = 16; o; o >>= 1) v = fmaxf(v, __shfl_down_sync(0xffffffffu, v, o));
    int lane = threadIdx.x & 31, w = threadIdx.x >> 5;
    if (lane == 0) sh[w] = v;
    __syncthreads();
    int nw = (blockDim.x + 31) >> 5;
    v = (threadIdx.x < (unsigned)nw) ? sh[threadIdx.x] : -3.4e38f;
    if (w == 0){
        #pragma unroll
        for (int o = 16; o; o >>= 1) v = fmaxf(v, __shfl_down_sync(0xffffffffu, v, o));
        if (lane == 0) sh[0] = v;
    }
    __syncthreads();
    float r = sh[0];
    __syncthreads();
    return r;
}
__device__ __forceinline__ uint32_t f2tf32(float v){
    uint32_t r;
    asm("cvt.rna.tf32.f32 %0, %1;" : "=r"(r) : "f"(v));
    return r;
}
__device__ __forceinline__ void mma_tf32(float* c, const uint32_t* a, const uint32_t* b){
    asm volatile("mma.sync.aligned.m16n8k8.row.col.f32.tf32.tf32.f32 "
        "{%0,%1,%2,%3}, {%4,%5,%6,%7}, {%8,%9}, {%0,%1,%2,%3};"
        : "+f"(c[0]), "+f"(c[1]), "+f"(c[2]), "+f"(c[3])
        : "r"(a[0]), "r"(a[1]), "r"(a[2]), "r"(a[3]), "r"(b[0]), "r"(b[1]));
}
__device__ __forceinline__ void cpa16(uint32_t dsh, const void* src){
    asm volatile("cp.async.ca.shared.global [%0], [%1], 16;" :: "r"(dsh), "l"(src));
}
__device__ __forceinline__ void cpa4z(uint32_t dsh, const void* src, bool pred){
    int sz = pred ? 4 : 0;
    asm volatile("cp.async.ca.shared.global [%0], [%1], 4, %2;" :: "r"(dsh), "l"(src), "r"(sz));
}
#define CP_COMMIT() asm volatile("cp.async.commit_group;" ::: "memory")
#define CP_WAIT1()  asm volatile("cp.async.wait_group 1;" ::: "memory")
#define CP_WAIT0()  asm volatile("cp.async.wait_group 0;" ::: "memory")

// ----------------------------- twiddle fill ----------------------------------------
__global__ void k_twfill(){
    int i = threadIdx.x;
    if (i < 1024){
        double a = -6.283185307179586476925287 * (double)i / 1024.0;
        g_tw1024[i] = make_float2((float)cos(a), (float)sin(a));
    }
    if (i < 256){
        double a = -6.283185307179586476925287 * (double)i / 256.0;
        g_tw256[i] = make_float2((float)cos(a), (float)sin(a));
    }
}
__global__ void k_zero(float* __restrict__ a, float* __restrict__ b){
    int i = blockIdx.x*1024 + threadIdx.x;
    a[i] = 0.f; b[i] = 0.f;
}

// ----------------------------- radix-4 Stockham FFT kernels ------------------------
// dual-branch: rows [0, BB*NSQ) = sentence (no log), rest = comment (with p_logmap0)
__global__ void k_fft256(const float* __restrict__ sent, const float* __restrict__ comm,
                         float2* __restrict__ out){
    __shared__ float2 bufA[4][256];
    __shared__ float2 bufB[4][256];
    __shared__ float2 tws[256];
    __shared__ float  rsum[4][2];
    int tx = threadIdx.x;                      // 64
    int ty = threadIdx.y;                      // 4
    int tid = ty*64 + tx;
    size_t row = (size_t)blockIdx.x*4 + ty;
    bool do_log = row >= (size_t)BB*NSQ;
    const float* x = do_log ? (comm + (row - (size_t)BB*NSQ)*256) : (sent + row*256);
    tws[tid] = g_tw256[tid];

    float v0 = x[tx], v1 = x[tx+64], v2 = x[tx+128], v3 = x[tx+192];
    float ss = v0*v0 + v1*v1 + v2*v2 + v3*v3;
    #pragma unroll
    for (int o = 16; o; o >>= 1) ss += __shfl_down_sync(0xffffffffu, ss, o);
    if ((tx & 31) == 0) rsum[ty][tx >> 5] = ss;
    __syncthreads();
    if (do_log){
        float tot = rsum[ty][0] + rsum[ty][1];
        float yn = sqrtf(fmaxf(tot, 1e-15f));
        float f = atanhc(yn) / yn;
        v0 *= f; v1 *= f; v2 *= f; v3 *= f;
    }
    bufA[ty][tx]       = make_float2(v0, 0.f);
    bufA[ty][tx + 64]  = make_float2(v1, 0.f);
    bufA[ty][tx + 128] = make_float2(v2, 0.f);
    bufA[ty][tx + 192] = make_float2(v3, 0.f);
    __syncthreads();

    float2* X = &bufA[ty][0];
    float2* Y = &bufB[ty][0];
    #pragma unroll
    for (int s = 0; s < 4; s++){
        int Ns = 1 << (2*s);
        int p = tx & (Ns - 1);
        float2 w1 = tws[p * (64/Ns)];
        float2 w2 = cmul(w1, w1);
        float2 w3 = cmul(w2, w1);
        float2 a0 = X[tx];
        float2 a1 = cmul(X[tx + 64],  w1);
        float2 a2 = cmul(X[tx + 128], w2);
        float2 a3 = cmul(X[tx + 192], w3);
        float2 pa = cadd(a0, a2), pb = csub(a0, a2);
        float2 pc = cadd(a1, a3), pd = csub(a1, a3);
        float2 dneg = make_float2(pd.y, -pd.x);
        float2 dpos = make_float2(-pd.y, pd.x);
        int idxD = ((tx >> (2*s)) << (2*s + 2)) + p;
        Y[idxD]          = cadd(pa, pc);
        Y[idxD + Ns]     = cadd(pb, dneg);
        Y[idxD + 2*Ns]   = csub(pa, pc);
        Y[idxD + 3*Ns]   = cadd(pb, dpos);
        __syncthreads();
        float2* tmp = X; X = Y; Y = tmp;
    }
    out[row*256 + tx]       = X[tx];
    out[row*256 + tx + 64]  = X[tx + 64];
    out[row*256 + tx + 128] = X[tx + 128];
    out[row*256 + tx + 192] = X[tx + 192];
}

__global__ void k_fft1024(const float2* __restrict__ in, float* __restrict__ outr){
    __shared__ float2 bufA[1024];
    __shared__ float2 bufB[1024];
    __shared__ float2 tws[1024];
    int t = threadIdx.x;                       // 256
    size_t row = blockIdx.x;
    const float2* src = in + row*1024;
    #pragma unroll
    for (int i = 0; i < 4; i++){
        tws[t + i*256]  = g_tw1024[t + i*256];
        bufA[t + i*256] = src[t + i*256];
    }
    __syncthreads();
    float2* X = bufA;
    float2* Y = bufB;
    #pragma unroll
    for (int s = 0; s < 5; s++){
        int Ns = 1 << (2*s);
        int p = t & (Ns - 1);
        float2 w1 = tws[p * (256/Ns)];
        float2 w2 = cmul(w1, w1);
        float2 w3 = cmul(w2, w1);
        float2 a0 = X[t];
        float2 a1 = cmul(X[t + 256], w1);
        float2 a2 = cmul(X[t + 512], w2);
        float2 a3 = cmul(X[t + 768], w3);
        float2 pa = cadd(a0, a2), pb = csub(a0, a2);
        float2 pc = cadd(a1, a3), pd = csub(a1, a3);
        float2 dneg = make_float2(pd.y, -pd.x);
        float2 dpos = make_float2(-pd.y, pd.x);
        int idxD = ((t >> (2*s)) << (2*s + 2)) + p;
        Y[idxD]        = cadd(pa, pc);
        Y[idxD + Ns]   = cadd(pb, dneg);
        Y[idxD + 2*Ns] = csub(pa, pc);
        Y[idxD + 3*Ns] = cadd(pb, dpos);
        __syncthreads();
        float2* tmp = X; X = Y; Y = tmp;
    }
    #pragma unroll
    for (int i = 0; i < 4; i++)
        outr[row*1024 + t + i*256] = X[t + i*256].x;
}

// transpose (2B, NS, 256)complex -> (2B, 129, NS)complex
__global__ void k_transpose_ch(const float2* __restrict__ in, float2* __restrict__ out){
    __shared__ float2 tile[32][33];
    int b = blockIdx.z;
    int c0 = blockIdx.x*32, r0 = blockIdx.y*32;
    const float2* src = in + (size_t)b*NSQ*DD;
    for (int i = threadIdx.y; i < 32; i += 8)
        tile[i][threadIdx.x] = src[(size_t)(r0+i)*DD + c0 + threadIdx.x];
    __syncthreads();
    float2* dst = out + (size_t)b*DH*NSQ;
    for (int i = threadIdx.y; i < 32; i += 8){
        int d = c0 + i;
        if (d < DH) dst[(size_t)d*NSQ + r0 + threadIdx.x] = tile[threadIdx.x][i];
    }
}
// transpose (2B, 129, NS) -> (2B, NS, 129) compact
__global__ void k_transpose_fh(const float* __restrict__ in, float* __restrict__ out){
    __shared__ float tile[32][33];
    int b = blockIdx.z;
    int d0 = blockIdx.x*32, n0 = blockIdx.y*32;
    const float* src = in + (size_t)b*DH*NSQ;
    for (int i = threadIdx.y; i < 32; i += 8){
        int d = d0 + i;
        tile[i][threadIdx.x] = (d < DH) ? src[(size_t)d*NSQ + n0 + threadIdx.x] : 0.f;
    }
    __syncthreads();
    float* dst = out + (size_t)b*NSQ*DH;
    int d = d0 + threadIdx.x;
    if (d < DH)
        for (int i = threadIdx.y; i < 32; i += 8)
            dst[(size_t)(n0+i)*DH + d] = tile[threadIdx.x][i];
}

// fused Hermitian mirror + euclid_to_lorentz; dual-branch output select.
// rl layout: (2B, NS, DH). col d<129 direct; col d>=129 = rl[(1024-n)%1024][256-d].
__global__ void k_e2l(const float* __restrict__ rl, float* __restrict__ Ls,
                      float* __restrict__ Lc){
    size_t row = blockIdx.x;                   // 0 .. 2*BB*NSQ-1
    int t = threadIdx.x;                       // 256
    size_t bb = row >> 10;
    int n = (int)(row & 1023);
    float v;
    if (t < DH){
        v = rl[(bb*NSQ + n)*DH + t];
    } else {
        int srcn = (1024 - n) & 1023;
        v = rl[(bb*NSQ + srcn)*DH + (256 - t)];
    }
    float ss = blockReduceSum(v*v);
    float xn = sqrtf(fmaxf(ss, 1e-15f)) + 1e-5f;
    float scl = fminf(1.f, 2.0f / xn);
    v *= scl;
    float vn = sqrtf(fmaxf(ss*scl*scl, 1e-15f));
    float f = sinhf(vn) / vn;
    float* out = (bb < BB) ? Ls : Lc;
    size_t orow = (bb < BB) ? row : row - (size_t)BB*NSQ;
    if (t == 0) out[orow*DPAD] = coshf(vn);
    out[orow*DPAD + 1 + t] = f * v;
    if (t < DPAD - DP1) out[orow*DPAD + DP1 + t] = 0.f;
}

// --------------- pipelined tensor-core GEMM (pure TF32, cp.async double-buffered) ---
template<int ATRANS, int BTRANS, int MODE, int VECA, int VECB>
__global__ void k_pgemm(const float* __restrict__ A, const float* __restrict__ Bm,
                        const float* __restrict__ bias, float* __restrict__ C,
                        int M, int N, int Klen, int lda, int ldb, int ldc,
                        long sA, long sB, long sC,
                        float* __restrict__ rss, float* __restrict__ css)
{
    constexpr int A_ELE = (ATRANS == 0) ? 128*20 : 16*132;
    constexpr int B_ELE = (BTRANS == 1) ? 128*20 : 16*132;
    __shared__ __align__(16) float As[2][A_ELE];
    __shared__ __align__(16) float Bs[2][B_ELE];

    int bz = blockIdx.z;
    A  += (size_t)bz * sA;
    Bm += (size_t)bz * sB;
    C  += (size_t)bz * sC;
    int bm = blockIdx.y * 128, bn = blockIdx.x * 128;
    int tid = threadIdx.x;
    int wid = tid >> 5, lane = tid & 31;
    int wm = (wid >> 2) * 64;
    int wn = (wid & 3) * 32;
    int g = lane >> 2, tg = lane & 3;

    int KT = (Klen + 15) >> 4;

    uint32_t asBase = (uint32_t)__cvta_generic_to_shared(&As[0][0]);
    uint32_t bsBase = (uint32_t)__cvta_generic_to_shared(&Bs[0][0]);

    auto issueA = [&](int st, int k0){
        uint32_t base = asBase + (uint32_t)(st * A_ELE * 4);
        if (ATRANS == 0){
            if (VECA == 4){
                #pragma unroll
                for (int i = 0; i < 2; i++){
                    int idx = tid + i*256;
                    int mm = idx >> 2, k4 = idx & 3;
                    cpa16(base + (mm*20 + k4*4)*4, A + (size_t)(bm+mm)*lda + k0 + k4*4);
                }
            } else {
                #pragma unroll
                for (int i = 0; i < 8; i++){
                    int idx = tid + i*256;
                    int mm = idx >> 4, kk = idx & 15;
                    int gm = bm + mm, gk = k0 + kk;
                    bool ok = (gm < M) && (gk < Klen);
                    const float* src = A + (ok ? ((size_t)gm*lda + gk) : 0);
                    cpa4z(base + (mm*20 + kk)*4, src, ok);
                }
            }
        } else {
            if (VECA == 4){
                #pragma unroll
                for (int i = 0; i < 2; i++){
                    int idx = tid + i*256;
                    int kk = idx >> 5, m4 = idx & 31;
                    cpa16(base + (kk*132 + m4*4)*4, A + (size_t)(k0+kk)*lda + bm + m4*4);
                }
            } else {
                #pragma unroll
                for (int i = 0; i < 8; i++){
                    int idx = tid + i*256;
                    int kk = idx >> 7, mm = idx & 127;
                    int gm = bm + mm, gk = k0 + kk;
                    bool ok = (gm < M) && (gk < Klen);
                    const float* src = A + (ok ? ((size_t)gk*lda + gm) : 0);
                    cpa4z(base + (kk*132 + mm)*4, src, ok);
                }
            }
        }
    };
    auto issueB = [&](int st, int k0){
        uint32_t base = bsBase + (uint32_t)(st * B_ELE * 4);
        if (BTRANS == 1){
            if (VECB == 4){
                #pragma unroll
                for (int i = 0; i < 2; i++){
                    int idx = tid + i*256;
                    int nn = idx >> 2, k4 = idx & 3;
                    cpa16(base + (nn*20 + k4*4)*4, Bm + (size_t)(bn+nn)*ldb + k0 + k4*4);
                }
            } else {
                #pragma unroll
                for (int i = 0; i < 8; i++){
                    int idx = tid + i*256;
                    int nn = idx >> 4, kk = idx & 15;
                    int gn = bn + nn, gk = k0 + kk;
                    bool ok = (gn < N) && (gk < Klen);
                    const float* src = Bm + (ok ? ((size_t)gn*ldb + gk) : 0);
                    cpa4z(base + (nn*20 + kk)*4, src, ok);
                }
            }
        } else {
            if (VECB == 4){
                #pragma unroll
                for (int i = 0; i < 2; i++){
                    int idx = tid + i*256;
                    int kk = idx >> 5, n4 = idx & 31;
                    cpa16(base + (kk*132 + n4*4)*4, Bm + (size_t)(k0+kk)*ldb + bn + n4*4);
                }
            } else {
                #pragma unroll
                for (int i = 0; i < 8; i++){
                    int idx = tid + i*256;
                    int kk = idx >> 7, nn = idx & 127;
                    int gn = bn + nn, gk = k0 + kk;
                    bool ok = (gn < N) && (gk < Klen);
                    const float* src = Bm + (ok ? ((size_t)gk*ldb + gn) : 0);
                    cpa4z(base + (kk*132 + nn)*4, src, ok);
                }
            }
        }
    };
    auto A_at = [&](int st, int m, int k)->float{
        return (ATRANS == 0) ? As[st][m*20 + k] : As[st][k*132 + m];
    };
    auto B_at = [&](int st, int n, int k)->float{
        return (BTRANS == 1) ? Bs[st][n*20 + k] : Bs[st][k*132 + n];
    };

    float acc[4][4][4];
    #pragma unroll
    for (int mi = 0; mi < 4; mi++)
        #pragma unroll
        for (int ni = 0; ni < 4; ni++)
            #pragma unroll
            for (int r = 0; r < 4; r++) acc[mi][ni][r] = 0.f;

    issueA(0, 0); issueB(0, 0);
    CP_COMMIT();

    for (int kt = 0; kt < KT; kt++){
        int st = kt & 1;
        if (kt + 1 < KT){
            issueA(st ^ 1, (kt+1)*16);
            issueB(st ^ 1, (kt+1)*16);
            CP_COMMIT();
            CP_WAIT1();
        } else {
            CP_WAIT0();
        }
        __syncthreads();

        #pragma unroll
        for (int ks = 0; ks < 2; ks++){
            int kk = ks*8;
            uint32_t bhf[4][2];
            #pragma unroll
            for (int ni = 0; ni < 4; ni++){
                int n = wn + ni*8 + g;
                bhf[ni][0] = f2tf32(B_at(st, n, kk+tg));
                bhf[ni][1] = f2tf32(B_at(st, n, kk+tg+4));
            }
            #pragma unroll
            for (int mi = 0; mi < 4; mi++){
                int m = wm + mi*16;
                uint32_t ahf[4];
                ahf[0] = f2tf32(A_at(st, m+g,   kk+tg));
                ahf[1] = f2tf32(A_at(st, m+g+8, kk+tg));
                ahf[2] = f2tf32(A_at(st, m+g,   kk+tg+4));
                ahf[3] = f2tf32(A_at(st, m+g+8, kk+tg+4));
                #pragma unroll
                for (int ni = 0; ni < 4; ni++)
                    mma_tf32(acc[mi][ni], ahf, bhf[ni]);
            }
        }
        __syncthreads();
    }

    // epilogue value transform
    #pragma unroll
    for (int mi = 0; mi < 4; mi++)
        #pragma unroll
        for (int ni = 0; ni < 4; ni++){
            int col = bn + wn + ni*8 + 2*tg;
            #pragma unroll
            for (int r = 0; r < 4; r++){
                int gn = col + (r & 1);
                float v = acc[mi][ni][r];
                if (MODE == 1 && gn < N) v += bias[gn];
                if (MODE == 2) v = (gn == 0) ? 0.f : gelu_exact(v);
                acc[mi][ni][r] = v;
            }
        }
    // store
    #pragma unroll
    for (int mi = 0; mi < 4; mi++)
        #pragma unroll
        for (int ni = 0; ni < 4; ni++){
            int col = bn + wn + ni*8 + 2*tg;
            #pragma unroll
            for (int r = 0; r < 4; r++){
                int gm = bm + wm + mi*16 + g + (r >= 2 ? 8 : 0);
                int gn = col + (r & 1);
                if (gn >= N) continue;
                C[(size_t)gm*ldc + gn] = acc[mi][ni][r];
            }
        }
    if (MODE == 2){
        #pragma unroll
        for (int mi = 0; mi < 4; mi++){
            #pragma unroll
            for (int half = 0; half < 2; half++){
                float rp = 0.f;
                #pragma unroll
                for (int ni = 0; ni < 4; ni++){
                    float a0 = acc[mi][ni][half*2], a1 = acc[mi][ni][half*2+1];
                    rp += a0*a0 + a1*a1;
                }
                rp += __shfl_down_sync(0xffffffffu, rp, 1);
                rp += __shfl_down_sync(0xffffffffu, rp, 2);
                if (tg == 0)
                    atomicAdd(&rss[(size_t)bz*1024 + bm + wm + mi*16 + g + half*8], rp);
            }
        }
        #pragma unroll
        for (int ni = 0; ni < 4; ni++){
            #pragma unroll
            for (int cb = 0; cb < 2; cb++){
                float cp = 0.f;
                #pragma unroll
                for (int mi = 0; mi < 4; mi++){
                    float a0 = acc[mi][ni][cb], a1 = acc[mi][ni][2+cb];
                    cp += a0*a0 + a1*a1;
                }
                cp += __shfl_down_sync(0xffffffffu, cp, 4);
                cp += __shfl_down_sync(0xffffffffu, cp, 8);
                cp += __shfl_down_sync(0xffffffffu, cp, 16);
                if (g == 0)
                    atomicAdd(&css[(size_t)bz*1024 + bn + wn + ni*8 + 2*tg + cb], cp);
            }
        }
    }
}

// ----------------------------- row-wise kernels ------------------------------------
__global__ void k_fix_time(float* __restrict__ Y){        // DPAD stride
    size_t row = blockIdx.x;
    int t = threadIdx.x;                                  // 256
    float sp = Y[row*DPAD + 1 + t];
    float S = blockReduceSum(sp*sp);
    if (t == 0) Y[row*DPAD] = sqrtf(S + 1.f);
}
// warp-per-row poincare: 129 -> 128
__global__ void k_poincare(const float* __restrict__ Y, float* __restrict__ out){
    size_t row = (size_t)blockIdx.x*8 + (threadIdx.x >> 5);
    int lane = threadIdx.x & 31;
    const float* y = Y + row*KP1 + 1;
    float v[4], s = 0.f;
    #pragma unroll
    for (int i = 0; i < 4; i++){ v[i] = y[lane + i*32]; s += v[i]*v[i]; }
    s = wsum(s);
    float inv = 1.f / (sqrtf(s + 1.f) + 1.f);
    float* o = out + row*KKW;
    #pragma unroll
    for (int i = 0; i < 4; i++) o[lane + i*32] = v[i] * inv;
}
// finalize norms from fused SSQ
__global__ void k_nfin(const float* __restrict__ rss, const float* __restrict__ css,
                       float* __restrict__ Lb, float* __restrict__ xnr,
                       float* __restrict__ xnc){
    int b = blockIdx.x, n = threadIdx.x;                  // 1024
    float S = rss[b*1024 + n];
    Lb[((size_t)b*1024 + n)*1024] = sqrtf(S + 1.f);
    xnr[b*1024 + n] = sqrtf(fmaxf(2.f*S + 1.f, 1e-15f));
    float ts = blockReduceSum(S + 1.f);
    float c = css[b*1024 + n];
    xnc[b*1024 + n] = (n == 0) ? sqrtf(ts) : sqrtf(fmaxf(c, 1e-15f));
}
// warp-per-row mobius_matvec scale factor
__global__ void k_mscale(const float* __restrict__ Mx, const float* __restrict__ xna,
                         float* __restrict__ sc){
    size_t row = (size_t)blockIdx.x*8 + (threadIdx.x >> 5);
    int lane = threadIdx.x & 31;
    const float* p = Mx + row*KKW;
    float s = 0.f;
    #pragma unroll
    for (int i = 0; i < 4; i++){ float v = p[lane + i*32]; s += v*v; }
    s = wsum(s);
    if (lane == 0){
        float mxn = sqrtf(fmaxf(s, 1e-15f));
        float xn = xna[row];
        sc[row] = tanhf(mxn / xn * atanhc(xn)) / mxn;
    }
}
// warp-per-row fused Hs pipeline (shuffle-only reductions)
__global__ void k_hs(const float* __restrict__ Hsa, const float* __restrict__ MxRaw,
                     const float* __restrict__ xnr,
                     const float* __restrict__ whs, float* __restrict__ lg){
    size_t row = (size_t)blockIdx.x*8 + (threadIdx.x >> 5);
    int lane = threadIdx.x & 31;
    const float* my = MxRaw + row*KKW;
    const float* hx = Hsa + row*KKW;
    float yr[4], x[4];
    float mm = 0.f;
    #pragma unroll
    for (int i = 0; i < 4; i++){
        yr[i] = my[lane + i*32];
        x[i]  = hx[lane + i*32];
        mm += yr[i]*yr[i];
    }
    mm = wsum(mm);
    float mxn = sqrtf(fmaxf(mm, 1e-15f));
    float xnb = xnr[row];
    float fac = tanhf(mxn / xnb * atanhc(xnb)) / mxn;

    float xy = 0.f, x2 = 0.f, y2 = 0.f;
    float y[4];
    #pragma unroll
    for (int i = 0; i < 4; i++){
        y[i] = yr[i] * fac;
        xy += x[i]*y[i]; x2 += x[i]*x[i]; y2 += y[i]*y[i];
    }
    xy = wsum(xy); x2 = wsum(x2); y2 = wsum(y2);
    float den = fmaxf(1.f + 2.f*xy + x2*y2, 1e-15f);
    float c1 = (1.f + 2.f*xy + y2) / den, c2 = (1.f - x2) / den;
    float h[4], hh = 0.f;
    #pragma unroll
    for (int i = 0; i < 4; i++){ h[i] = c1*x[i] + c2*y[i]; hh += h[i]*h[i]; }
    hh = wsum(hh);
    float hn = sqrtf(fmaxf(hh, 1e-15f));
    float fa = atanhc(hn) / hn;
    float gv[4], gg = 0.f;
    #pragma unroll
    for (int i = 0; i < 4; i++){ gv[i] = gelu_exact(fa*h[i]); gg += gv[i]*gv[i]; }
    gg = wsum(gg);
    float gn = sqrtf(fmaxf(gg, 1e-15f));
    float fb = tanhf(gn) / gn;
    float mx = 0.f, xn2 = 0.f;
    #pragma unroll
    for (int i = 0; i < 4; i++){
        float hs = fb * gv[i];
        mx += hs * __ldg(&whs[lane + i*32]);
        xn2 += hs*hs;
    }
    mx = wsum(mx); xn2 = wsum(xn2);
    if (lane == 0){
        float xn = sqrtf(fmaxf(xn2, 1e-15f));
        float mxn2 = sqrtf(fmaxf(mx*mx, 1e-15f));
        lg[row] = tanhf(mxn2 / xn * atanhc(xn)) * mx / mxn2;
    }
}
__global__ void k_hc(const float* __restrict__ Hca, const float* __restrict__ Yb,
                     const float* __restrict__ sc, float* __restrict__ Hc){
    int bj = blockIdx.x;
    int b = bj >> 7, j = bj & 127;
    int t = threadIdx.x;                                  // 256
    float x[4], y[4];
    #pragma unroll
    for (int i = 0; i < 4; i++){
        int m = t + i*256;
        size_t idx = ((size_t)(b*NCQ + m))*KKW + j;
        x[i] = Hca[idx]; y[i] = Yb[idx] * sc[b*NCQ + m];
    }
    float sxy = 0.f, sx2 = 0.f, sy2 = 0.f;
    #pragma unroll
    for (int i = 0; i < 4; i++){ sxy += x[i]*y[i]; sx2 += x[i]*x[i]; sy2 += y[i]*y[i]; }
    blockReduceSum3(sxy, sx2, sy2);
    float xy = sxy, x2 = sx2, y2 = sy2;
    float den = fmaxf(1.f + 2.f*xy + x2*y2, 1e-15f);
    float c1 = 1.f + 2.f*xy + y2, c2 = 1.f - x2;
    float h[4], hh = 0.f;
    #pragma unroll
    for (int i = 0; i < 4; i++){ h[i] = (c1*x[i] + c2*y[i]) / den; hh += h[i]*h[i]; }
    float hn = sqrtf(fmaxf(blockReduceSum(hh), 1e-15f));
    float fa = atanhc(hn) / hn;
    float g[4], gg = 0.f;
    #pragma unroll
    for (int i = 0; i < 4; i++){ g[i] = gelu_exact(fa*h[i]); gg += g[i]*g[i]; }
    float gn = sqrtf(fmaxf(blockReduceSum(gg), 1e-15f));
    float fb = tanhf(gn) / gn;
    #pragma unroll
    for (int i = 0; i < 4; i++)
        Hc[((size_t)(b*KKW + j))*NCQ + (t + i*256)] = fb * g[i];
}
__global__ void k_ac(const float* __restrict__ Hc, const float* __restrict__ whc,
                     float* __restrict__ lg){
    __shared__ float wsh[KKW];
    int b = blockIdx.y;
    int m = blockIdx.x*256 + threadIdx.x;
    if (threadIdx.x < KKW) wsh[threadIdx.x] = whc[threadIdx.x];
    __syncthreads();
    const float* base = Hc + (size_t)b*KKW*NCQ + m;
    float mx = 0.f, ss = 0.f;
    #pragma unroll 4
    for (int j = 0; j < KKW; j++){
        float v = base[(size_t)j*NCQ];
        mx += v * wsh[j]; ss += v*v;
    }
    float xn = sqrtf(fmaxf(ss, 1e-15f));
    float mxn = sqrtf(fmaxf(mx*mx, 1e-15f));
    lg[b*NCQ + m] = tanhf(mxn / xn * atanhc(xn)) * mx / mxn;
}
__global__ void k_softmax(const float* __restrict__ lg, float* __restrict__ out){
    int b = blockIdx.x, t = threadIdx.x;                  // 256
    float l[4];
    float lm = -3.4e38f;
    #pragma unroll
    for (int i = 0; i < 4; i++){ l[i] = lg[b*1024 + t + i*256]; lm = fmaxf(lm, l[i]); }
    float M = blockReduceMax(lm);
    float es = 0.f, e[4];
    #pragma unroll
    for (int i = 0; i < 4; i++){ e[i] = expf(l[i] - M); es += e[i]; }
    float S = blockReduceSum(es);
    #pragma unroll
    for (int i = 0; i < 4; i++) out[b*1024 + t + i*256] = e[i] / S;
}
__global__ void k_centroid_part(const float* __restrict__ Lx, const float* __restrict__ w,
                                float* __restrict__ part){
    __shared__ float wsh[128];
    int ch = blockIdx.x, b = blockIdx.y;
    int t = threadIdx.x;                                  // 288, t<257 active
    for (int i = t; i < 128; i += blockDim.x) wsh[i] = w[(size_t)b*NSQ + ch*128 + i];
    __syncthreads();
    if (t < DP1){
        const float* base = Lx + ((size_t)b*NSQ + (size_t)ch*128)*DPAD + t;
        float acc = 0.f;
        for (int n = 0; n < 128; n++) acc += wsh[n] * base[(size_t)n*DPAD];
        part[(b*8 + ch)*DP1 + t] = acc;
    }
}
__global__ void k_centroid_fin(const float* __restrict__ part, float* __restrict__ co){
    __shared__ float t0sh;
    int b = blockIdx.x, t = threadIdx.x;                  // 288
    float acc = 0.f;
    if (t < DP1){
        #pragma unroll
        for (int c = 0; c < 8; c++) acc += part[(b*8 + c)*DP1 + t];
    }
    float sp = (t >= 1 && t < DP1) ? acc*acc : 0.f;
    float ssp = blockReduceSum(sp);
    if (t == 0) t0sh = acc;
    __syncthreads();
    float inner = -t0sh*t0sh + ssp;
    float den = sqrtf(fmaxf(fabsf(inner), 1e-8f));
    if (t < DP1) co[(size_t)b*DP1 + t] = acc / den;
}
__global__ void k_concat(const float* __restrict__ cs, const float* __restrict__ cc,
                         float* __restrict__ out){
    int b = blockIdx.x, t = threadIdx.x;                  // 256
    float t0s = cs[(size_t)b*DP1];
    float t0c = cc[(size_t)b*DP1];
    float sps = cs[(size_t)b*DP1 + 1 + t];
    float spc = cc[(size_t)b*DP1 + 1 + t];
    float ns  = sqrtf(fmaxf(blockReduceSum(sps*sps), 1e-15f));
    float ncv = sqrtf(fmaxf(blockReduceSum(spc*spc), 1e-15f));
    float zs = acoshf(fmaxf(t0s, 1.f + 1e-7f)) * sps / ns;
    float zc = acoshf(fmaxf(t0c, 1.f + 1e-7f)) * spc / ncv;
    float vn = sqrtf(fmaxf(blockReduceSum(zs*zs + zc*zc), 1e-15f));
    float f = sinhf(vn) / vn;
    float* o = out + (size_t)b*513;
    if (t == 0) o[0] = coshf(vn);
    o[1 + t]       = f * zs;
    o[1 + DD + t]  = f * zc;
}

// ----------------------------- launch ----------------------------------------------
extern "C" void kernel_launch(void* const* d_in, const int* in_sizes, int n_in,
                              void* d_out, int out_size)
{
    const float* sent = (const float*)d_in[0];
    const float* comm = (const float*)d_in[1];
    const float* WlW  = (const float*)d_in[2];
    const float* Wlb  = (const float*)d_in[3];
    const float* WcW  = (const float*)d_in[4];
    const float* Wcb  = (const float*)d_in[5];
    const float* WsW  = (const float*)d_in[6];
    const float* Wsb  = (const float*)d_in[7];
    const float* whs  = (const float*)d_in[8];
    const float* whc  = (const float*)d_in[9];
    float* out = (float*)d_out;
    (void)in_sizes; (void)n_in; (void)out_size;

    float2 *c1, *c1T;
    float *sT, *rl, *Ls, *Lc, *Llin, *Yt, *Lb, *rss, *css, *xnr, *xnc, *msc,
          *Hsa, *Hca, *Mxs, *Mxc, *Hcm, *lgs, *lgc, *cs, *cc, *part;
    cudaGetSymbolAddress((void**)&c1,  g_c1);
    cudaGetSymbolAddress((void**)&c1T, g_c1T);
    cudaGetSymbolAddress((void**)&sT,  g_sT);
    cudaGetSymbolAddress((void**)&rl,  g_real);
    cudaGetSymbolAddress((void**)&Ls,  g_Ls);
    cudaGetSymbolAddress((void**)&Lc,  g_Lc);
    cudaGetSymbolAddress((void**)&Llin,g_Llin);
    cudaGetSymbolAddress((void**)&Yt,  g_Yt);
    cudaGetSymbolAddress((void**)&Lb,  g_Lb);
    cudaGetSymbolAddress((void**)&rss, g_rss);
    cudaGetSymbolAddress((void**)&css, g_css);
    cudaGetSymbolAddress((void**)&xnr, g_xnr);
    cudaGetSymbolAddress((void**)&xnc, g_xnc);
    cudaGetSymbolAddress((void**)&msc, g_msc);
    cudaGetSymbolAddress((void**)&Hsa, g_Hsa);
    cudaGetSymbolAddress((void**)&Hca, g_Hca);
    cudaGetSymbolAddress((void**)&Mxs, g_Mxs);
    cudaGetSymbolAddress((void**)&Mxc, g_Mxc);
    cudaGetSymbolAddress((void**)&Hcm, g_Hcm);
    cudaGetSymbolAddress((void**)&lgs, g_lgs);
    cudaGetSymbolAddress((void**)&lgc, g_lgc);
    cudaGetSymbolAddress((void**)&cs,  g_cs);
    cudaGetSymbolAddress((void**)&cc,  g_cc);
    cudaGetSymbolAddress((void**)&part,g_part);

    const int AS_OFF = BB*513;             // 16416
    const int AC_OFF = AS_OFF + BB*NSQ;    // 49184

    k_twfill<<<1, 1024>>>();
    k_zero<<<32, 1024>>>(rss, css);

    // ---- dual-branch FFT2 (Hermitian-reduced) + fused mirror + euclid_to_lorentz ----
    k_fft256<<<2*BB*NSQ/4, dim3(64,4)>>>(sent, comm, c1);
    k_transpose_ch<<<dim3(5, NSQ/32, 2*BB), dim3(32,8)>>>(c1, c1T);
    k_fft1024<<<2*BB*DH, 256>>>(c1T, sT);
    k_transpose_fh<<<dim3(5, NSQ/32, 2*BB), dim3(32,8)>>>(sT, rl);
    k_e2l<<<2*BB*NSQ, 256>>>(rl, Ls, Lc);

    // ---- linear layers ----
    k_pgemm<0,1,1,4,1><<<dim3(3,256,1),256>>>(Lc, WlW, Wlb, Llin,
        BB*NCQ, DP1, DP1, DPAD, DP1, DPAD, 0, 0, 0, nullptr, nullptr);
    k_fix_time<<<BB*NCQ, 256>>>(Llin);

    k_pgemm<0,1,1,4,1><<<dim3(2,256,1),256>>>(Ls, WsW, Wsb, Yt,
        BB*NSQ, KP1, DP1, DPAD, DP1, KP1, 0, 0, 0, nullptr, nullptr);
    k_poincare<<<BB*NSQ/8, 256>>>(Yt, Hsa);

    k_pgemm<0,1,1,4,1><<<dim3(2,256,1),256>>>(Lc, WcW, Wcb, Yt,
        BB*NCQ, KP1, DP1, DPAD, DP1, KP1, 0, 0, 0, nullptr, nullptr);
    k_poincare<<<BB*NCQ/8, 256>>>(Yt, Hca);

    // ---- big einsum + lorentz_act + fused norms ----
    k_pgemm<0,1,2,4,4><<<dim3(8,8,BB),256>>>(Ls, Llin, nullptr, Lb,
        NSQ, NCQ, DP1, DPAD, DPAD, NCQ,
        (long)NSQ*DPAD, (long)NCQ*DPAD, (long)NSQ*NCQ, rss, css);
    k_nfin<<<BB, 1024>>>(rss, css, Lb, xnr, xnc);

    // ---- mobius_matvec GEMMs ----
    k_pgemm<0,0,0,4,4><<<dim3(1,8,BB),256>>>(Lb, Hca, nullptr, Mxs,
        NSQ, KKW, NCQ, NCQ, KKW, KKW,
        (long)NSQ*NCQ, (long)NCQ*KKW, (long)NSQ*KKW, nullptr, nullptr);
    k_pgemm<1,0,0,4,4><<<dim3(1,8,BB),256>>>(Lb, Hsa, nullptr, Mxc,
        NCQ, KKW, NSQ, NCQ, KKW, KKW,
        (long)NSQ*NCQ, (long)NSQ*KKW, (long)NCQ*KKW, nullptr, nullptr);
    k_mscale<<<BB*NCQ/8, 256>>>(Mxc, xnc, msc);

    // ---- mobius_add + gelu pipeline + attention logits ----
    k_hs<<<BB*NSQ/8, 256>>>(Hsa, Mxs, xnr, whs, lgs);
    k_hc<<<BB*KKW, 256>>>(Hca, Mxc, msc, Hcm);
    k_ac<<<dim3(NCQ/256, BB), 256>>>(Hcm, whc, lgc);

    // ---- softmaxes straight into output ----
    k_softmax<<<BB, 256>>>(lgs, out + AS_OFF);
    k_softmax<<<BB, 256>>>(lgc, out + AC_OFF);

    // ---- centroids + concat ----
    k_centroid_part<<<dim3(8,BB), 288>>>(Ls, out + AS_OFF, part);
    k_centroid_fin<<<BB, 288>>>(part, cs);
    k_centroid_part<<<dim3(8,BB), 288>>>(Lc, out + AC_OFF, part);
    k_centroid_fin<<<BB, 288>>>(part, cc);
    k_concat<<<BB, 256>>>(cs, cc, out);
}

// round 8
// speedup vs baseline: 2.8429x; 1.0387x over previous
#include <cuda_runtime.h>
#include <math.h>
#include <stdint.h>

#define BB  32
#define NSQ 1024
#define NCQ 1024
#define DD  256
#define DP1 257
#define DPAD 272
#define KKW 128
#define KP1 129
#define DH  129   // Hermitian-reduced column count

// ----------------------------- scratch (static device globals; no runtime alloc) ---
static __device__ float2 g_c1 [(size_t)2*BB*NSQ*DH];
static __device__ float2 g_c1T[(size_t)2*BB*DH*NSQ];
static __device__ float  g_sT [(size_t)2*BB*DH*NSQ];
static __device__ float  g_real[(size_t)2*BB*NSQ*DH];
static __device__ float  g_Ls [(size_t)BB*NSQ*DPAD];
static __device__ float  g_Lc [(size_t)BB*NCQ*DPAD];
static __device__ float  g_Llin[(size_t)BB*NCQ*DPAD];
static __device__ float  g_Yt [(size_t)BB*NSQ*KP1];
static __device__ float  g_Lb [(size_t)BB*NSQ*NCQ];
static __device__ float  g_Wt [(size_t)896*DPAD];     // Wl@0, Ws@384*DPAD, Wc@640*DPAD
static __device__ float  g_rss[BB*NSQ];
static __device__ float  g_css[BB*NCQ];
static __device__ float  g_amx[BB*NCQ];
static __device__ float  g_ass[BB*NCQ];
static __device__ float  g_xnr[BB*NSQ];
static __device__ float  g_xnc[BB*NCQ];
static __device__ float  g_msc[BB*NCQ];
static __device__ float  g_Hsa[(size_t)BB*NSQ*KKW];
static __device__ float  g_Hca[(size_t)BB*NCQ*KKW];
static __device__ float  g_HcaT[(size_t)BB*KKW*NCQ];
static __device__ float  g_Mxs[(size_t)BB*NSQ*KKW];
static __device__ float  g_MxcT[(size_t)BB*KKW*NCQ];
static __device__ float  g_lgs[BB*NSQ];
static __device__ float  g_lgc[BB*NCQ];
static __device__ float  g_cs [BB*DP1];
static __device__ float  g_cc [BB*DP1];
static __device__ float  g_part[BB*8*DP1];
static __device__ float2 g_tw1024[1024];
static __device__ float2 g_tw256[256];

// ----------------------------- helpers ---------------------------------------------
__device__ __forceinline__ float atanhc(float x){
    x = fminf(fmaxf(x, -1.f + 1e-5f), 1.f - 1e-5f);
    return 0.5f * (log1pf(x) - log1pf(-x));
}
__device__ __forceinline__ float gelu_exact(float v){
    return 0.5f * v * (1.f + erff(v * 0.70710678118654752f));
}
__device__ __forceinline__ float2 cmul(float2 a, float2 b){
    return make_float2(a.x*b.x - a.y*b.y, a.x*b.y + a.y*b.x);
}
__device__ __forceinline__ float2 cadd(float2 a, float2 b){ return make_float2(a.x+b.x, a.y+b.y); }
__device__ __forceinline__ float2 csub(float2 a, float2 b){ return make_float2(a.x-b.x, a.y-b.y); }

__device__ __forceinline__ float wsum(float v){
    #pragma unroll
    for (int o = 16; o; o >>= 1) v += __shfl_xor_sync(0xffffffffu, v, o);
    return v;
}
__device__ __forceinline__ float blockReduceSum(float v){
    __shared__ float sh[32];
    #pragma unroll
    for (int o = 16; o; o >>= 1) v += __shfl_down_sync(0xffffffffu, v, o);
    int lane = threadIdx.x & 31, w = threadIdx.x >> 5;
    if (lane == 0) sh[w] = v;
    __syncthreads();
    int nw = (blockDim.x + 31) >> 5;
    v = (threadIdx.x < (unsigned)nw) ? sh[threadIdx.x] : 0.f;
    if (w == 0){
        #pragma unroll
        for (int o = 16; o; o >>= 1) v += __shfl_down_sync(0xffffffffu, v, o);
        if (lane == 0) sh[0] = v;
    }
    __syncthreads();
    float r = sh[0];
    __syncthreads();
    return r;
}
__device__ __forceinline__ void blockReduceSum3(float& a, float& b, float& c){
    __shared__ float sh3[32][3];
    #pragma unroll
    for (int o = 16; o; o >>= 1){
        a += __shfl_down_sync(0xffffffffu, a, o);
        b += __shfl_down_sync(0xffffffffu, b, o);
        c += __shfl_down_sync(0xffffffffu, c, o);
    }
    int lane = threadIdx.x & 31, w = threadIdx.x >> 5;
    if (lane == 0){ sh3[w][0] = a; sh3[w][1] = b; sh3[w][2] = c; }
    __syncthreads();
    int nw = (blockDim.x + 31) >> 5;
    a = (threadIdx.x < (unsigned)nw) ? sh3[threadIdx.x][0] : 0.f;
    b = (threadIdx.x < (unsigned)nw) ? sh3[threadIdx.x][1] : 0.f;
    c = (threadIdx.x < (unsigned)nw) ? sh3[threadIdx.x][2] : 0.f;
    if (w == 0){
        #pragma unroll
        for (int o = 16; o; o >>= 1){
            a += __shfl_down_sync(0xffffffffu, a, o);
            b += __shfl_down_sync(0xffffffffu, b, o);
            c += __shfl_down_sync(0xffffffffu, c, o);
        }
        if (lane == 0){ sh3[0][0] = a; sh3[0][1] = b; sh3[0][2] = c; }
    }
    __syncthreads();
    a = sh3[0][0]; b = sh3[0][1]; c = sh3[0][2];
    __syncthreads();
}
__device__ __forceinline__ float blockReduceMax(float v){
    __shared__ float sh[32];
    #pragma unroll
    for (int o = 16; o; o >>= 1) v = fmaxf(v, __shfl_down_sync(0xffffffffu, v, o));
    int lane = threadIdx.x & 31, w = threadIdx.x >> 5;
    if (lane == 0) sh[w] = v;
    __syncthreads();
    int nw = (blockDim.x + 31) >> 5;
    v = (threadIdx.x < (unsigned)nw) ? sh[threadIdx.x] : -3.4e38f;
    if (w == 0){
        #pragma unroll
        for (int o = 16; o; o >>= 1) v = fmaxf(v, __shfl_down_sync(0xffffffffu, v, o));
        if (lane == 0) sh[0] = v;
    }
    __syncthreads();
    float r = sh[0];
    __syncthreads();
    return r;
}
__device__ __forceinline__ uint32_t f2tf32(float v){
    uint32_t r;
    asm("cvt.rna.tf32.f32 %0, %1;" : "=r"(r) : "f"(v));
    return r;
}
__device__ __forceinline__ float tf32r(float v){ return __uint_as_float(f2tf32(v)); }
__device__ __forceinline__ void mma_tf32(float* c, const uint32_t* a, const uint32_t* b){
    asm volatile("mma.sync.aligned.m16n8k8.row.col.f32.tf32.tf32.f32 "
        "{%0,%1,%2,%3}, {%4,%5,%6,%7}, {%8,%9}, {%0,%1,%2,%3};"
        : "+f"(c[0]), "+f"(c[1]), "+f"(c[2]), "+f"(c[3])
        : "r"(a[0]), "r"(a[1]), "r"(a[2]), "r"(a[3]), "r"(b[0]), "r"(b[1]));
}
__device__ __forceinline__ void cpa16(uint32_t dsh, const void* src){
    asm volatile("cp.async.ca.shared.global [%0], [%1], 16;" :: "r"(dsh), "l"(src));
}
#define CP_COMMIT() asm volatile("cp.async.commit_group;" ::: "memory")
#define CP_WAIT1()  asm volatile("cp.async.wait_group 1;" ::: "memory")
#define CP_WAIT0()  asm volatile("cp.async.wait_group 0;" ::: "memory")

// ----------------------------- setup kernels ---------------------------------------
__global__ void k_twfill(){
    int i = threadIdx.x;
    if (i < 1024){
        double a = -6.283185307179586476925287 * (double)i / 1024.0;
        g_tw1024[i] = make_float2((float)cos(a), (float)sin(a));
    }
    if (i < 256){
        double a = -6.283185307179586476925287 * (double)i / 256.0;
        g_tw256[i] = make_float2((float)cos(a), (float)sin(a));
    }
}
__global__ void k_zero(float* __restrict__ a, float* __restrict__ b,
                       float* __restrict__ c, float* __restrict__ d){
    int i = blockIdx.x*1024 + threadIdx.x;
    a[i] = 0.f; b[i] = 0.f; c[i] = 0.f; d[i] = 0.f;
}
// pre-rounded + padded weight copies (pad rows/cols stay zero from static init)
__global__ void k_wprep(const float* __restrict__ Wl, const float* __restrict__ Ws,
                        const float* __restrict__ Wc, float* __restrict__ Wt){
    int r = blockIdx.x;           // 0..514
    int t = threadIdx.x;          // 288
    if (t >= DP1) return;
    const float* src; float* dst;
    if (r < DP1){ src = Wl + (size_t)r*DP1; dst = Wt + (size_t)r*DPAD; }
    else if (r < DP1 + KP1){ int rr = r - DP1; src = Ws + (size_t)rr*DP1; dst = Wt + (size_t)(384+rr)*DPAD; }
    else { int rr = r - DP1 - KP1; src = Wc + (size_t)rr*DP1; dst = Wt + (size_t)(640+rr)*DPAD; }
    dst[t] = tf32r(src[t]);
}

// ----------------------------- radix-4 Stockham FFT kernels ------------------------
// dual-branch; compact Hermitian output (only cols 0..128)
__global__ void k_fft256(const float* __restrict__ sent, const float* __restrict__ comm,
                         float2* __restrict__ out){
    __shared__ float2 bufA[4][256];
    __shared__ float2 bufB[4][256];
    __shared__ float2 tws[256];
    __shared__ float  rsum[4][2];
    int tx = threadIdx.x;                      // 64
    int ty = threadIdx.y;                      // 4
    int tid = ty*64 + tx;
    size_t row = (size_t)blockIdx.x*4 + ty;
    bool do_log = row >= (size_t)BB*NSQ;
    const float* x = do_log ? (comm + (row - (size_t)BB*NSQ)*256) : (sent + row*256);
    tws[tid] = g_tw256[tid];

    float v0 = x[tx], v1 = x[tx+64], v2 = x[tx+128], v3 = x[tx+192];
    float ss = v0*v0 + v1*v1 + v2*v2 + v3*v3;
    #pragma unroll
    for (int o = 16; o; o >>= 1) ss += __shfl_down_sync(0xffffffffu, ss, o);
    if ((tx & 31) == 0) rsum[ty][tx >> 5] = ss;
    __syncthreads();
    if (do_log){
        float tot = rsum[ty][0] + rsum[ty][1];
        float yn = sqrtf(fmaxf(tot, 1e-15f));
        float f = atanhc(yn) / yn;
        v0 *= f; v1 *= f; v2 *= f; v3 *= f;
    }
    bufA[ty][tx]       = make_float2(v0, 0.f);
    bufA[ty][tx + 64]  = make_float2(v1, 0.f);
    bufA[ty][tx + 128] = make_float2(v2, 0.f);
    bufA[ty][tx + 192] = make_float2(v3, 0.f);
    __syncthreads();

    float2* X = &bufA[ty][0];
    float2* Y = &bufB[ty][0];
    #pragma unroll
    for (int s = 0; s < 4; s++){
        int Ns = 1 << (2*s);
        int p = tx & (Ns - 1);
        float2 w1 = tws[p * (64/Ns)];
        float2 w2 = cmul(w1, w1);
        float2 w3 = cmul(w2, w1);
        float2 a0 = X[tx];
        float2 a1 = cmul(X[tx + 64],  w1);
        float2 a2 = cmul(X[tx + 128], w2);
        float2 a3 = cmul(X[tx + 192], w3);
        float2 pa = cadd(a0, a2), pb = csub(a0, a2);
        float2 pc = cadd(a1, a3), pd = csub(a1, a3);
        float2 dneg = make_float2(pd.y, -pd.x);
        float2 dpos = make_float2(-pd.y, pd.x);
        int idxD = ((tx >> (2*s)) << (2*s + 2)) + p;
        Y[idxD]          = cadd(pa, pc);
        Y[idxD + Ns]     = cadd(pb, dneg);
        Y[idxD + 2*Ns]   = csub(pa, pc);
        Y[idxD + 3*Ns]   = cadd(pb, dpos);
        __syncthreads();
        float2* tmp = X; X = Y; Y = tmp;
    }
    out[row*DH + tx]      = X[tx];
    out[row*DH + tx + 64] = X[tx + 64];
    if (tx == 0) out[row*DH + 128] = X[128];
}

__global__ void k_fft1024(const float2* __restrict__ in, float* __restrict__ outr){
    __shared__ float2 bufA[1024];
    __shared__ float2 bufB[1024];
    __shared__ float2 tws[1024];
    int t = threadIdx.x;                       // 256
    size_t row = blockIdx.x;
    const float2* src = in + row*1024;
    #pragma unroll
    for (int i = 0; i < 4; i++){
        tws[t + i*256]  = g_tw1024[t + i*256];
        bufA[t + i*256] = src[t + i*256];
    }
    __syncthreads();
    float2* X = bufA;
    float2* Y = bufB;
    #pragma unroll
    for (int s = 0; s < 5; s++){
        int Ns = 1 << (2*s);
        int p = t & (Ns - 1);
        float2 w1 = tws[p * (256/Ns)];
        float2 w2 = cmul(w1, w1);
        float2 w3 = cmul(w2, w1);
        float2 a0 = X[t];
        float2 a1 = cmul(X[t + 256], w1);
        float2 a2 = cmul(X[t + 512], w2);
        float2 a3 = cmul(X[t + 768], w3);
        float2 pa = cadd(a0, a2), pb = csub(a0, a2);
        float2 pc = cadd(a1, a3), pd = csub(a1, a3);
        float2 dneg = make_float2(pd.y, -pd.x);
        float2 dpos = make_float2(-pd.y, pd.x);
        int idxD = ((t >> (2*s)) << (2*s + 2)) + p;
        Y[idxD]        = cadd(pa, pc);
        Y[idxD + Ns]   = cadd(pb, dneg);
        Y[idxD + 2*Ns] = csub(pa, pc);
        Y[idxD + 3*Ns] = cadd(pb, dpos);
        __syncthreads();
        float2* tmp = X; X = Y; Y = tmp;
    }
    #pragma unroll
    for (int i = 0; i < 4; i++)
        outr[row*1024 + t + i*256] = X[t + i*256].x;
}

// transpose (2B, NS, DH)complex -> (2B, DH, NS)complex
__global__ void k_transpose_ch(const float2* __restrict__ in, float2* __restrict__ out){
    __shared__ float2 tile[32][33];
    int b = blockIdx.z;
    int c0 = blockIdx.x*32, r0 = blockIdx.y*32;
    const float2* src = in + (size_t)b*NSQ*DH;
    for (int i = threadIdx.y; i < 32; i += 8){
        int d = c0 + threadIdx.x;
        tile[i][threadIdx.x] = (d < DH) ? src[(size_t)(r0+i)*DH + d]
                                        : make_float2(0.f, 0.f);
    }
    __syncthreads();
    float2* dst = out + (size_t)b*DH*NSQ;
    for (int i = threadIdx.y; i < 32; i += 8){
        int d = c0 + i;
        if (d < DH) dst[(size_t)d*NSQ + r0 + threadIdx.x] = tile[threadIdx.x][i];
    }
}
// transpose (2B, DH, NS) -> (2B, NS, DH) compact
__global__ void k_transpose_fh(const float* __restrict__ in, float* __restrict__ out){
    __shared__ float tile[32][33];
    int b = blockIdx.z;
    int d0 = blockIdx.x*32, n0 = blockIdx.y*32;
    const float* src = in + (size_t)b*DH*NSQ;
    for (int i = threadIdx.y; i < 32; i += 8){
        int d = d0 + i;
        tile[i][threadIdx.x] = (d < DH) ? src[(size_t)d*NSQ + n0 + threadIdx.x] : 0.f;
    }
    __syncthreads();
    float* dst = out + (size_t)b*NSQ*DH;
    int d = d0 + threadIdx.x;
    if (d < DH)
        for (int i = threadIdx.y; i < 32; i += 8)
            dst[(size_t)(n0+i)*DH + d] = tile[threadIdx.x][i];
}

// fused Hermitian mirror + euclid_to_lorentz, tf32-rounded outputs
__global__ void k_e2l(const float* __restrict__ rl, float* __restrict__ Ls,
                      float* __restrict__ Lc){
    size_t row = blockIdx.x;                   // 0 .. 2*BB*NSQ-1
    int t = threadIdx.x;                       // 256
    size_t bb = row >> 10;
    int n = (int)(row & 1023);
    float v;
    if (t < DH){
        v = rl[(bb*NSQ + n)*DH + t];
    } else {
        int srcn = (1024 - n) & 1023;
        v = rl[(bb*NSQ + srcn)*DH + (256 - t)];
    }
    float ss = blockReduceSum(v*v);
    float xn = sqrtf(fmaxf(ss, 1e-15f)) + 1e-5f;
    float scl = fminf(1.f, 2.0f / xn);
    v *= scl;
    float vn = sqrtf(fmaxf(ss*scl*scl, 1e-15f));
    float f = sinhf(vn) / vn;
    float* out = (bb < BB) ? Ls : Lc;
    size_t orow = (bb < BB) ? row : row - (size_t)BB*NSQ;
    if (t == 0) out[orow*DPAD] = tf32r(coshf(vn));
    out[orow*DPAD + 1 + t] = tf32r(f * v);
    if (t < DPAD - DP1) out[orow*DPAD + DP1 + t] = 0.f;
}

// --------- pipelined tensor-core GEMM (pre-rounded TF32 operands, no inner cvt) ----
//  MODE: 0 plain, 1 +bias[n], 2 gelu except col0(->0) + fused row/col SSQ atomics
//  ROUND: tf32-round stores
template<int ATRANS, int BTRANS, int MODE, int ROUND>
__global__ void k_pgemm(const float* __restrict__ A, const float* __restrict__ Bm,
                        const float* __restrict__ bias, float* __restrict__ C,
                        int M, int N, int Klen, int lda, int ldb, int ldc,
                        long sA, long sB, long sC,
                        float* __restrict__ rss, float* __restrict__ css)
{
    constexpr int A_ELE = (ATRANS == 0) ? 128*20 : 16*132;
    constexpr int B_ELE = (BTRANS == 1) ? 128*20 : 16*132;
    __shared__ __align__(16) float As[2][A_ELE];
    __shared__ __align__(16) float Bs[2][B_ELE];

    int bz = blockIdx.z;
    A  += (size_t)bz * sA;
    Bm += (size_t)bz * sB;
    C  += (size_t)bz * sC;
    int bm = blockIdx.y * 128, bn = blockIdx.x * 128;
    int tid = threadIdx.x;
    int wid = tid >> 5, lane = tid & 31;
    int wm = (wid >> 2) * 64;
    int wn = (wid & 3) * 32;
    int g = lane >> 2, tg = lane & 3;

    int KT = (Klen + 15) >> 4;

    uint32_t asBase = (uint32_t)__cvta_generic_to_shared(&As[0][0]);
    uint32_t bsBase = (uint32_t)__cvta_generic_to_shared(&Bs[0][0]);

    auto issueA = [&](int st, int k0){
        uint32_t base = asBase + (uint32_t)(st * A_ELE * 4);
        if (ATRANS == 0){
            #pragma unroll
            for (int i = 0; i < 2; i++){
                int idx = tid + i*256;
                int mm = idx >> 2, k4 = idx & 3;
                cpa16(base + (mm*20 + k4*4)*4, A + (size_t)(bm+mm)*lda + k0 + k4*4);
            }
        } else {
            #pragma unroll
            for (int i = 0; i < 2; i++){
                int idx = tid + i*256;
                int kk = idx >> 5, m4 = idx & 31;
                cpa16(base + (kk*132 + m4*4)*4, A + (size_t)(k0+kk)*lda + bm + m4*4);
            }
        }
    };
    auto issueB = [&](int st, int k0){
        uint32_t base = bsBase + (uint32_t)(st * B_ELE * 4);
        if (BTRANS == 1){
            #pragma unroll
            for (int i = 0; i < 2; i++){
                int idx = tid + i*256;
                int nn = idx >> 2, k4 = idx & 3;
                cpa16(base + (nn*20 + k4*4)*4, Bm + (size_t)(bn+nn)*ldb + k0 + k4*4);
            }
        } else {
            #pragma unroll
            for (int i = 0; i < 2; i++){
                int idx = tid + i*256;
                int kk = idx >> 5, n4 = idx & 31;
                cpa16(base + (kk*132 + n4*4)*4, Bm + (size_t)(k0+kk)*ldb + bn + n4*4);
            }
        }
    };
    auto A_at = [&](int st, int m, int k)->uint32_t{
        const uint32_t* p = reinterpret_cast<const uint32_t*>(&As[st][0]);
        return (ATRANS == 0) ? p[m*20 + k] : p[k*132 + m];
    };
    auto B_at = [&](int st, int n, int k)->uint32_t{
        const uint32_t* p = reinterpret_cast<const uint32_t*>(&Bs[st][0]);
        return (BTRANS == 1) ? p[n*20 + k] : p[k*132 + n];
    };

    float acc[4][4][4];
    #pragma unroll
    for (int mi = 0; mi < 4; mi++)
        #pragma unroll
        for (int ni = 0; ni < 4; ni++)
            #pragma unroll
            for (int r = 0; r < 4; r++) acc[mi][ni][r] = 0.f;

    issueA(0, 0); issueB(0, 0);
    CP_COMMIT();

    for (int kt = 0; kt < KT; kt++){
        int st = kt & 1;
        if (kt + 1 < KT){
            issueA(st ^ 1, (kt+1)*16);
            issueB(st ^ 1, (kt+1)*16);
            CP_COMMIT();
            CP_WAIT1();
        } else {
            CP_WAIT0();
        }
        __syncthreads();

        #pragma unroll
        for (int ks = 0; ks < 2; ks++){
            int kk = ks*8;
            uint32_t bhf[4][2];
            #pragma unroll
            for (int ni = 0; ni < 4; ni++){
                int n = wn + ni*8 + g;
                bhf[ni][0] = B_at(st, n, kk+tg);
                bhf[ni][1] = B_at(st, n, kk+tg+4);
            }
            #pragma unroll
            for (int mi = 0; mi < 4; mi++){
                int m = wm + mi*16;
                uint32_t ahf[4];
                ahf[0] = A_at(st, m+g,   kk+tg);
                ahf[1] = A_at(st, m+g+8, kk+tg);
                ahf[2] = A_at(st, m+g,   kk+tg+4);
                ahf[3] = A_at(st, m+g+8, kk+tg+4);
                #pragma unroll
                for (int ni = 0; ni < 4; ni++)
                    mma_tf32(acc[mi][ni], ahf, bhf[ni]);
            }
        }
        __syncthreads();
    }

    // epilogue value transform
    #pragma unroll
    for (int mi = 0; mi < 4; mi++)
        #pragma unroll
        for (int ni = 0; ni < 4; ni++){
            int col = bn + wn + ni*8 + 2*tg;
            #pragma unroll
            for (int r = 0; r < 4; r++){
                int gn = col + (r & 1);
                float v = acc[mi][ni][r];
                if (MODE == 1 && gn < N) v += bias[gn];
                if (MODE == 2) v = (gn == 0) ? 0.f : gelu_exact(v);
                if (ROUND) v = tf32r(v);
                acc[mi][ni][r] = v;
            }
        }
    // store
    #pragma unroll
    for (int mi = 0; mi < 4; mi++)
        #pragma unroll
        for (int ni = 0; ni < 4; ni++){
            int col = bn + wn + ni*8 + 2*tg;
            #pragma unroll
            for (int r = 0; r < 4; r++){
                int gm = bm + wm + mi*16 + g + (r >= 2 ? 8 : 0);
                int gn = col + (r & 1);
                if (gn >= N) continue;
                C[(size_t)gm*ldc + gn] = acc[mi][ni][r];
            }
        }
    if (MODE == 2){
        #pragma unroll
        for (int mi = 0; mi < 4; mi++){
            #pragma unroll
            for (int half = 0; half < 2; half++){
                float rp = 0.f;
                #pragma unroll
                for (int ni = 0; ni < 4; ni++){
                    float a0 = acc[mi][ni][half*2], a1 = acc[mi][ni][half*2+1];
                    rp += a0*a0 + a1*a1;
                }
                rp += __shfl_down_sync(0xffffffffu, rp, 1);
                rp += __shfl_down_sync(0xffffffffu, rp, 2);
                if (tg == 0)
                    atomicAdd(&rss[(size_t)bz*1024 + bm + wm + mi*16 + g + half*8], rp);
            }
        }
        #pragma unroll
        for (int ni = 0; ni < 4; ni++){
            #pragma unroll
            for (int cb = 0; cb < 2; cb++){
                float cp = 0.f;
                #pragma unroll
                for (int mi = 0; mi < 4; mi++){
                    float a0 = acc[mi][ni][cb], a1 = acc[mi][ni][2+cb];
                    cp += a0*a0 + a1*a1;
                }
                cp += __shfl_down_sync(0xffffffffu, cp, 4);
                cp += __shfl_down_sync(0xffffffffu, cp, 8);
                cp += __shfl_down_sync(0xffffffffu, cp, 16);
                if (g == 0)
                    atomicAdd(&css[(size_t)bz*1024 + bn + wn + ni*8 + 2*tg + cb], cp);
            }
        }
    }
}

// ----------------------------- row-wise kernels ------------------------------------
__global__ void k_fix_time(float* __restrict__ Y){        // DPAD stride, rounded
    size_t row = blockIdx.x;
    int t = threadIdx.x;                                  // 256
    float sp = Y[row*DPAD + 1 + t];
    float S = blockReduceSum(sp*sp);
    if (t == 0) Y[row*DPAD] = tf32r(sqrtf(S + 1.f));
}
// warp-per-row poincare: 129 -> 128, rounded
__global__ void k_poincare(const float* __restrict__ Y, float* __restrict__ out){
    size_t row = (size_t)blockIdx.x*8 + (threadIdx.x >> 5);
    int lane = threadIdx.x & 31;
    const float* y = Y + row*KP1 + 1;
    float v[4], s = 0.f;
    #pragma unroll
    for (int i = 0; i < 4; i++){ v[i] = y[lane + i*32]; s += v[i]*v[i]; }
    s = wsum(s);
    float inv = 1.f / (sqrtf(s + 1.f) + 1.f);
    float* o = out + row*KKW;
    #pragma unroll
    for (int i = 0; i < 4; i++) o[lane + i*32] = tf32r(v[i] * inv);
}
// finalize norms from fused SSQ; round Lb time col
__global__ void k_nfin(const float* __restrict__ rss, const float* __restrict__ css,
                       float* __restrict__ Lb, float* __restrict__ xnr,
                       float* __restrict__ xnc){
    int b = blockIdx.x, n = threadIdx.x;                  // 1024
    float S = rss[b*1024 + n];
    Lb[((size_t)b*1024 + n)*1024] = tf32r(sqrtf(S + 1.f));
    xnr[b*1024 + n] = sqrtf(fmaxf(2.f*S + 1.f, 1e-15f));
    float ts = blockReduceSum(S + 1.f);
    float c = css[b*1024 + n];
    xnc[b*1024 + n] = (n == 0) ? sqrtf(ts) : sqrtf(fmaxf(c, 1e-15f));
}
// mobius_matvec scale from MxcT (coalesced column loop)
__global__ void k_mscale(const float* __restrict__ MxT, const float* __restrict__ xna,
                         float* __restrict__ sc){
    int b = blockIdx.y;
    int m = blockIdx.x*256 + threadIdx.x;
    const float* base = MxT + (size_t)b*KKW*NCQ + m;
    float ss = 0.f;
    #pragma unroll 4
    for (int j = 0; j < KKW; j++){
        float v = base[(size_t)j*NCQ];
        ss += v*v;
    }
    float mxn = sqrtf(fmaxf(ss, 1e-15f));
    float xn = xna[b*NCQ + m];
    sc[b*NCQ + m] = tanhf(mxn / xn * atanhc(xn)) / mxn;
}
// warp-per-row fused Hs pipeline
__global__ void k_hs(const float* __restrict__ Hsa, const float* __restrict__ MxRaw,
                     const float* __restrict__ xnr,
                     const float* __restrict__ whs, float* __restrict__ lg){
    size_t row = (size_t)blockIdx.x*8 + (threadIdx.x >> 5);
    int lane = threadIdx.x & 31;
    const float* my = MxRaw + row*KKW;
    const float* hx = Hsa + row*KKW;
    float yr[4], x[4];
    float mm = 0.f;
    #pragma unroll
    for (int i = 0; i < 4; i++){
        yr[i] = my[lane + i*32];
        x[i]  = hx[lane + i*32];
        mm += yr[i]*yr[i];
    }
    mm = wsum(mm);
    float mxn = sqrtf(fmaxf(mm, 1e-15f));
    float xnb = xnr[row];
    float fac = tanhf(mxn / xnb * atanhc(xnb)) / mxn;

    float xy = 0.f, x2 = 0.f, y2 = 0.f;
    float y[4];
    #pragma unroll
    for (int i = 0; i < 4; i++){
        y[i] = yr[i] * fac;
        xy += x[i]*y[i]; x2 += x[i]*x[i]; y2 += y[i]*y[i];
    }
    xy = wsum(xy); x2 = wsum(x2); y2 = wsum(y2);
    float den = fmaxf(1.f + 2.f*xy + x2*y2, 1e-15f);
    float c1 = (1.f + 2.f*xy + y2) / den, c2 = (1.f - x2) / den;
    float h[4], hh = 0.f;
    #pragma unroll
    for (int i = 0; i < 4; i++){ h[i] = c1*x[i] + c2*y[i]; hh += h[i]*h[i]; }
    hh = wsum(hh);
    float hn = sqrtf(fmaxf(hh, 1e-15f));
    float fa = atanhc(hn) / hn;
    float gv[4], gg = 0.f;
    #pragma unroll
    for (int i = 0; i < 4; i++){ gv[i] = gelu_exact(fa*h[i]); gg += gv[i]*gv[i]; }
    gg = wsum(gg);
    float gn = sqrtf(fmaxf(gg, 1e-15f));
    float fb = tanhf(gn) / gn;
    float mx = 0.f, xn2 = 0.f;
    #pragma unroll
    for (int i = 0; i < 4; i++){
        float hs = fb * gv[i];
        mx += hs * __ldg(&whs[lane + i*32]);
        xn2 += hs*hs;
    }
    mx = wsum(mx); xn2 = wsum(xn2);
    if (lane == 0){
        float xn = sqrtf(fmaxf(xn2, 1e-15f));
        float mxn2 = sqrtf(fmaxf(mx*mx, 1e-15f));
        lg[row] = tanhf(mxn2 / xn * atanhc(xn)) * mx / mxn2;
    }
}
// transpose (b, 1024, 128) -> (b, 128, 1024)
__global__ void k_tbk(const float* __restrict__ in, float* __restrict__ out){
    __shared__ float tile[32][33];
    int b = blockIdx.z;
    int j0 = blockIdx.x*32, m0 = blockIdx.y*32;
    const float* src = in + (size_t)b*NCQ*KKW;
    for (int i = threadIdx.y; i < 32; i += 8)
        tile[i][threadIdx.x] = src[(size_t)(m0+i)*KKW + j0 + threadIdx.x];
    __syncthreads();
    float* dst = out + (size_t)b*KKW*NCQ;
    for (int i = threadIdx.y; i < 32; i += 8)
        dst[(size_t)(j0+i)*NCQ + m0 + threadIdx.x] = tile[threadIdx.x][i];
}
// Hc pipeline on transposed inputs, fused Ac-logit accumulation (atomics)
__global__ void k_hc(const float* __restrict__ HcaT, const float* __restrict__ MxcT,
                     const float* __restrict__ sc, const float* __restrict__ whc,
                     float* __restrict__ amx, float* __restrict__ ass){
    int bj = blockIdx.x;
    int b = bj >> 7, j = bj & 127;
    int t = threadIdx.x;                                  // 256
    float wj = __ldg(&whc[j]);
    const float* xrow = HcaT + ((size_t)(b*KKW + j))*NCQ;
    const float* yrow = MxcT + ((size_t)(b*KKW + j))*NCQ;
    const float* srow = sc + (size_t)b*NCQ;
    float x[4], y[4];
    #pragma unroll
    for (int i = 0; i < 4; i++){
        int m = t + i*256;
        x[i] = xrow[m]; y[i] = yrow[m] * srow[m];
    }
    float sxy = 0.f, sx2 = 0.f, sy2 = 0.f;
    #pragma unroll
    for (int i = 0; i < 4; i++){ sxy += x[i]*y[i]; sx2 += x[i]*x[i]; sy2 += y[i]*y[i]; }
    blockReduceSum3(sxy, sx2, sy2);
    float xy = sxy, x2 = sx2, y2 = sy2;
    float den = fmaxf(1.f + 2.f*xy + x2*y2, 1e-15f);
    float c1 = 1.f + 2.f*xy + y2, c2 = 1.f - x2;
    float h[4], hh = 0.f;
    #pragma unroll
    for (int i = 0; i < 4; i++){ h[i] = (c1*x[i] + c2*y[i]) / den; hh += h[i]*h[i]; }
    float hn = sqrtf(fmaxf(blockReduceSum(hh), 1e-15f));
    float fa = atanhc(hn) / hn;
    float g[4], gg = 0.f;
    #pragma unroll
    for (int i = 0; i < 4; i++){ g[i] = gelu_exact(fa*h[i]); gg += g[i]*g[i]; }
    float gn = sqrtf(fmaxf(blockReduceSum(gg), 1e-15f));
    float fb = tanhf(gn) / gn;
    #pragma unroll
    for (int i = 0; i < 4; i++){
        int m = t + i*256;
        float hc = fb * g[i];
        atomicAdd(&amx[b*NCQ + m], hc * wj);
        atomicAdd(&ass[b*NCQ + m], hc * hc);
    }
}
__global__ void k_acfin(const float* __restrict__ amx, const float* __restrict__ ass,
                        float* __restrict__ lg){
    int b = blockIdx.x, m = threadIdx.x;                  // 1024
    float mx = amx[b*NCQ + m];
    float ss = ass[b*NCQ + m];
    float xn = sqrtf(fmaxf(ss, 1e-15f));
    float mxn = sqrtf(fmaxf(mx*mx, 1e-15f));
    lg[b*NCQ + m] = tanhf(mxn / xn * atanhc(xn)) * mx / mxn;
}
__global__ void k_softmax(const float* __restrict__ lg, float* __restrict__ out){
    int b = blockIdx.x, t = threadIdx.x;                  // 256
    float l[4];
    float lm = -3.4e38f;
    #pragma unroll
    for (int i = 0; i < 4; i++){ l[i] = lg[b*1024 + t + i*256]; lm = fmaxf(lm, l[i]); }
    float M = blockReduceMax(lm);
    float es = 0.f, e[4];
    #pragma unroll
    for (int i = 0; i < 4; i++){ e[i] = expf(l[i] - M); es += e[i]; }
    float S = blockReduceSum(es);
    #pragma unroll
    for (int i = 0; i < 4; i++) out[b*1024 + t + i*256] = e[i] / S;
}
__global__ void k_centroid_part(const float* __restrict__ Lx, const float* __restrict__ w,
                                float* __restrict__ part){
    __shared__ float wsh[128];
    int ch = blockIdx.x, b = blockIdx.y;
    int t = threadIdx.x;                                  // 288, t<257 active
    for (int i = t; i < 128; i += blockDim.x) wsh[i] = w[(size_t)b*NSQ + ch*128 + i];
    __syncthreads();
    if (t < DP1){
        const float* base = Lx + ((size_t)b*NSQ + (size_t)ch*128)*DPAD + t;
        float acc = 0.f;
        for (int n = 0; n < 128; n++) acc += wsh[n] * base[(size_t)n*DPAD];
        part[(b*8 + ch)*DP1 + t] = acc;
    }
}
__global__ void k_centroid_fin(const float* __restrict__ part, float* __restrict__ co){
    __shared__ float t0sh;
    int b = blockIdx.x, t = threadIdx.x;                  // 288
    float acc = 0.f;
    if (t < DP1){
        #pragma unroll
        for (int c = 0; c < 8; c++) acc += part[(b*8 + c)*DP1 + t];
    }
    float sp = (t >= 1 && t < DP1) ? acc*acc : 0.f;
    float ssp = blockReduceSum(sp);
    if (t == 0) t0sh = acc;
    __syncthreads();
    float inner = -t0sh*t0sh + ssp;
    float den = sqrtf(fmaxf(fabsf(inner), 1e-8f));
    if (t < DP1) co[(size_t)b*DP1 + t] = acc / den;
}
__global__ void k_concat(const float* __restrict__ cs, const float* __restrict__ cc,
                         float* __restrict__ out){
    int b = blockIdx.x, t = threadIdx.x;                  // 256
    float t0s = cs[(size_t)b*DP1];
    float t0c = cc[(size_t)b*DP1];
    float sps = cs[(size_t)b*DP1 + 1 + t];
    float spc = cc[(size_t)b*DP1 + 1 + t];
    float ns  = sqrtf(fmaxf(blockReduceSum(sps*sps), 1e-15f));
    float ncv = sqrtf(fmaxf(blockReduceSum(spc*spc), 1e-15f));
    float zs = acoshf(fmaxf(t0s, 1.f + 1e-7f)) * sps / ns;
    float zc = acoshf(fmaxf(t0c, 1.f + 1e-7f)) * spc / ncv;
    float vn = sqrtf(fmaxf(blockReduceSum(zs*zs + zc*zc), 1e-15f));
    float f = sinhf(vn) / vn;
    float* o = out + (size_t)b*513;
    if (t == 0) o[0] = coshf(vn);
    o[1 + t]       = f * zs;
    o[1 + DD + t]  = f * zc;
}

// ----------------------------- launch ----------------------------------------------
extern "C" void kernel_launch(void* const* d_in, const int* in_sizes, int n_in,
                              void* d_out, int out_size)
{
    const float* sent = (const float*)d_in[0];
    const float* comm = (const float*)d_in[1];
    const float* WlW  = (const float*)d_in[2];
    const float* Wlb  = (const float*)d_in[3];
    const float* WcW  = (const float*)d_in[4];
    const float* Wcb  = (const float*)d_in[5];
    const float* WsW  = (const float*)d_in[6];
    const float* Wsb  = (const float*)d_in[7];
    const float* whs  = (const float*)d_in[8];
    const float* whc  = (const float*)d_in[9];
    float* out = (float*)d_out;
    (void)in_sizes; (void)n_in; (void)out_size;

    float2 *c1, *c1T;
    float *sT, *rl, *Ls, *Lc, *Llin, *Yt, *Lb, *Wt, *rss, *css, *amx, *ass, *xnr, *xnc,
          *msc, *Hsa, *Hca, *HcaT, *Mxs, *MxcT, *lgs, *lgc, *cs, *cc, *part;
    cudaGetSymbolAddress((void**)&c1,  g_c1);
    cudaGetSymbolAddress((void**)&c1T, g_c1T);
    cudaGetSymbolAddress((void**)&sT,  g_sT);
    cudaGetSymbolAddress((void**)&rl,  g_real);
    cudaGetSymbolAddress((void**)&Ls,  g_Ls);
    cudaGetSymbolAddress((void**)&Lc,  g_Lc);
    cudaGetSymbolAddress((void**)&Llin,g_Llin);
    cudaGetSymbolAddress((void**)&Yt,  g_Yt);
    cudaGetSymbolAddress((void**)&Lb,  g_Lb);
    cudaGetSymbolAddress((void**)&Wt,  g_Wt);
    cudaGetSymbolAddress((void**)&rss, g_rss);
    cudaGetSymbolAddress((void**)&css, g_css);
    cudaGetSymbolAddress((void**)&amx, g_amx);
    cudaGetSymbolAddress((void**)&ass, g_ass);
    cudaGetSymbolAddress((void**)&xnr, g_xnr);
    cudaGetSymbolAddress((void**)&xnc, g_xnc);
    cudaGetSymbolAddress((void**)&msc, g_msc);
    cudaGetSymbolAddress((void**)&Hsa, g_Hsa);
    cudaGetSymbolAddress((void**)&Hca, g_Hca);
    cudaGetSymbolAddress((void**)&HcaT,g_HcaT);
    cudaGetSymbolAddress((void**)&Mxs, g_Mxs);
    cudaGetSymbolAddress((void**)&MxcT,g_MxcT);
    cudaGetSymbolAddress((void**)&lgs, g_lgs);
    cudaGetSymbolAddress((void**)&lgc, g_lgc);
    cudaGetSymbolAddress((void**)&cs,  g_cs);
    cudaGetSymbolAddress((void**)&cc,  g_cc);
    cudaGetSymbolAddress((void**)&part,g_part);

    const int AS_OFF = BB*513;             // 16416
    const int AC_OFF = AS_OFF + BB*NSQ;    // 49184

    k_twfill<<<1, 1024>>>();
    k_zero<<<32, 1024>>>(rss, css, amx, ass);
    k_wprep<<<DP1 + 2*KP1, 288>>>(WlW, WsW, WcW, Wt);

    // ---- dual-branch FFT2 (Hermitian-compact) + fused mirror + euclid_to_lorentz ----
    k_fft256<<<2*BB*NSQ/4, dim3(64,4)>>>(sent, comm, c1);
    k_transpose_ch<<<dim3(5, NSQ/32, 2*BB), dim3(32,8)>>>(c1, c1T);
    k_fft1024<<<2*BB*DH, 256>>>(c1T, sT);
    k_transpose_fh<<<dim3(5, NSQ/32, 2*BB), dim3(32,8)>>>(sT, rl);
    k_e2l<<<2*BB*NSQ, 256>>>(rl, Ls, Lc);

    // ---- linear layers ----
    k_pgemm<0,1,1,1><<<dim3(3,256,1),256>>>(Lc, Wt, Wlb, Llin,
        BB*NCQ, DP1, DP1, DPAD, DPAD, DPAD, 0, 0, 0, nullptr, nullptr);
    k_fix_time<<<BB*NCQ, 256>>>(Llin);

    k_pgemm<0,1,1,0><<<dim3(2,256,1),256>>>(Ls, Wt + (size_t)384*DPAD, Wsb, Yt,
        BB*NSQ, KP1, DP1, DPAD, DPAD, KP1, 0, 0, 0, nullptr, nullptr);
    k_poincare<<<BB*NSQ/8, 256>>>(Yt, Hsa);

    k_pgemm<0,1,1,0><<<dim3(2,256,1),256>>>(Lc, Wt + (size_t)640*DPAD, Wcb, Yt,
        BB*NCQ, KP1, DP1, DPAD, DPAD, KP1, 0, 0, 0, nullptr, nullptr);
    k_poincare<<<BB*NCQ/8, 256>>>(Yt, Hca);

    // ---- big einsum + lorentz_act + fused norms (rounded stores) ----
    k_pgemm<0,1,2,1><<<dim3(8,8,BB),256>>>(Ls, Llin, nullptr, Lb,
        NSQ, NCQ, DP1, DPAD, DPAD, NCQ,
        (long)NSQ*DPAD, (long)NCQ*DPAD, (long)NSQ*NCQ, rss, css);
    k_nfin<<<BB, 1024>>>(rss, css, Lb, xnr, xnc);

    // ---- mobius_matvec GEMMs (Mxc produced transposed: MxcT = Hsa^T * Lb) ----
    k_pgemm<0,0,0,0><<<dim3(1,8,BB),256>>>(Lb, Hca, nullptr, Mxs,
        NSQ, KKW, NCQ, NCQ, KKW, KKW,
        (long)NSQ*NCQ, (long)NCQ*KKW, (long)NSQ*KKW, nullptr, nullptr);
    k_pgemm<1,0,0,0><<<dim3(8,1,BB),256>>>(Hsa, Lb, nullptr, MxcT,
        KKW, NCQ, NSQ, KKW, NCQ, NCQ,
        (long)NSQ*KKW, (long)NSQ*NCQ, (long)KKW*NCQ, nullptr, nullptr);
    k_tbk<<<dim3(4, 32, BB), dim3(32,8)>>>(Hca, HcaT);
    k_mscale<<<dim3(NCQ/256, BB), 256>>>(MxcT, xnc, msc);

    // ---- mobius_add + gelu pipelines + attention logits ----
    k_hs<<<BB*NSQ/8, 256>>>(Hsa, Mxs, xnr, whs, lgs);
    k_hc<<<BB*KKW, 256>>>(HcaT, MxcT, msc, whc, amx, ass);
    k_acfin<<<BB, 1024>>>(amx, ass, lgc);

    // ---- softmaxes straight into output ----
    k_softmax<<<BB, 256>>>(lgs, out + AS_OFF);
    k_softmax<<<BB, 256>>>(lgc, out + AC_OFF);

    // ---- centroids + concat ----
    k_centroid_part<<<dim3(8,BB), 288>>>(Ls, out + AS_OFF, part);
    k_centroid_fin<<<BB, 288>>>(part, cs);
    k_centroid_part<<<dim3(8,BB), 288>>>(Lc, out + AC_OFF, part);
    k_centroid_fin<<<BB, 288>>>(part, cc);
    k_concat<<<BB, 256>>>(cs, cc, out);
}

// round 9
// speedup vs baseline: 3.0865x; 1.0857x over previous
#include <cuda_runtime.h>
#include <math.h>
#include <stdint.h>

#define BB  32
#define NSQ 1024
#define NCQ 1024
#define DD  256
#define DP1 257
#define DPAD 272
#define KKW 128
#define KP1 129
#define DH  129   // Hermitian-reduced column count

// ----------------------------- scratch (static device globals; no runtime alloc) ---
static __device__ float2 g_c1 [(size_t)2*BB*NSQ*DH];
static __device__ float2 g_c1T[(size_t)2*BB*DH*NSQ];
static __device__ float  g_sT [(size_t)2*BB*DH*NSQ];
static __device__ float  g_real[(size_t)2*BB*NSQ*DH];
static __device__ float  g_Ls [(size_t)BB*NSQ*DPAD];
static __device__ float  g_Lc [(size_t)BB*NCQ*DPAD];
static __device__ float  g_Llin[(size_t)BB*NCQ*DPAD];
static __device__ float  g_Yt [(size_t)BB*NSQ*KKW];
static __device__ float  g_Lb [(size_t)BB*NSQ*NCQ];
static __device__ float  g_Wt [(size_t)896*DPAD];     // Wl@0, Ws@384*DPAD, Wc@640*DPAD
static __device__ float  g_rss[BB*NSQ];
static __device__ float  g_css[BB*NCQ];
static __device__ float  g_amx[BB*NCQ];
static __device__ float  g_ass[BB*NCQ];
static __device__ float  g_xnr[BB*NSQ];
static __device__ float  g_xnc[BB*NCQ];
static __device__ float  g_msc[BB*NCQ];
static __device__ float  g_Hsa[(size_t)BB*NSQ*KKW];
static __device__ float  g_Hca[(size_t)BB*NCQ*KKW];
static __device__ float  g_HcaT[(size_t)BB*KKW*NCQ];
static __device__ float  g_Mxs[(size_t)BB*NSQ*KKW];
static __device__ float  g_MxcT[(size_t)BB*KKW*NCQ];
static __device__ float  g_lgs[BB*NSQ];
static __device__ float  g_lgc[BB*NCQ];
static __device__ float  g_cs [BB*DP1];
static __device__ float  g_cc [BB*DP1];
static __device__ float  g_part[BB*8*DP1];
static __device__ float2 g_tw1024[1024];
static __device__ float2 g_tw256[256];

// ----------------------------- helpers ---------------------------------------------
__device__ __forceinline__ float atanhc(float x){
    x = fminf(fmaxf(x, -1.f + 1e-5f), 1.f - 1e-5f);
    return 0.5f * (log1pf(x) - log1pf(-x));
}
__device__ __forceinline__ float gelu_exact(float v){
    return 0.5f * v * (1.f + erff(v * 0.70710678118654752f));
}
__device__ __forceinline__ float2 cmul(float2 a, float2 b){
    return make_float2(a.x*b.x - a.y*b.y, a.x*b.y + a.y*b.x);
}
__device__ __forceinline__ float2 cadd(float2 a, float2 b){ return make_float2(a.x+b.x, a.y+b.y); }
__device__ __forceinline__ float2 csub(float2 a, float2 b){ return make_float2(a.x-b.x, a.y-b.y); }

__device__ __forceinline__ float wsum(float v){
    #pragma unroll
    for (int o = 16; o; o >>= 1) v += __shfl_xor_sync(0xffffffffu, v, o);
    return v;
}
__device__ __forceinline__ float blockReduceSum(float v){
    __shared__ float sh[32];
    #pragma unroll
    for (int o = 16; o; o >>= 1) v += __shfl_down_sync(0xffffffffu, v, o);
    int lane = threadIdx.x & 31, w = threadIdx.x >> 5;
    if (lane == 0) sh[w] = v;
    __syncthreads();
    int nw = (blockDim.x + 31) >> 5;
    v = (threadIdx.x < (unsigned)nw) ? sh[threadIdx.x] : 0.f;
    if (w == 0){
        #pragma unroll
        for (int o = 16; o; o >>= 1) v += __shfl_down_sync(0xffffffffu, v, o);
        if (lane == 0) sh[0] = v;
    }
    __syncthreads();
    float r = sh[0];
    __syncthreads();
    return r;
}
__device__ __forceinline__ void blockReduceSum3(float& a, float& b, float& c){
    __shared__ float sh3[32][3];
    #pragma unroll
    for (int o = 16; o; o >>= 1){
        a += __shfl_down_sync(0xffffffffu, a, o);
        b += __shfl_down_sync(0xffffffffu, b, o);
        c += __shfl_down_sync(0xffffffffu, c, o);
    }
    int lane = threadIdx.x & 31, w = threadIdx.x >> 5;
    if (lane == 0){ sh3[w][0] = a; sh3[w][1] = b; sh3[w][2] = c; }
    __syncthreads();
    int nw = (blockDim.x + 31) >> 5;
    a = (threadIdx.x < (unsigned)nw) ? sh3[threadIdx.x][0] : 0.f;
    b = (threadIdx.x < (unsigned)nw) ? sh3[threadIdx.x][1] : 0.f;
    c = (threadIdx.x < (unsigned)nw) ? sh3[threadIdx.x][2] : 0.f;
    if (w == 0){
        #pragma unroll
        for (int o = 16; o; o >>= 1){
            a += __shfl_down_sync(0xffffffffu, a, o);
            b += __shfl_down_sync(0xffffffffu, b, o);
            c += __shfl_down_sync(0xffffffffu, c, o);
        }
        if (lane == 0){ sh3[0][0] = a; sh3[0][1] = b; sh3[0][2] = c; }
    }
    __syncthreads();
    a = sh3[0][0]; b = sh3[0][1]; c = sh3[0][2];
    __syncthreads();
}
__device__ __forceinline__ float blockReduceMax(float v){
    __shared__ float sh[32];
    #pragma unroll
    for (int o = 16; o; o >>= 1) v = fmaxf(v, __shfl_down_sync(0xffffffffu, v, o));
    int lane = threadIdx.x & 31, w = threadIdx.x >> 5;
    if (lane == 0) sh[w] = v;
    __syncthreads();
    int nw = (blockDim.x + 31) >> 5;
    v = (threadIdx.x < (unsigned)nw) ? sh[threadIdx.x] : -3.4e38f;
    if (w == 0){
        #pragma unroll
        for (int o = 16; o; o >>= 1) v = fmaxf(v, __shfl_down_sync(0xffffffffu, v, o));
        if (lane == 0) sh[0] = v;
    }
    __syncthreads();
    float r = sh[0];
    __syncthreads();
    return r;
}
__device__ __forceinline__ uint32_t f2tf32(float v){
    uint32_t r;
    asm("cvt.rna.tf32.f32 %0, %1;" : "=r"(r) : "f"(v));
    return r;
}
__device__ __forceinline__ float tf32r(float v){ return __uint_as_float(f2tf32(v)); }
__device__ __forceinline__ void mma_tf32(float* c, const uint32_t* a, const uint32_t* b){
    asm volatile("mma.sync.aligned.m16n8k8.row.col.f32.tf32.tf32.f32 "
        "{%0,%1,%2,%3}, {%4,%5,%6,%7}, {%8,%9}, {%0,%1,%2,%3};"
        : "+f"(c[0]), "+f"(c[1]), "+f"(c[2]), "+f"(c[3])
        : "r"(a[0]), "r"(a[1]), "r"(a[2]), "r"(a[3]), "r"(b[0]), "r"(b[1]));
}
__device__ __forceinline__ void cpa16(uint32_t dsh, const void* src){
    asm volatile("cp.async.ca.shared.global [%0], [%1], 16;" :: "r"(dsh), "l"(src));
}
#define CP_COMMIT() asm volatile("cp.async.commit_group;" ::: "memory")
#define CP_WAIT1()  asm volatile("cp.async.wait_group 1;" ::: "memory")
#define CP_WAIT0()  asm volatile("cp.async.wait_group 0;" ::: "memory")

// ----------------------------- merged setup kernel ---------------------------------
// blocks 0..31: zero accumulators (+block 0 also fills twiddles)
// blocks 32..546: pre-rounded padded weight copies
__global__ void k_setup(const float* __restrict__ Wl, const float* __restrict__ Ws,
                        const float* __restrict__ Wc, float* __restrict__ Wt,
                        float* __restrict__ a, float* __restrict__ b,
                        float* __restrict__ c, float* __restrict__ d){
    int blk = blockIdx.x;
    int t = threadIdx.x;                       // 1024
    if (blk < 32){
        int i = blk*1024 + t;
        a[i] = 0.f; b[i] = 0.f; c[i] = 0.f; d[i] = 0.f;
        if (blk == 0){
            double ang = -6.283185307179586476925287 * (double)t / 1024.0;
            g_tw1024[t] = make_float2((float)cos(ang), (float)sin(ang));
            if (t < 256){
                double a2 = -6.283185307179586476925287 * (double)t / 256.0;
                g_tw256[t] = make_float2((float)cos(a2), (float)sin(a2));
            }
        }
        return;
    }
    int r = blk - 32;                          // 0..514
    if (t >= DP1) return;
    const float* src; float* dst;
    if (r < DP1){ src = Wl + (size_t)r*DP1; dst = Wt + (size_t)r*DPAD; }
    else if (r < DP1 + KP1){ int rr = r - DP1; src = Ws + (size_t)rr*DP1; dst = Wt + (size_t)(384+rr)*DPAD; }
    else { int rr = r - DP1 - KP1; src = Wc + (size_t)rr*DP1; dst = Wt + (size_t)(640+rr)*DPAD; }
    dst[t] = tf32r(src[t]);
}

// ----------------------------- radix-4 Stockham FFT kernels ------------------------
// dual-branch; stage 0 fused into load (twiddle-free); compact Hermitian output
__global__ void k_fft256(const float* __restrict__ sent, const float* __restrict__ comm,
                         float2* __restrict__ out){
    __shared__ float2 bufA[4][256];
    __shared__ float2 bufB[4][256];
    __shared__ float2 tws[256];
    __shared__ float  rsum[4][2];
    int tx = threadIdx.x;                      // 64
    int ty = threadIdx.y;                      // 4
    int tid = ty*64 + tx;
    size_t row = (size_t)blockIdx.x*4 + ty;
    bool do_log = row >= (size_t)BB*NSQ;
    const float* x = do_log ? (comm + (row - (size_t)BB*NSQ)*256) : (sent + row*256);
    tws[tid] = g_tw256[tid];

    float v0 = x[tx], v1 = x[tx+64], v2 = x[tx+128], v3 = x[tx+192];
    float ss = v0*v0 + v1*v1 + v2*v2 + v3*v3;
    #pragma unroll
    for (int o = 16; o; o >>= 1) ss += __shfl_down_sync(0xffffffffu, ss, o);
    if ((tx & 31) == 0) rsum[ty][tx >> 5] = ss;
    __syncthreads();
    if (do_log){
        float tot = rsum[ty][0] + rsum[ty][1];
        float yn = sqrtf(fmaxf(tot, 1e-15f));
        float f = atanhc(yn) / yn;
        v0 *= f; v1 *= f; v2 *= f; v3 *= f;
    }
    // stage 0 in registers (inputs real, twiddles = 1)
    {
        float pa = v0 + v2, pb = v0 - v2;
        float pc = v1 + v3, pd = v1 - v3;
        bufA[ty][4*tx]     = make_float2(pa + pc, 0.f);
        bufA[ty][4*tx + 1] = make_float2(pb, -pd);
        bufA[ty][4*tx + 2] = make_float2(pa - pc, 0.f);
        bufA[ty][4*tx + 3] = make_float2(pb,  pd);
    }
    __syncthreads();

    float2* X = &bufA[ty][0];
    float2* Y = &bufB[ty][0];
    #pragma unroll
    for (int s = 1; s < 4; s++){
        int Ns = 1 << (2*s);
        int p = tx & (Ns - 1);
        float2 w1 = tws[p * (64/Ns)];
        float2 w2 = cmul(w1, w1);
        float2 w3 = cmul(w2, w1);
        float2 a0 = X[tx];
        float2 a1 = cmul(X[tx + 64],  w1);
        float2 a2 = cmul(X[tx + 128], w2);
        float2 a3 = cmul(X[tx + 192], w3);
        float2 pa = cadd(a0, a2), pb = csub(a0, a2);
        float2 pc = cadd(a1, a3), pd = csub(a1, a3);
        float2 dneg = make_float2(pd.y, -pd.x);
        float2 dpos = make_float2(-pd.y, pd.x);
        int idxD = ((tx >> (2*s)) << (2*s + 2)) + p;
        Y[idxD]          = cadd(pa, pc);
        Y[idxD + Ns]     = cadd(pb, dneg);
        Y[idxD + 2*Ns]   = csub(pa, pc);
        Y[idxD + 3*Ns]   = cadd(pb, dpos);
        __syncthreads();
        float2* tmp = X; X = Y; Y = tmp;
    }
    out[row*DH + tx]      = X[tx];
    out[row*DH + tx + 64] = X[tx + 64];
    if (tx == 0) out[row*DH + 128] = X[128];
}

__global__ void k_fft1024(const float2* __restrict__ in, float* __restrict__ outr){
    __shared__ float2 bufA[1024];
    __shared__ float2 bufB[1024];
    __shared__ float2 tws[1024];
    int t = threadIdx.x;                       // 256
    size_t row = blockIdx.x;
    const float2* src = in + row*1024;
    float2 a0 = src[t], a1 = src[t+256], a2 = src[t+512], a3 = src[t+768];
    #pragma unroll
    for (int i = 0; i < 4; i++)
        tws[t + i*256] = g_tw1024[t + i*256];
    // stage 0 in registers (twiddles = 1)
    {
        float2 pa = cadd(a0, a2), pb = csub(a0, a2);
        float2 pc = cadd(a1, a3), pd = csub(a1, a3);
        bufA[4*t]     = cadd(pa, pc);
        bufA[4*t + 1] = cadd(pb, make_float2(pd.y, -pd.x));
        bufA[4*t + 2] = csub(pa, pc);
        bufA[4*t + 3] = cadd(pb, make_float2(-pd.y, pd.x));
    }
    __syncthreads();
    float2* X = bufA;
    float2* Y = bufB;
    #pragma unroll
    for (int s = 1; s < 5; s++){
        int Ns = 1 << (2*s);
        int p = t & (Ns - 1);
        float2 w1 = tws[p * (256/Ns)];
        float2 w2 = cmul(w1, w1);
        float2 w3 = cmul(w2, w1);
        float2 b0 = X[t];
        float2 b1 = cmul(X[t + 256], w1);
        float2 b2 = cmul(X[t + 512], w2);
        float2 b3 = cmul(X[t + 768], w3);
        float2 pa = cadd(b0, b2), pb = csub(b0, b2);
        float2 pc = cadd(b1, b3), pd = csub(b1, b3);
        float2 dneg = make_float2(pd.y, -pd.x);
        float2 dpos = make_float2(-pd.y, pd.x);
        int idxD = ((t >> (2*s)) << (2*s + 2)) + p;
        Y[idxD]        = cadd(pa, pc);
        Y[idxD + Ns]   = cadd(pb, dneg);
        Y[idxD + 2*Ns] = csub(pa, pc);
        Y[idxD + 3*Ns] = cadd(pb, dpos);
        __syncthreads();
        float2* tmp = X; X = Y; Y = tmp;
    }
    #pragma unroll
    for (int i = 0; i < 4; i++)
        outr[row*1024 + t + i*256] = X[t + i*256].x;
}

// transpose (2B, NS, DH)complex -> (2B, DH, NS)complex
__global__ void k_transpose_ch(const float2* __restrict__ in, float2* __restrict__ out){
    __shared__ float2 tile[32][33];
    int b = blockIdx.z;
    int c0 = blockIdx.x*32, r0 = blockIdx.y*32;
    const float2* src = in + (size_t)b*NSQ*DH;
    for (int i = threadIdx.y; i < 32; i += 8){
        int d = c0 + threadIdx.x;
        tile[i][threadIdx.x] = (d < DH) ? src[(size_t)(r0+i)*DH + d]
                                        : make_float2(0.f, 0.f);
    }
    __syncthreads();
    float2* dst = out + (size_t)b*DH*NSQ;
    for (int i = threadIdx.y; i < 32; i += 8){
        int d = c0 + i;
        if (d < DH) dst[(size_t)d*NSQ + r0 + threadIdx.x] = tile[threadIdx.x][i];
    }
}
// transpose (2B, DH, NS) -> (2B, NS, DH) compact
__global__ void k_transpose_fh(const float* __restrict__ in, float* __restrict__ out){
    __shared__ float tile[32][33];
    int b = blockIdx.z;
    int d0 = blockIdx.x*32, n0 = blockIdx.y*32;
    const float* src = in + (size_t)b*DH*NSQ;
    for (int i = threadIdx.y; i < 32; i += 8){
        int d = d0 + i;
        tile[i][threadIdx.x] = (d < DH) ? src[(size_t)d*NSQ + n0 + threadIdx.x] : 0.f;
    }
    __syncthreads();
    float* dst = out + (size_t)b*NSQ*DH;
    int d = d0 + threadIdx.x;
    if (d < DH)
        for (int i = threadIdx.y; i < 32; i += 8)
            dst[(size_t)(n0+i)*DH + d] = tile[threadIdx.x][i];
}

// fused Hermitian mirror + euclid_to_lorentz, tf32-rounded outputs
__global__ void k_e2l(const float* __restrict__ rl, float* __restrict__ Ls,
                      float* __restrict__ Lc){
    size_t row = blockIdx.x;                   // 0 .. 2*BB*NSQ-1
    int t = threadIdx.x;                       // 256
    size_t bb = row >> 10;
    int n = (int)(row & 1023);
    float v;
    if (t < DH){
        v = rl[(bb*NSQ + n)*DH + t];
    } else {
        int srcn = (1024 - n) & 1023;
        v = rl[(bb*NSQ + srcn)*DH + (256 - t)];
    }
    float ss = blockReduceSum(v*v);
    float xn = sqrtf(fmaxf(ss, 1e-15f)) + 1e-5f;
    float scl = fminf(1.f, 2.0f / xn);
    v *= scl;
    float vn = sqrtf(fmaxf(ss*scl*scl, 1e-15f));
    float f = sinhf(vn) / vn;
    float* out = (bb < BB) ? Ls : Lc;
    size_t orow = (bb < BB) ? row : row - (size_t)BB*NSQ;
    if (t == 0) out[orow*DPAD] = tf32r(coshf(vn));
    out[orow*DPAD + 1 + t] = tf32r(f * v);
    if (t < DPAD - DP1) out[orow*DPAD + DP1 + t] = 0.f;
}

// --------- pipelined tensor-core GEMM (pre-rounded TF32 operands, no inner cvt) ----
template<int ATRANS, int BTRANS, int MODE, int ROUND>
__global__ void k_pgemm(const float* __restrict__ A, const float* __restrict__ Bm,
                        const float* __restrict__ bias, float* __restrict__ C,
                        int M, int N, int Klen, int lda, int ldb, int ldc,
                        long sA, long sB, long sC,
                        float* __restrict__ rss, float* __restrict__ css)
{
    constexpr int A_ELE = (ATRANS == 0) ? 128*20 : 16*132;
    constexpr int B_ELE = (BTRANS == 1) ? 128*20 : 16*132;
    __shared__ __align__(16) float As[2][A_ELE];
    __shared__ __align__(16) float Bs[2][B_ELE];

    int bz = blockIdx.z;
    A  += (size_t)bz * sA;
    Bm += (size_t)bz * sB;
    C  += (size_t)bz * sC;
    int bm = blockIdx.y * 128, bn = blockIdx.x * 128;
    int tid = threadIdx.x;
    int wid = tid >> 5, lane = tid & 31;
    int wm = (wid >> 2) * 64;
    int wn = (wid & 3) * 32;
    int g = lane >> 2, tg = lane & 3;

    int KT = (Klen + 15) >> 4;

    uint32_t asBase = (uint32_t)__cvta_generic_to_shared(&As[0][0]);
    uint32_t bsBase = (uint32_t)__cvta_generic_to_shared(&Bs[0][0]);

    auto issueA = [&](int st, int k0){
        uint32_t base = asBase + (uint32_t)(st * A_ELE * 4);
        if (ATRANS == 0){
            #pragma unroll
            for (int i = 0; i < 2; i++){
                int idx = tid + i*256;
                int mm = idx >> 2, k4 = idx & 3;
                cpa16(base + (mm*20 + k4*4)*4, A + (size_t)(bm+mm)*lda + k0 + k4*4);
            }
        } else {
            #pragma unroll
            for (int i = 0; i < 2; i++){
                int idx = tid + i*256;
                int kk = idx >> 5, m4 = idx & 31;
                cpa16(base + (kk*132 + m4*4)*4, A + (size_t)(k0+kk)*lda + bm + m4*4);
            }
        }
    };
    auto issueB = [&](int st, int k0){
        uint32_t base = bsBase + (uint32_t)(st * B_ELE * 4);
        if (BTRANS == 1){
            #pragma unroll
            for (int i = 0; i < 2; i++){
                int idx = tid + i*256;
                int nn = idx >> 2, k4 = idx & 3;
                cpa16(base + (nn*20 + k4*4)*4, Bm + (size_t)(bn+nn)*ldb + k0 + k4*4);
            }
        } else {
            #pragma unroll
            for (int i = 0; i < 2; i++){
                int idx = tid + i*256;
                int kk = idx >> 5, n4 = idx & 31;
                cpa16(base + (kk*132 + n4*4)*4, Bm + (size_t)(k0+kk)*ldb + bn + n4*4);
            }
        }
    };
    auto A_at = [&](int st, int m, int k)->uint32_t{
        const uint32_t* p = reinterpret_cast<const uint32_t*>(&As[st][0]);
        return (ATRANS == 0) ? p[m*20 + k] : p[k*132 + m];
    };
    auto B_at = [&](int st, int n, int k)->uint32_t{
        const uint32_t* p = reinterpret_cast<const uint32_t*>(&Bs[st][0]);
        return (BTRANS == 1) ? p[n*20 + k] : p[k*132 + n];
    };

    float acc[4][4][4];
    #pragma unroll
    for (int mi = 0; mi < 4; mi++)
        #pragma unroll
        for (int ni = 0; ni < 4; ni++)
            #pragma unroll
            for (int r = 0; r < 4; r++) acc[mi][ni][r] = 0.f;

    issueA(0, 0); issueB(0, 0);
    CP_COMMIT();

    for (int kt = 0; kt < KT; kt++){
        int st = kt & 1;
        if (kt + 1 < KT){
            issueA(st ^ 1, (kt+1)*16);
            issueB(st ^ 1, (kt+1)*16);
            CP_COMMIT();
            CP_WAIT1();
        } else {
            CP_WAIT0();
        }
        __syncthreads();

        #pragma unroll
        for (int ks = 0; ks < 2; ks++){
            int kk = ks*8;
            uint32_t bhf[4][2];
            #pragma unroll
            for (int ni = 0; ni < 4; ni++){
                int n = wn + ni*8 + g;
                bhf[ni][0] = B_at(st, n, kk+tg);
                bhf[ni][1] = B_at(st, n, kk+tg+4);
            }
            #pragma unroll
            for (int mi = 0; mi < 4; mi++){
                int m = wm + mi*16;
                uint32_t ahf[4];
                ahf[0] = A_at(st, m+g,   kk+tg);
                ahf[1] = A_at(st, m+g+8, kk+tg);
                ahf[2] = A_at(st, m+g,   kk+tg+4);
                ahf[3] = A_at(st, m+g+8, kk+tg+4);
                #pragma unroll
                for (int ni = 0; ni < 4; ni++)
                    mma_tf32(acc[mi][ni], ahf, bhf[ni]);
            }
        }
        __syncthreads();
    }

    // epilogue value transform
    #pragma unroll
    for (int mi = 0; mi < 4; mi++)
        #pragma unroll
        for (int ni = 0; ni < 4; ni++){
            int col = bn + wn + ni*8 + 2*tg;
            #pragma unroll
            for (int r = 0; r < 4; r++){
                int gn = col + (r & 1);
                float v = acc[mi][ni][r];
                if (MODE == 1 && gn < N) v += bias[gn];
                if (MODE == 2) v = (gn == 0) ? 0.f : gelu_exact(v);
                if (ROUND) v = tf32r(v);
                acc[mi][ni][r] = v;
            }
        }
    // store
    #pragma unroll
    for (int mi = 0; mi < 4; mi++)
        #pragma unroll
        for (int ni = 0; ni < 4; ni++){
            int col = bn + wn + ni*8 + 2*tg;
            #pragma unroll
            for (int r = 0; r < 4; r++){
                int gm = bm + wm + mi*16 + g + (r >= 2 ? 8 : 0);
                int gn = col + (r & 1);
                if (gn >= N) continue;
                C[(size_t)gm*ldc + gn] = acc[mi][ni][r];
            }
        }
    if (MODE == 2){
        #pragma unroll
        for (int mi = 0; mi < 4; mi++){
            #pragma unroll
            for (int half = 0; half < 2; half++){
                float rp = 0.f;
                #pragma unroll
                for (int ni = 0; ni < 4; ni++){
                    float a0 = acc[mi][ni][half*2], a1 = acc[mi][ni][half*2+1];
                    rp += a0*a0 + a1*a1;
                }
                rp += __shfl_down_sync(0xffffffffu, rp, 1);
                rp += __shfl_down_sync(0xffffffffu, rp, 2);
                if (tg == 0)
                    atomicAdd(&rss[(size_t)bz*1024 + bm + wm + mi*16 + g + half*8], rp);
            }
        }
        #pragma unroll
        for (int ni = 0; ni < 4; ni++){
            #pragma unroll
            for (int cb = 0; cb < 2; cb++){
                float cp = 0.f;
                #pragma unroll
                for (int mi = 0; mi < 4; mi++){
                    float a0 = acc[mi][ni][cb], a1 = acc[mi][ni][2+cb];
                    cp += a0*a0 + a1*a1;
                }
                cp += __shfl_down_sync(0xffffffffu, cp, 4);
                cp += __shfl_down_sync(0xffffffffu, cp, 8);
                cp += __shfl_down_sync(0xffffffffu, cp, 16);
                if (g == 0)
                    atomicAdd(&css[(size_t)bz*1024 + bn + wn + ni*8 + 2*tg + cb], cp);
            }
        }
    }
}

// ----------------------------- row-wise kernels ------------------------------------
__global__ void k_fix_time(float* __restrict__ Y){        // DPAD stride, rounded
    size_t row = blockIdx.x;
    int t = threadIdx.x;                                  // 256
    float sp = Y[row*DPAD + 1 + t];
    float S = blockReduceSum(sp*sp);
    if (t == 0) Y[row*DPAD] = tf32r(sqrtf(S + 1.f));
}
// warp-per-row poincare on 128-wide space rows, rounded
__global__ void k_poincare(const float* __restrict__ Y, float* __restrict__ out){
    size_t row = (size_t)blockIdx.x*8 + (threadIdx.x >> 5);
    int lane = threadIdx.x & 31;
    const float* y = Y + row*KKW;
    float v[4], s = 0.f;
    #pragma unroll
    for (int i = 0; i < 4; i++){ v[i] = y[lane + i*32]; s += v[i]*v[i]; }
    s = wsum(s);
    float inv = 1.f / (sqrtf(s + 1.f) + 1.f);
    float* o = out + row*KKW;
    #pragma unroll
    for (int i = 0; i < 4; i++) o[lane + i*32] = tf32r(v[i] * inv);
}
// finalize norms from fused SSQ; round Lb time col
__global__ void k_nfin(const float* __restrict__ rss, const float* __restrict__ css,
                       float* __restrict__ Lb, float* __restrict__ xnr,
                       float* __restrict__ xnc){
    int b = blockIdx.x, n = threadIdx.x;                  // 1024
    float S = rss[b*1024 + n];
    Lb[((size_t)b*1024 + n)*1024] = tf32r(sqrtf(S + 1.f));
    xnr[b*1024 + n] = sqrtf(fmaxf(2.f*S + 1.f, 1e-15f));
    float ts = blockReduceSum(S + 1.f);
    float c = css[b*1024 + n];
    xnc[b*1024 + n] = (n == 0) ? sqrtf(ts) : sqrtf(fmaxf(c, 1e-15f));
}
// mobius_matvec scale from MxcT (coalesced column loop)
__global__ void k_mscale(const float* __restrict__ MxT, const float* __restrict__ xna,
                         float* __restrict__ sc){
    int b = blockIdx.y;
    int m = blockIdx.x*256 + threadIdx.x;
    const float* base = MxT + (size_t)b*KKW*NCQ + m;
    float ss = 0.f;
    #pragma unroll 4
    for (int j = 0; j < KKW; j++){
        float v = base[(size_t)j*NCQ];
        ss += v*v;
    }
    float mxn = sqrtf(fmaxf(ss, 1e-15f));
    float xn = xna[b*NCQ + m];
    sc[b*NCQ + m] = tanhf(mxn / xn * atanhc(xn)) / mxn;
}
// warp-per-row fused Hs pipeline
__global__ void k_hs(const float* __restrict__ Hsa, const float* __restrict__ MxRaw,
                     const float* __restrict__ xnr,
                     const float* __restrict__ whs, float* __restrict__ lg){
    size_t row = (size_t)blockIdx.x*8 + (threadIdx.x >> 5);
    int lane = threadIdx.x & 31;
    const float* my = MxRaw + row*KKW;
    const float* hx = Hsa + row*KKW;
    float yr[4], x[4];
    float mm = 0.f;
    #pragma unroll
    for (int i = 0; i < 4; i++){
        yr[i] = my[lane + i*32];
        x[i]  = hx[lane + i*32];
        mm += yr[i]*yr[i];
    }
    mm = wsum(mm);
    float mxn = sqrtf(fmaxf(mm, 1e-15f));
    float xnb = xnr[row];
    float fac = tanhf(mxn / xnb * atanhc(xnb)) / mxn;

    float xy = 0.f, x2 = 0.f, y2 = 0.f;
    float y[4];
    #pragma unroll
    for (int i = 0; i < 4; i++){
        y[i] = yr[i] * fac;
        xy += x[i]*y[i]; x2 += x[i]*x[i]; y2 += y[i]*y[i];
    }
    xy = wsum(xy); x2 = wsum(x2); y2 = wsum(y2);
    float den = fmaxf(1.f + 2.f*xy + x2*y2, 1e-15f);
    float c1 = (1.f + 2.f*xy + y2) / den, c2 = (1.f - x2) / den;
    float h[4], hh = 0.f;
    #pragma unroll
    for (int i = 0; i < 4; i++){ h[i] = c1*x[i] + c2*y[i]; hh += h[i]*h[i]; }
    hh = wsum(hh);
    float hn = sqrtf(fmaxf(hh, 1e-15f));
    float fa = atanhc(hn) / hn;
    float gv[4], gg = 0.f;
    #pragma unroll
    for (int i = 0; i < 4; i++){ gv[i] = gelu_exact(fa*h[i]); gg += gv[i]*gv[i]; }
    gg = wsum(gg);
    float gn = sqrtf(fmaxf(gg, 1e-15f));
    float fb = tanhf(gn) / gn;
    float mx = 0.f, xn2 = 0.f;
    #pragma unroll
    for (int i = 0; i < 4; i++){
        float hs = fb * gv[i];
        mx += hs * __ldg(&whs[lane + i*32]);
        xn2 += hs*hs;
    }
    mx = wsum(mx); xn2 = wsum(xn2);
    if (lane == 0){
        float xn = sqrtf(fmaxf(xn2, 1e-15f));
        float mxn2 = sqrtf(fmaxf(mx*mx, 1e-15f));
        lg[row] = tanhf(mxn2 / xn * atanhc(xn)) * mx / mxn2;
    }
}
// transpose (b, 1024, 128) -> (b, 128, 1024)
__global__ void k_tbk(const float* __restrict__ in, float* __restrict__ out){
    __shared__ float tile[32][33];
    int b = blockIdx.z;
    int j0 = blockIdx.x*32, m0 = blockIdx.y*32;
    const float* src = in + (size_t)b*NCQ*KKW;
    for (int i = threadIdx.y; i < 32; i += 8)
        tile[i][threadIdx.x] = src[(size_t)(m0+i)*KKW + j0 + threadIdx.x];
    __syncthreads();
    float* dst = out + (size_t)b*KKW*NCQ;
    for (int i = threadIdx.y; i < 32; i += 8)
        dst[(size_t)(j0+i)*NCQ + m0 + threadIdx.x] = tile[threadIdx.x][i];
}
// Hc pipeline on transposed inputs, fused Ac-logit accumulation (atomics)
__global__ void k_hc(const float* __restrict__ HcaT, const float* __restrict__ MxcT,
                     const float* __restrict__ sc, const float* __restrict__ whc,
                     float* __restrict__ amx, float* __restrict__ ass){
    int bj = blockIdx.x;
    int b = bj >> 7, j = bj & 127;
    int t = threadIdx.x;                                  // 256
    float wj = __ldg(&whc[j]);
    const float* xrow = HcaT + ((size_t)(b*KKW + j))*NCQ;
    const float* yrow = MxcT + ((size_t)(b*KKW + j))*NCQ;
    const float* srow = sc + (size_t)b*NCQ;
    float x[4], y[4];
    #pragma unroll
    for (int i = 0; i < 4; i++){
        int m = t + i*256;
        x[i] = xrow[m]; y[i] = yrow[m] * srow[m];
    }
    float sxy = 0.f, sx2 = 0.f, sy2 = 0.f;
    #pragma unroll
    for (int i = 0; i < 4; i++){ sxy += x[i]*y[i]; sx2 += x[i]*x[i]; sy2 += y[i]*y[i]; }
    blockReduceSum3(sxy, sx2, sy2);
    float xy = sxy, x2 = sx2, y2 = sy2;
    float den = fmaxf(1.f + 2.f*xy + x2*y2, 1e-15f);
    float c1 = 1.f + 2.f*xy + y2, c2 = 1.f - x2;
    float h[4], hh = 0.f;
    #pragma unroll
    for (int i = 0; i < 4; i++){ h[i] = (c1*x[i] + c2*y[i]) / den; hh += h[i]*h[i]; }
    float hn = sqrtf(fmaxf(blockReduceSum(hh), 1e-15f));
    float fa = atanhc(hn) / hn;
    float g[4], gg = 0.f;
    #pragma unroll
    for (int i = 0; i < 4; i++){ g[i] = gelu_exact(fa*h[i]); gg += g[i]*g[i]; }
    float gn = sqrtf(fmaxf(blockReduceSum(gg), 1e-15f));
    float fb = tanhf(gn) / gn;
    #pragma unroll
    for (int i = 0; i < 4; i++){
        int m = t + i*256;
        float hc = fb * g[i];
        atomicAdd(&amx[b*NCQ + m], hc * wj);
        atomicAdd(&ass[b*NCQ + m], hc * hc);
    }
}
__global__ void k_acfin(const float* __restrict__ amx, const float* __restrict__ ass,
                        float* __restrict__ lg){
    int b = blockIdx.x, m = threadIdx.x;                  // 1024
    float mx = amx[b*NCQ + m];
    float ss = ass[b*NCQ + m];
    float xn = sqrtf(fmaxf(ss, 1e-15f));
    float mxn = sqrtf(fmaxf(mx*mx, 1e-15f));
    lg[b*NCQ + m] = tanhf(mxn / xn * atanhc(xn)) * mx / mxn;
}
__global__ void k_softmax(const float* __restrict__ lg, float* __restrict__ out){
    int b = blockIdx.x, t = threadIdx.x;                  // 256
    float l[4];
    float lm = -3.4e38f;
    #pragma unroll
    for (int i = 0; i < 4; i++){ l[i] = lg[b*1024 + t + i*256]; lm = fmaxf(lm, l[i]); }
    float M = blockReduceMax(lm);
    float es = 0.f, e[4];
    #pragma unroll
    for (int i = 0; i < 4; i++){ e[i] = expf(l[i] - M); es += e[i]; }
    float S = blockReduceSum(es);
    #pragma unroll
    for (int i = 0; i < 4; i++) out[b*1024 + t + i*256] = e[i] / S;
}
__global__ void k_centroid_part(const float* __restrict__ Lx, const float* __restrict__ w,
                                float* __restrict__ part){
    __shared__ float wsh[128];
    int ch = blockIdx.x, b = blockIdx.y;
    int t = threadIdx.x;                                  // 288, t<257 active
    for (int i = t; i < 128; i += blockDim.x) wsh[i] = w[(size_t)b*NSQ + ch*128 + i];
    __syncthreads();
    if (t < DP1){
        const float* base = Lx + ((size_t)b*NSQ + (size_t)ch*128)*DPAD + t;
        float acc = 0.f;
        for (int n = 0; n < 128; n++) acc += wsh[n] * base[(size_t)n*DPAD];
        part[(b*8 + ch)*DP1 + t] = acc;
    }
}
__global__ void k_centroid_fin(const float* __restrict__ part, float* __restrict__ co){
    __shared__ float t0sh;
    int b = blockIdx.x, t = threadIdx.x;                  // 288
    float acc = 0.f;
    if (t < DP1){
        #pragma unroll
        for (int c = 0; c < 8; c++) acc += part[(b*8 + c)*DP1 + t];
    }
    float sp = (t >= 1 && t < DP1) ? acc*acc : 0.f;
    float ssp = blockReduceSum(sp);
    if (t == 0) t0sh = acc;
    __syncthreads();
    float inner = -t0sh*t0sh + ssp;
    float den = sqrtf(fmaxf(fabsf(inner), 1e-8f));
    if (t < DP1) co[(size_t)b*DP1 + t] = acc / den;
}
__global__ void k_concat(const float* __restrict__ cs, const float* __restrict__ cc,
                         float* __restrict__ out){
    int b = blockIdx.x, t = threadIdx.x;                  // 256
    float t0s = cs[(size_t)b*DP1];
    float t0c = cc[(size_t)b*DP1];
    float sps = cs[(size_t)b*DP1 + 1 + t];
    float spc = cc[(size_t)b*DP1 + 1 + t];
    float ns  = sqrtf(fmaxf(blockReduceSum(sps*sps), 1e-15f));
    float ncv = sqrtf(fmaxf(blockReduceSum(spc*spc), 1e-15f));
    float zs = acoshf(fmaxf(t0s, 1.f + 1e-7f)) * sps / ns;
    float zc = acoshf(fmaxf(t0c, 1.f + 1e-7f)) * spc / ncv;
    float vn = sqrtf(fmaxf(blockReduceSum(zs*zs + zc*zc), 1e-15f));
    float f = sinhf(vn) / vn;
    float* o = out + (size_t)b*513;
    if (t == 0) o[0] = coshf(vn);
    o[1 + t]       = f * zs;
    o[1 + DD + t]  = f * zc;
}

// ----------------------------- launch ----------------------------------------------
extern "C" void kernel_launch(void* const* d_in, const int* in_sizes, int n_in,
                              void* d_out, int out_size)
{
    const float* sent = (const float*)d_in[0];
    const float* comm = (const float*)d_in[1];
    const float* WlW  = (const float*)d_in[2];
    const float* Wlb  = (const float*)d_in[3];
    const float* WcW  = (const float*)d_in[4];
    const float* Wcb  = (const float*)d_in[5];
    const float* WsW  = (const float*)d_in[6];
    const float* Wsb  = (const float*)d_in[7];
    const float* whs  = (const float*)d_in[8];
    const float* whc  = (const float*)d_in[9];
    float* out = (float*)d_out;
    (void)in_sizes; (void)n_in; (void)out_size;

    float2 *c1, *c1T;
    float *sT, *rl, *Ls, *Lc, *Llin, *Yt, *Lb, *Wt, *rss, *css, *amx, *ass, *xnr, *xnc,
          *msc, *Hsa, *Hca, *HcaT, *Mxs, *MxcT, *lgs, *lgc, *cs, *cc, *part;
    cudaGetSymbolAddress((void**)&c1,  g_c1);
    cudaGetSymbolAddress((void**)&c1T, g_c1T);
    cudaGetSymbolAddress((void**)&sT,  g_sT);
    cudaGetSymbolAddress((void**)&rl,  g_real);
    cudaGetSymbolAddress((void**)&Ls,  g_Ls);
    cudaGetSymbolAddress((void**)&Lc,  g_Lc);
    cudaGetSymbolAddress((void**)&Llin,g_Llin);
    cudaGetSymbolAddress((void**)&Yt,  g_Yt);
    cudaGetSymbolAddress((void**)&Lb,  g_Lb);
    cudaGetSymbolAddress((void**)&Wt,  g_Wt);
    cudaGetSymbolAddress((void**)&rss, g_rss);
    cudaGetSymbolAddress((void**)&css, g_css);
    cudaGetSymbolAddress((void**)&amx, g_amx);
    cudaGetSymbolAddress((void**)&ass, g_ass);
    cudaGetSymbolAddress((void**)&xnr, g_xnr);
    cudaGetSymbolAddress((void**)&xnc, g_xnc);
    cudaGetSymbolAddress((void**)&msc, g_msc);
    cudaGetSymbolAddress((void**)&Hsa, g_Hsa);
    cudaGetSymbolAddress((void**)&Hca, g_Hca);
    cudaGetSymbolAddress((void**)&HcaT,g_HcaT);
    cudaGetSymbolAddress((void**)&Mxs, g_Mxs);
    cudaGetSymbolAddress((void**)&MxcT,g_MxcT);
    cudaGetSymbolAddress((void**)&lgs, g_lgs);
    cudaGetSymbolAddress((void**)&lgc, g_lgc);
    cudaGetSymbolAddress((void**)&cs,  g_cs);
    cudaGetSymbolAddress((void**)&cc,  g_cc);
    cudaGetSymbolAddress((void**)&part,g_part);

    const int AS_OFF = BB*513;             // 16416
    const int AC_OFF = AS_OFF + BB*NSQ;    // 49184

    k_setup<<<32 + DP1 + 2*KP1, 1024>>>(WlW, WsW, WcW, Wt, rss, css, amx, ass);

    // ---- dual-branch FFT2 (stage-0 fused, Hermitian-compact) + euclid_to_lorentz ----
    k_fft256<<<2*BB*NSQ/4, dim3(64,4)>>>(sent, comm, c1);
    k_transpose_ch<<<dim3(5, NSQ/32, 2*BB), dim3(32,8)>>>(c1, c1T);
    k_fft1024<<<2*BB*DH, 256>>>(c1T, sT);
    k_transpose_fh<<<dim3(5, NSQ/32, 2*BB), dim3(32,8)>>>(sT, rl);
    k_e2l<<<2*BB*NSQ, 256>>>(rl, Ls, Lc);

    // ---- linear layers (dead time-column skipped: W rows 1..) ----
    k_pgemm<0,1,1,1><<<dim3(2,256,1),256>>>(Lc, Wt + (size_t)1*DPAD, Wlb + 1, Llin + 1,
        BB*NCQ, 256, DP1, DPAD, DPAD, DPAD, 0, 0, 0, nullptr, nullptr);
    k_fix_time<<<BB*NCQ, 256>>>(Llin);

    k_pgemm<0,1,1,0><<<dim3(1,256,1),256>>>(Ls, Wt + (size_t)385*DPAD, Wsb + 1, Yt,
        BB*NSQ, KKW, DP1, DPAD, DPAD, KKW, 0, 0, 0, nullptr, nullptr);
    k_poincare<<<BB*NSQ/8, 256>>>(Yt, Hsa);

    k_pgemm<0,1,1,0><<<dim3(1,256,1),256>>>(Lc, Wt + (size_t)641*DPAD, Wcb + 1, Yt,
        BB*NCQ, KKW, DP1, DPAD, DPAD, KKW, 0, 0, 0, nullptr, nullptr);
    k_poincare<<<BB*NCQ/8, 256>>>(Yt, Hca);

    // ---- big einsum + lorentz_act + fused norms (rounded stores) ----
    k_pgemm<0,1,2,1><<<dim3(8,8,BB),256>>>(Ls, Llin, nullptr, Lb,
        NSQ, NCQ, DP1, DPAD, DPAD, NCQ,
        (long)NSQ*DPAD, (long)NCQ*DPAD, (long)NSQ*NCQ, rss, css);
    k_nfin<<<BB, 1024>>>(rss, css, Lb, xnr, xnc);

    // ---- mobius_matvec GEMMs (Mxc produced transposed: MxcT = Hsa^T * Lb) ----
    k_pgemm<0,0,0,0><<<dim3(1,8,BB),256>>>(Lb, Hca, nullptr, Mxs,
        NSQ, KKW, NCQ, NCQ, KKW, KKW,
        (long)NSQ*NCQ, (long)NCQ*KKW, (long)NSQ*KKW, nullptr, nullptr);
    k_pgemm<1,0,0,0><<<dim3(8,1,BB),256>>>(Hsa, Lb, nullptr, MxcT,
        KKW, NCQ, NSQ, KKW, NCQ, NCQ,
        (long)NSQ*KKW, (long)NSQ*NCQ, (long)KKW*NCQ, nullptr, nullptr);
    k_tbk<<<dim3(4, 32, BB), dim3(32,8)>>>(Hca, HcaT);
    k_mscale<<<dim3(NCQ/256, BB), 256>>>(MxcT, xnc, msc);

    // ---- mobius_add + gelu pipelines + attention logits ----
    k_hs<<<BB*NSQ/8, 256>>>(Hsa, Mxs, xnr, whs, lgs);
    k_hc<<<BB*KKW, 256>>>(HcaT, MxcT, msc, whc, amx, ass);
    k_acfin<<<BB, 1024>>>(amx, ass, lgc);

    // ---- softmaxes straight into output ----
    k_softmax<<<BB, 256>>>(lgs, out + AS_OFF);
    k_softmax<<<BB, 256>>>(lgc, out + AC_OFF);

    // ---- centroids + concat ----
    k_centroid_part<<<dim3(8,BB), 288>>>(Ls, out + AS_OFF, part);
    k_centroid_fin<<<BB, 288>>>(part, cs);
    k_centroid_part<<<dim3(8,BB), 288>>>(Lc, out + AC_OFF, part);
    k_centroid_fin<<<BB, 288>>>(part, cc);
    k_concat<<<BB, 256>>>(cs, cc, out);
}